// round 10
// baseline (speedup 1.0000x reference)
#include <cuda_runtime.h>
#include <cuda_bf16.h>
#include <cstdint>

#define Bb 8
#define Cc 512
#define Tt 4
#define NN 256
#define LL 1024
#define HH 8
#define DD 64

#define EPSY 3e-4f

typedef __nv_bfloat16 bf16;

// Scratch
__device__ bf16  g_wsp[4 * 3 * Cc * Cc];   // [mat(q,k,v,p)][split][o][c] exact 3-way bf16
__device__ bf16  g_s0b[Bb * Cc * LL];      // proj spikes bf16 [b][c][l]
__device__ float g_y[3 * Bb * Cc * LL];    // qkv pre-activation fp32
__device__ bf16  g_qb[Bb * HH * LL * DD];  // q spikes [b][h][l][d]
__device__ bf16  g_kb[Bb * Cc * LL];       // k spikes [b][c][l]
__device__ bf16  g_vb[Bb * HH * LL * DD];  // v spikes [b][h][l][d]
__device__ bf16  g_sattnb[Bb * Cc * LL];   // attn spikes [b][c][l]

// ---------------------------------------------------------------------------
__device__ __forceinline__ uint32_t smem_u32(const void* p) {
    return (uint32_t)__cvta_generic_to_shared(p);
}
__device__ __forceinline__ void ldsm4(uint32_t* r, uint32_t a) {
    asm volatile("ldmatrix.sync.aligned.m8n8.x4.shared.b16 {%0,%1,%2,%3}, [%4];"
                 : "=r"(r[0]), "=r"(r[1]), "=r"(r[2]), "=r"(r[3]) : "r"(a));
}
__device__ __forceinline__ void ldsm4t(uint32_t* r, uint32_t a) {
    asm volatile("ldmatrix.sync.aligned.m8n8.x4.trans.shared.b16 {%0,%1,%2,%3}, [%4];"
                 : "=r"(r[0]), "=r"(r[1]), "=r"(r[2]), "=r"(r[3]) : "r"(a));
}
__device__ __forceinline__ void mma16816(float* c, const uint32_t* a, uint32_t b0, uint32_t b1) {
    asm volatile(
        "mma.sync.aligned.m16n8k16.row.col.f32.bf16.bf16.f32 "
        "{%0,%1,%2,%3}, {%4,%5,%6,%7}, {%8,%9}, {%0,%1,%2,%3};"
        : "+f"(c[0]), "+f"(c[1]), "+f"(c[2]), "+f"(c[3])
        : "r"(a[0]), "r"(a[1]), "r"(a[2]), "r"(a[3]), "r"(b0), "r"(b1));
}
__device__ __forceinline__ uint32_t packbf(float lo, float hi) {
    uint32_t l = (uint32_t)__bfloat16_as_ushort(__float2bfloat16(lo));
    uint32_t h = (uint32_t)__bfloat16_as_ushort(__float2bfloat16(hi));
    return l | (h << 16);
}

// ---------------------------------------------------------------------------
// Kernel 1 (fused prep): blocks [0,4096) = exact 3-way bf16 split of weights;
// blocks [4096,8192) = proj BN + multi-step LIF -> g_s0b.
// ---------------------------------------------------------------------------
__global__ void k_prep(const float* __restrict__ wq, const float* __restrict__ wk,
                       const float* __restrict__ wv, const float* __restrict__ wp,
                       const float* __restrict__ x,
                       const float* __restrict__ gp, const float* __restrict__ bpn,
                       const float* __restrict__ mp, const float* __restrict__ vp) {
    if (blockIdx.x < 4096) {
        int idx = blockIdx.x * 256 + threadIdx.x;   // over 4*Cc*Cc
        int m = idx / (Cc * Cc);
        int rc = idx % (Cc * Cc);
        const float* W = (m == 0) ? wq : (m == 1) ? wk : (m == 2) ? wv : wp;
        float w = W[rc];
        bf16 hi = __float2bfloat16(w);
        float r1 = w - __bfloat162float(hi);
        bf16 mid = __float2bfloat16(r1);
        float r2 = r1 - __bfloat162float(mid);
        g_wsp[(size_t)(m * 3 + 0) * Cc * Cc + rc] = hi;
        g_wsp[(size_t)(m * 3 + 1) * Cc * Cc + rc] = mid;
        g_wsp[(size_t)(m * 3 + 2) * Cc * Cc + rc] = __float2bfloat16(r2);
    } else {
        int idx = (blockIdx.x - 4096) * 256 + threadIdx.x;  // over B*C*NN
        int n = idx % NN;
        int c = (idx / NN) % Cc;
        int b = idx / (NN * Cc);

        float sc = gp[c] / sqrtf(vp[c] + 1e-5f);
        float sh = bpn[c] - mp[c] * sc;

        const float* xp = x + ((size_t)(b * Cc + c) * Tt) * NN + n;
        bf16* sp = g_s0b + (size_t)(b * Cc + c) * LL + n;

        float v = 0.0f;
#pragma unroll
        for (int t = 0; t < Tt; t++) {
            float xb = xp[(size_t)t * NN] * sc + sh;
            v = v + (xb - v) / 1.5f;
            float s = (v >= 1.0f) ? 1.0f : 0.0f;
            sp[(size_t)t * NN] = __float2bfloat16(s);
            if (s != 0.0f) v = 0.0f;
        }
    }
}

// ---------------------------------------------------------------------------
// Tensor-core GEMM core (validated): C[512,1024] = A(3 splits, K'=1536) @ B
// ---------------------------------------------------------------------------
__device__ __forceinline__ void gemm_core(const bf16* __restrict__ A,
                                          const bf16* __restrict__ B,
                                          float* __restrict__ C,
                                          const float* __restrict__ bias) {
    __shared__ bf16 As[128 * 40];
    __shared__ bf16 Bs[32 * 128];

    const int tid = threadIdx.x;
    const int lane = tid & 31, warp = tid >> 5;
    const int wm = warp >> 1, wn = warp & 1;
    const int o0 = blockIdx.y * 128, l0 = blockIdx.x * 128;

    float acc[2][8][4];
#pragma unroll
    for (int i = 0; i < 2; i++)
#pragma unroll
        for (int j = 0; j < 8; j++)
#pragma unroll
            for (int k = 0; k < 4; k++) acc[i][j][k] = 0.0f;

    int aM[2], aK[2], bK[2], bX[2];
#pragma unroll
    for (int t = 0; t < 2; t++) {
        int id = tid + t * 256;
        aM[t] = id >> 2; aK[t] = id & 3;
        bK[t] = id >> 4; bX[t] = id & 15;
    }
    uint4 pa[2], pb[2];
    const uint32_t sA = smem_u32(As), sB = smem_u32(Bs);

#define LOADG(kk)                                                                      \
    {                                                                                  \
        int split = ((kk) * 32) >> 9;                                                  \
        int c0 = ((kk) * 32) & 511;                                                    \
        const bf16* Ab = A + (size_t)split * (Cc * Cc);                                \
        _Pragma("unroll") for (int t = 0; t < 2; t++)                                  \
            pa[t] = *(const uint4*)(Ab + (size_t)(o0 + aM[t]) * Cc + c0 + aK[t] * 8);  \
        _Pragma("unroll") for (int t = 0; t < 2; t++)                                  \
            pb[t] = *(const uint4*)(B + (size_t)(c0 + bK[t]) * LL + l0 + bX[t] * 8);   \
    }
#define STOS()                                                                         \
    {                                                                                  \
        _Pragma("unroll") for (int t = 0; t < 2; t++)                                  \
            *(uint4*)((char*)As + aM[t] * 80 + aK[t] * 16) = pa[t];                    \
        _Pragma("unroll") for (int t = 0; t < 2; t++) {                                \
            int k = bK[t];                                                             \
            int x = bX[t] ^ (k & 7);                                                   \
            *(uint4*)((char*)Bs + k * 256 + x * 16) = pb[t];                           \
        }                                                                              \
    }

    LOADG(0);
    STOS();

    for (int kk = 0; kk < 48; kk++) {
        __syncthreads();
        if (kk < 47) LOADG(kk + 1);
#pragma unroll
        for (int ks = 0; ks < 2; ks++) {
            uint32_t a[2][4];
#pragma unroll
            for (int mi = 0; mi < 2; mi++) {
                int row = wm * 32 + mi * 16 + (lane & 15);
                ldsm4(a[mi], sA + row * 80 + (ks * 16 + (lane >> 4) * 8) * 2);
            }
            uint32_t bfr[4][4];
#pragma unroll
            for (int nb = 0; nb < 4; nb++) {
                int krow = ks * 16 + (lane & 7) + ((lane >> 3) & 1) * 8;
                int x = (wn * 8 + nb * 2 + (lane >> 4)) ^ (krow & 7);
                ldsm4t(bfr[nb], sB + krow * 256 + x * 16);
            }
#pragma unroll
            for (int mi = 0; mi < 2; mi++)
#pragma unroll
                for (int nj = 0; nj < 8; nj++)
                    mma16816(acc[mi][nj], a[mi], bfr[nj >> 1][(nj & 1) * 2],
                             bfr[nj >> 1][(nj & 1) * 2 + 1]);
        }
        __syncthreads();
        if (kk < 47) STOS();
    }
#undef LOADG
#undef STOS

#pragma unroll
    for (int mi = 0; mi < 2; mi++) {
        int r0 = o0 + wm * 32 + mi * 16 + (lane >> 2);
        float bi0 = bias ? bias[r0] : 0.0f;
        float bi1 = bias ? bias[r0 + 8] : 0.0f;
#pragma unroll
        for (int nj = 0; nj < 8; nj++) {
            int cb = l0 + wn * 64 + nj * 8 + (lane & 3) * 2;
            float2 v0 = make_float2(acc[mi][nj][0] + bi0, acc[mi][nj][1] + bi0);
            float2 v1 = make_float2(acc[mi][nj][2] + bi1, acc[mi][nj][3] + bi1);
            *(float2*)&C[(size_t)r0 * LL + cb] = v0;
            *(float2*)&C[(size_t)(r0 + 8) * LL + cb] = v1;
        }
    }
}

// grid = (LL/128, Cc/128, 3*Bb)
__global__ __launch_bounds__(256, 2) void k_gemm_qkv_mma() {
    int z = blockIdx.z;
    int w = z >> 3, b = z & 7;
    gemm_core(g_wsp + (size_t)w * 3 * Cc * Cc,
              g_s0b + (size_t)b * Cc * LL,
              g_y + (size_t)z * Cc * LL, nullptr);
}

// grid = (LL/128, Cc/128, Bb)
__global__ __launch_bounds__(256, 2) void k_gemm_out_mma(const float* __restrict__ bp,
                                                         float* __restrict__ out) {
    gemm_core(g_wsp + (size_t)3 * 3 * Cc * Cc,
              g_sattnb + (size_t)blockIdx.z * Cc * LL,
              out + (size_t)blockIdx.z * Cc * LL, bp);
}

// ---------------------------------------------------------------------------
// Kernel 3: per-branch BN + LIF with certified margin + INLINE exact fallback.
// If |v-1| < e at any step (e = rigorous bound on TC-vs-exact v deviation),
// recompute this chain's 4 dot products bitwise (ascending c, single acc)
// and redo the LIF — trajectory then provably equals the reference.
// ---------------------------------------------------------------------------
__global__ __launch_bounds__(256) void k_bn_lif_qkv(
        const float* __restrict__ wq, const float* __restrict__ wk,
        const float* __restrict__ wv,
        const float* __restrict__ gq, const float* __restrict__ bq,
        const float* __restrict__ mq, const float* __restrict__ vq,
        const float* __restrict__ gk, const float* __restrict__ bk,
        const float* __restrict__ mk, const float* __restrict__ vk,
        const float* __restrict__ gv, const float* __restrict__ bv,
        const float* __restrict__ mv, const float* __restrict__ vv) {
    int z = blockIdx.z;
    int w = z / Bb, b = z % Bb;
    int h = blockIdx.y;
    int n0 = blockIdx.x * 32;
    int tid = threadIdx.x, lane = tid & 31, wrp = tid >> 5;

    const float *gg, *bb, *mm, *vvv, *Wm;
    if (w == 0) { gg = gq; bb = bq; mm = mq; vvv = vq; Wm = wq; }
    else if (w == 1) { gg = gk; bb = bk; mm = mk; vvv = vk; Wm = wk; }
    else { gg = gv; bb = bv; mm = mv; vvv = vv; Wm = wv; }

    const bool isK = (w == 1);
    __shared__ bf16 sm[Tt][32][66];

#pragma unroll
    for (int i = 0; i < 8; i++) {
        int od = wrp * 8 + i;
        int o = h * 64 + od;
        float sc = gg[o] / sqrtf(vvv[o] + 1e-5f);
        float sh = bb[o] - mm[o] * sc;
        const float* yp = g_y + (size_t)((w * Bb + b) * Cc + o) * LL + n0 + lane;

        float y[4];
#pragma unroll
        for (int t = 0; t < Tt; t++) y[t] = yp[(size_t)t * NN];

        float de = (2.0f / 3.0f) * fabsf(sc) * EPSY;
        float e = 0.0f;
        bool flagged = false;
        {
            float v = 0.0f;
#pragma unroll
            for (int t = 0; t < Tt; t++) {
                float yb = y[t] * sc + sh;
                v = v + (yb - v) / 1.5f;
                e = e * (1.0f / 3.0f) + de;
                if (fabsf(v - 1.0f) < e) flagged = true;
                float s = (v >= 1.0f) ? 1.0f : 0.0f;
                if (s != 0.0f) { v = 0.0f; e = 0.0f; }
            }
        }

        if (flagged) {
            // exact recompute: ascending c, one fp32 accumulator per output
            const float* Wrow = Wm + (size_t)o * Cc;
            const bf16* sb = g_s0b + (size_t)b * Cc * LL + n0 + lane;
            float a0 = 0.0f, a1 = 0.0f, a2 = 0.0f, a3 = 0.0f;
#pragma unroll 8
            for (int c = 0; c < Cc; c++) {
                float wv_ = Wrow[c];
                const bf16* sp = sb + (size_t)c * LL;
                a0 += wv_ * __bfloat162float(sp[0 * NN]);
                a1 += wv_ * __bfloat162float(sp[1 * NN]);
                a2 += wv_ * __bfloat162float(sp[2 * NN]);
                a3 += wv_ * __bfloat162float(sp[3 * NN]);
            }
            y[0] = a0; y[1] = a1; y[2] = a2; y[3] = a3;
        }

        // final LIF + store
        float v = 0.0f;
#pragma unroll
        for (int t = 0; t < Tt; t++) {
            float yb = y[t] * sc + sh;
            v = v + (yb - v) / 1.5f;
            float s = (v >= 1.0f) ? 1.0f : 0.0f;
            if (isK)
                g_kb[(size_t)(b * Cc + o) * LL + t * NN + n0 + lane] = __float2bfloat16(s);
            else
                sm[t][lane][od] = __float2bfloat16(s);
            if (s != 0.0f) v = 0.0f;
        }
    }

    if (!isK) {
        __syncthreads();
        bf16* dst = ((w == 0) ? g_qb : g_vb) + (size_t)(b * HH + h) * LL * DD;
#pragma unroll
        for (int j = 0; j < 16; j++) {
            int flat = tid + 256 * j;
            int row = flat >> 5, col = flat & 31;
            int t = row >> 5, n = row & 31;
            uint32_t val;
            memcpy(&val, &sm[t][n][col * 2], 4);
            *(uint32_t*)(dst + ((size_t)(t * NN + n0 + n)) * DD + col * 2) = val;
        }
    }
}

// ---------------------------------------------------------------------------
// Kernel 4: attention on tensor cores (exact), K/V double-buffered,
// one __syncthreads per k-block.
// ---------------------------------------------------------------------------
__global__ __launch_bounds__(256) void k_attn_mma() {
    int l0 = blockIdx.x * 128;
    int bh = blockIdx.y;
    int b = bh >> 3, h = bh & 7;

    const bf16* Q = g_qb + (size_t)bh * LL * DD;
    const bf16* K = g_kb + (size_t)(b * Cc + h * 64) * LL;
    const bf16* V = g_vb + (size_t)bh * LL * DD;

    __shared__ bf16 Qs[128 * 72];
    __shared__ bf16 Ks[2][64 * 64];
    __shared__ bf16 Vs[2][64 * 64];

    int tid = threadIdx.x, lane = tid & 31, warp = tid >> 5;
    const uint32_t sQ = smem_u32(Qs);
    const uint32_t sK[2] = {smem_u32(Ks[0]), smem_u32(Ks[1])};
    const uint32_t sV[2] = {smem_u32(Vs[0]), smem_u32(Vs[1])};

    // per-thread K/V staging coords: 512 chunks each (64 rows x 8 chunks), 2/thread
    int rr[2], cc[2], xx[2];
#pragma unroll
    for (int t = 0; t < 2; t++) {
        int id = tid + t * 256;
        rr[t] = id >> 3; cc[t] = id & 7;
        xx[t] = cc[t] ^ (rr[t] & 7);
    }
    uint4 pk[2], pv[2];

#define LDKV(k0)                                                                   \
    {                                                                              \
        _Pragma("unroll") for (int t = 0; t < 2; t++) {                            \
            pk[t] = *(const uint4*)(K + (size_t)rr[t] * LL + (k0) + cc[t] * 8);    \
            pv[t] = *(const uint4*)(V + (size_t)((k0) + rr[t]) * DD + cc[t] * 8);  \
        }                                                                          \
    }
#define STKV(p)                                                                    \
    {                                                                              \
        _Pragma("unroll") for (int t = 0; t < 2; t++) {                            \
            *(uint4*)((char*)Ks[p] + rr[t] * 128 + xx[t] * 16) = pk[t];            \
            *(uint4*)((char*)Vs[p] + rr[t] * 128 + xx[t] * 16) = pv[t];            \
        }                                                                          \
    }

    // load Q tile (128 x 64) and first K/V block
#pragma unroll
    for (int t = 0; t < 4; t++) {
        int id = tid + t * 256;
        int r = id >> 3, c = id & 7;
        uint4 qv = *(const uint4*)(Q + (size_t)(l0 + r) * DD + c * 8);
        *(uint4*)((char*)Qs + r * 144 + c * 16) = qv;
    }
    LDKV(0);
    STKV(0);
    __syncthreads();

    uint32_t aq[4][4];
    {
        int row = warp * 16 + (lane & 15);
#pragma unroll
        for (int kc = 0; kc < 4; kc++)
            ldsm4(aq[kc], sQ + row * 144 + kc * 32 + (lane >> 4) * 16);
    }

    float oacc[8][4];
#pragma unroll
    for (int i = 0; i < 8; i++)
#pragma unroll
        for (int j = 0; j < 4; j++) oacc[i][j] = 0.0f;

    for (int it = 0; it < 16; it++) {
        int p = it & 1;
        if (it < 15) LDKV((it + 1) * 64);

        // Stage 1: S(m16 x n64) = Q @ K^T
        float sacc[8][4];
#pragma unroll
        for (int i = 0; i < 8; i++)
#pragma unroll
            for (int j = 0; j < 4; j++) sacc[i][j] = 0.0f;
#pragma unroll
        for (int nb = 0; nb < 4; nb++) {
#pragma unroll
            for (int ks = 0; ks < 4; ks++) {
                uint32_t bf[4];
                int krow = ks * 16 + (lane & 7) + ((lane >> 3) & 1) * 8;
                int ch = nb * 2 + (lane >> 4);
                int x = ch ^ (krow & 7);
                ldsm4t(bf, sK[p] + krow * 128 + x * 16);
                mma16816(sacc[nb * 2],     aq[ks], bf[0], bf[1]);
                mma16816(sacc[nb * 2 + 1], aq[ks], bf[2], bf[3]);
            }
        }
        uint32_t sa[4][4];
#pragma unroll
        for (int kb = 0; kb < 4; kb++) {
            sa[kb][0] = packbf(sacc[2 * kb][0],     sacc[2 * kb][1]);
            sa[kb][1] = packbf(sacc[2 * kb][2],     sacc[2 * kb][3]);
            sa[kb][2] = packbf(sacc[2 * kb + 1][0], sacc[2 * kb + 1][1]);
            sa[kb][3] = packbf(sacc[2 * kb + 1][2], sacc[2 * kb + 1][3]);
        }
        // Stage 2: O += S @ V
#pragma unroll
        for (int nb = 0; nb < 4; nb++) {
#pragma unroll
            for (int kb = 0; kb < 4; kb++) {
                uint32_t bf[4];
                int krow = kb * 16 + (lane & 7) + ((lane >> 3) & 1) * 8;
                int ch = nb * 2 + (lane >> 4);
                int x = ch ^ (krow & 7);
                ldsm4t(bf, sV[p] + krow * 128 + x * 16);
                mma16816(oacc[nb * 2],     sa[kb], bf[0], bf[1]);
                mma16816(oacc[nb * 2 + 1], sa[kb], bf[2], bf[3]);
            }
        }

        if (it < 15) STKV(p ^ 1);
        __syncthreads();
    }
#undef LDKV
#undef STKV

    int row = warp * 16 + (lane >> 2);
#pragma unroll
    for (int nj = 0; nj < 8; nj++) {
        int col = nj * 8 + (lane & 3) * 2;
#pragma unroll
        for (int e = 0; e < 4; e++) {
            int r = row + (e >> 1) * 8;
            int c = col + (e & 1);
            float o = oacc[nj][e] * 0.125f;
            float s = ((o / 1.5f - 1.0f) >= 0.0f) ? 1.0f : 0.0f;
            g_sattnb[((size_t)b * Cc + h * 64 + c) * LL + (l0 + r)] = __float2bfloat16(s);
        }
    }
}

// ---------------------------------------------------------------------------
extern "C" void kernel_launch(void* const* d_in, const int* in_sizes, int n_in,
                              void* d_out, int out_size) {
    const float* x   = (const float*)d_in[0];
    const float* wq  = (const float*)d_in[1];
    const float* wk  = (const float*)d_in[2];
    const float* wv  = (const float*)d_in[3];
    const float* wp  = (const float*)d_in[4];
    const float* bp  = (const float*)d_in[5];
    const float* gq  = (const float*)d_in[6];
    const float* bq  = (const float*)d_in[7];
    const float* mq  = (const float*)d_in[8];
    const float* vq  = (const float*)d_in[9];
    const float* gk  = (const float*)d_in[10];
    const float* bk  = (const float*)d_in[11];
    const float* mk  = (const float*)d_in[12];
    const float* vk  = (const float*)d_in[13];
    const float* gv  = (const float*)d_in[14];
    const float* bv  = (const float*)d_in[15];
    const float* mv  = (const float*)d_in[16];
    const float* vv  = (const float*)d_in[17];
    const float* gp  = (const float*)d_in[18];
    const float* bpn = (const float*)d_in[19];
    const float* mp  = (const float*)d_in[20];
    const float* vp  = (const float*)d_in[21];
    float* out = (float*)d_out;

    k_prep<<<8192, 256>>>(wq, wk, wv, wp, x, gp, bpn, mp, vp);
    k_gemm_qkv_mma<<<dim3(LL / 128, Cc / 128, 3 * Bb), 256>>>();
    k_bn_lif_qkv<<<dim3(NN / 32, HH, 3 * Bb), 256>>>(wq, wk, wv,
                                                     gq, bq, mq, vq,
                                                     gk, bk, mk, vk,
                                                     gv, bv, mv, vv);
    k_attn_mma<<<dim3(LL / 128, Bb * HH), 256>>>();
    k_gemm_out_mma<<<dim3(LL / 128, Cc / 128, Bb), 256>>>(bp, out);
}

// round 11
// speedup vs baseline: 1.2033x; 1.2033x over previous
#include <cuda_runtime.h>
#include <cuda_bf16.h>
#include <cstdint>

#define Bb 8
#define Cc 512
#define Tt 4
#define NN 256
#define LL 1024
#define HH 8
#define DD 64

#define EPSY 3e-4f
#define FLAG_CAP (1 << 20)

typedef __nv_bfloat16 bf16;

// Scratch
__device__ bf16  g_wsp[4 * 2 * Cc * Cc];   // [mat(q,k,v,p)][split(hi,mid)][o][c]
__device__ bf16  g_s0b[Bb * Cc * LL];      // proj spikes bf16 [b][c][l]
__device__ float g_y[3 * Bb * Cc * LL];    // qkv pre-activation fp32
__device__ bf16  g_qb[Bb * HH * LL * DD];  // q spikes [b][h][l][d]
__device__ bf16  g_kb[Bb * Cc * LL];       // k spikes [b][c][l]
__device__ bf16  g_vb[Bb * HH * LL * DD];  // v spikes [b][h][l][d]
__device__ bf16  g_sattnb[Bb * Cc * LL];   // attn spikes [b][c][l]
__device__ unsigned int g_nflag;
__device__ unsigned int g_flag[FLAG_CAP];  // (w<<20)|(b<<17)|(o<<8)|n

// ---------------------------------------------------------------------------
__device__ __forceinline__ uint32_t smem_u32(const void* p) {
    return (uint32_t)__cvta_generic_to_shared(p);
}
__device__ __forceinline__ void ldsm4(uint32_t* r, uint32_t a) {
    asm volatile("ldmatrix.sync.aligned.m8n8.x4.shared.b16 {%0,%1,%2,%3}, [%4];"
                 : "=r"(r[0]), "=r"(r[1]), "=r"(r[2]), "=r"(r[3]) : "r"(a));
}
__device__ __forceinline__ void ldsm4t(uint32_t* r, uint32_t a) {
    asm volatile("ldmatrix.sync.aligned.m8n8.x4.trans.shared.b16 {%0,%1,%2,%3}, [%4];"
                 : "=r"(r[0]), "=r"(r[1]), "=r"(r[2]), "=r"(r[3]) : "r"(a));
}
__device__ __forceinline__ void mma16816(float* c, const uint32_t* a, uint32_t b0, uint32_t b1) {
    asm volatile(
        "mma.sync.aligned.m16n8k16.row.col.f32.bf16.bf16.f32 "
        "{%0,%1,%2,%3}, {%4,%5,%6,%7}, {%8,%9}, {%0,%1,%2,%3};"
        : "+f"(c[0]), "+f"(c[1]), "+f"(c[2]), "+f"(c[3])
        : "r"(a[0]), "r"(a[1]), "r"(a[2]), "r"(a[3]), "r"(b0), "r"(b1));
}
__device__ __forceinline__ uint32_t packbf(float lo, float hi) {
    uint32_t l = (uint32_t)__bfloat16_as_ushort(__float2bfloat16(lo));
    uint32_t h = (uint32_t)__bfloat16_as_ushort(__float2bfloat16(hi));
    return l | (h << 16);
}

// ---------------------------------------------------------------------------
// Kernel 1 (fused prep): blocks [0,4096) = 2-way bf16 split of 4 weights;
// blocks [4096,8192) = proj BN + multi-step LIF -> g_s0b. Also zeroes flags.
// ---------------------------------------------------------------------------
__global__ void k_prep(const float* __restrict__ wq, const float* __restrict__ wk,
                       const float* __restrict__ wv, const float* __restrict__ wp,
                       const float* __restrict__ x,
                       const float* __restrict__ gp, const float* __restrict__ bpn,
                       const float* __restrict__ mp, const float* __restrict__ vp) {
    if (blockIdx.x == 0 && threadIdx.x == 0) g_nflag = 0;
    if (blockIdx.x < 4096) {
        int idx = blockIdx.x * 256 + threadIdx.x;   // over 4*Cc*Cc
        int m = idx / (Cc * Cc);
        int rc = idx % (Cc * Cc);
        const float* W = (m == 0) ? wq : (m == 1) ? wk : (m == 2) ? wv : wp;
        float w = W[rc];
        bf16 hi = __float2bfloat16(w);
        float r1 = w - __bfloat162float(hi);
        g_wsp[(size_t)(m * 2 + 0) * Cc * Cc + rc] = hi;
        g_wsp[(size_t)(m * 2 + 1) * Cc * Cc + rc] = __float2bfloat16(r1);
    } else {
        int idx = (blockIdx.x - 4096) * 256 + threadIdx.x;  // over B*C*NN
        int n = idx % NN;
        int c = (idx / NN) % Cc;
        int b = idx / (NN * Cc);

        float sc = gp[c] / sqrtf(vp[c] + 1e-5f);
        float sh = bpn[c] - mp[c] * sc;

        const float* xp = x + ((size_t)(b * Cc + c) * Tt) * NN + n;
        bf16* sp = g_s0b + (size_t)(b * Cc + c) * LL + n;

        float v = 0.0f;
#pragma unroll
        for (int t = 0; t < Tt; t++) {
            float xb = xp[(size_t)t * NN] * sc + sh;
            v = v + (xb - v) / 1.5f;
            float s = (v >= 1.0f) ? 1.0f : 0.0f;
            sp[(size_t)t * NN] = __float2bfloat16(s);
            if (s != 0.0f) v = 0.0f;
        }
    }
}

// ---------------------------------------------------------------------------
// Tensor-core GEMM core: C[512,1024] = A(2 splits, K'=1024) @ B.
// Double-buffered smem, ONE __syncthreads per k-step.
// ---------------------------------------------------------------------------
__device__ __forceinline__ void gemm_core(const bf16* __restrict__ A,
                                          const bf16* __restrict__ B,
                                          float* __restrict__ C,
                                          const float* __restrict__ bias) {
    __shared__ bf16 As[2][128 * 40];
    __shared__ bf16 Bs[2][32 * 128];

    const int tid = threadIdx.x;
    const int lane = tid & 31, warp = tid >> 5;
    const int wm = warp >> 1, wn = warp & 1;
    const int o0 = blockIdx.y * 128, l0 = blockIdx.x * 128;

    float acc[2][8][4];
#pragma unroll
    for (int i = 0; i < 2; i++)
#pragma unroll
        for (int j = 0; j < 8; j++)
#pragma unroll
            for (int k = 0; k < 4; k++) acc[i][j][k] = 0.0f;

    int aM[2], aK[2], bK[2], bX[2];
#pragma unroll
    for (int t = 0; t < 2; t++) {
        int id = tid + t * 256;
        aM[t] = id >> 2; aK[t] = id & 3;
        bK[t] = id >> 4; bX[t] = id & 15;
    }
    uint4 pa[2], pb[2];
    const uint32_t sA[2] = {smem_u32(As[0]), smem_u32(As[1])};
    const uint32_t sB[2] = {smem_u32(Bs[0]), smem_u32(Bs[1])};

#define LOADG(kk)                                                                      \
    {                                                                                  \
        int split = ((kk) * 32) >> 9;                                                  \
        int c0 = ((kk) * 32) & 511;                                                    \
        const bf16* Ab = A + (size_t)split * (Cc * Cc);                                \
        _Pragma("unroll") for (int t = 0; t < 2; t++)                                  \
            pa[t] = *(const uint4*)(Ab + (size_t)(o0 + aM[t]) * Cc + c0 + aK[t] * 8);  \
        _Pragma("unroll") for (int t = 0; t < 2; t++)                                  \
            pb[t] = *(const uint4*)(B + (size_t)(c0 + bK[t]) * LL + l0 + bX[t] * 8);   \
    }
#define STOS(p)                                                                        \
    {                                                                                  \
        _Pragma("unroll") for (int t = 0; t < 2; t++)                                  \
            *(uint4*)((char*)As[p] + aM[t] * 80 + aK[t] * 16) = pa[t];                 \
        _Pragma("unroll") for (int t = 0; t < 2; t++) {                                \
            int k = bK[t];                                                             \
            int x = bX[t] ^ (k & 7);                                                   \
            *(uint4*)((char*)Bs[p] + k * 256 + x * 16) = pb[t];                        \
        }                                                                              \
    }

    LOADG(0);
    STOS(0);
    __syncthreads();

    for (int kk = 0; kk < 32; kk++) {
        int p = kk & 1;
        if (kk < 31) LOADG(kk + 1);

#pragma unroll
        for (int ks = 0; ks < 2; ks++) {
            uint32_t a[2][4];
#pragma unroll
            for (int mi = 0; mi < 2; mi++) {
                int row = wm * 32 + mi * 16 + (lane & 15);
                ldsm4(a[mi], sA[p] + row * 80 + (ks * 16 + (lane >> 4) * 8) * 2);
            }
            uint32_t bfr[4][4];
#pragma unroll
            for (int nb = 0; nb < 4; nb++) {
                int krow = ks * 16 + (lane & 7) + ((lane >> 3) & 1) * 8;
                int x = (wn * 8 + nb * 2 + (lane >> 4)) ^ (krow & 7);
                ldsm4t(bfr[nb], sB[p] + krow * 256 + x * 16);
            }
#pragma unroll
            for (int mi = 0; mi < 2; mi++)
#pragma unroll
                for (int nj = 0; nj < 8; nj++)
                    mma16816(acc[mi][nj], a[mi], bfr[nj >> 1][(nj & 1) * 2],
                             bfr[nj >> 1][(nj & 1) * 2 + 1]);
        }

        if (kk < 31) STOS(p ^ 1);
        __syncthreads();
    }
#undef LOADG
#undef STOS

#pragma unroll
    for (int mi = 0; mi < 2; mi++) {
        int r0 = o0 + wm * 32 + mi * 16 + (lane >> 2);
        float bi0 = bias ? bias[r0] : 0.0f;
        float bi1 = bias ? bias[r0 + 8] : 0.0f;
#pragma unroll
        for (int nj = 0; nj < 8; nj++) {
            int cb = l0 + wn * 64 + nj * 8 + (lane & 3) * 2;
            float2 v0 = make_float2(acc[mi][nj][0] + bi0, acc[mi][nj][1] + bi0);
            float2 v1 = make_float2(acc[mi][nj][2] + bi1, acc[mi][nj][3] + bi1);
            *(float2*)&C[(size_t)r0 * LL + cb] = v0;
            *(float2*)&C[(size_t)(r0 + 8) * LL + cb] = v1;
        }
    }
}

// grid = (LL/128, Cc/128, 3*Bb)
__global__ __launch_bounds__(256, 2) void k_gemm_qkv_mma() {
    int z = blockIdx.z;
    int w = z >> 3, b = z & 7;
    gemm_core(g_wsp + (size_t)w * 2 * Cc * Cc,
              g_s0b + (size_t)b * Cc * LL,
              g_y + (size_t)z * Cc * LL, nullptr);
}

// grid = (LL/128, Cc/128, Bb)
__global__ __launch_bounds__(256, 2) void k_gemm_out_mma(const float* __restrict__ bp,
                                                         float* __restrict__ out) {
    gemm_core(g_wsp + (size_t)3 * 2 * Cc * Cc,
              g_sattnb + (size_t)blockIdx.z * Cc * LL,
              out + (size_t)blockIdx.z * Cc * LL, bp);
}

// ---------------------------------------------------------------------------
// Kernel 3: per-branch BN + LIF (coalesced) with certified-margin flagging.
// e <- e/3 + (2/3)*|sc|*EPSY ; flag chain if any step has |v-1| < e.
// ---------------------------------------------------------------------------
__global__ __launch_bounds__(256) void k_bn_lif_qkv(
        const float* __restrict__ gq, const float* __restrict__ bq,
        const float* __restrict__ mq, const float* __restrict__ vq,
        const float* __restrict__ gk, const float* __restrict__ bk,
        const float* __restrict__ mk, const float* __restrict__ vk,
        const float* __restrict__ gv, const float* __restrict__ bv,
        const float* __restrict__ mv, const float* __restrict__ vv) {
    int z = blockIdx.z;
    int w = z / Bb, b = z % Bb;
    int h = blockIdx.y;
    int n0 = blockIdx.x * 32;
    int tid = threadIdx.x, lane = tid & 31, wrp = tid >> 5;

    const float *gg, *bb, *mm, *vvv;
    if (w == 0) { gg = gq; bb = bq; mm = mq; vvv = vq; }
    else if (w == 1) { gg = gk; bb = bk; mm = mk; vvv = vk; }
    else { gg = gv; bb = bv; mm = mv; vvv = vv; }

    const bool isK = (w == 1);
    __shared__ bf16 sm[Tt][32][66];

#pragma unroll
    for (int i = 0; i < 8; i++) {
        int od = wrp * 8 + i;
        int o = h * 64 + od;
        float sc = gg[o] / sqrtf(vvv[o] + 1e-5f);
        float sh = bb[o] - mm[o] * sc;
        const float* yp = g_y + (size_t)((w * Bb + b) * Cc + o) * LL + n0 + lane;

        float de = (2.0f / 3.0f) * fabsf(sc) * EPSY;
        float e = 0.0f;
        bool flagged = false;

        float v = 0.0f;
#pragma unroll
        for (int t = 0; t < Tt; t++) {
            float yb = yp[(size_t)t * NN] * sc + sh;
            v = v + (yb - v) / 1.5f;
            e = e * (1.0f / 3.0f) + de;
            if (fabsf(v - 1.0f) < e) flagged = true;
            float s = (v >= 1.0f) ? 1.0f : 0.0f;
            if (isK)
                g_kb[(size_t)(b * Cc + o) * LL + t * NN + n0 + lane] = __float2bfloat16(s);
            else
                sm[t][lane][od] = __float2bfloat16(s);
            if (s != 0.0f) { v = 0.0f; e = 0.0f; }
        }
        if (flagged) {
            unsigned int pos = atomicAdd(&g_nflag, 1u);
            if (pos < FLAG_CAP)
                g_flag[pos] = ((unsigned)w << 20) | ((unsigned)b << 17) |
                              ((unsigned)o << 8) | (unsigned)(n0 + lane);
        }
    }

    if (!isK) {
        __syncthreads();
        bf16* dst = ((w == 0) ? g_qb : g_vb) + (size_t)(b * HH + h) * LL * DD;
#pragma unroll
        for (int j = 0; j < 16; j++) {
            int flat = tid + 256 * j;
            int row = flat >> 5, col = flat & 31;
            int t = row >> 5, n = row & 31;
            uint32_t val;
            memcpy(&val, &sm[t][n][col * 2], 4);
            *(uint32_t*)(dst + ((size_t)(t * NN + n0 + n)) * DD + col * 2) = val;
        }
    }
}

// ---------------------------------------------------------------------------
// Kernel 3f: exact fallback for flagged chains — bitwise ascending-k fp32.
// ---------------------------------------------------------------------------
__global__ void k_fallback(
        const float* __restrict__ wq, const float* __restrict__ wk,
        const float* __restrict__ wv,
        const float* __restrict__ gq, const float* __restrict__ bq,
        const float* __restrict__ mq, const float* __restrict__ vq,
        const float* __restrict__ gk, const float* __restrict__ bk,
        const float* __restrict__ mk, const float* __restrict__ vk,
        const float* __restrict__ gv, const float* __restrict__ bv,
        const float* __restrict__ mv, const float* __restrict__ vv) {
    unsigned int total = g_nflag;
    if (total > FLAG_CAP) total = FLAG_CAP;
    for (unsigned int i = blockIdx.x * blockDim.x + threadIdx.x; i < total;
         i += gridDim.x * blockDim.x) {
        unsigned int enc = g_flag[i];
        int n = enc & 255;
        int o = (enc >> 8) & 511;
        int b = (enc >> 17) & 7;
        int w = enc >> 20;

        const float* W = (w == 0) ? wq : (w == 1) ? wk : wv;
        const float* Wrow = W + (size_t)o * Cc;
        const bf16* sbase = g_s0b + (size_t)b * Cc * LL + n;

        float acc0 = 0.0f, acc1 = 0.0f, acc2 = 0.0f, acc3 = 0.0f;
#pragma unroll 8
        for (int c = 0; c < Cc; c++) {
            float wv_ = Wrow[c];
            const bf16* sp = sbase + (size_t)c * LL;
            acc0 += wv_ * __bfloat162float(sp[0 * NN]);
            acc1 += wv_ * __bfloat162float(sp[1 * NN]);
            acc2 += wv_ * __bfloat162float(sp[2 * NN]);
            acc3 += wv_ * __bfloat162float(sp[3 * NN]);
        }
        float y[4] = {acc0, acc1, acc2, acc3};

        const float *gg, *bb, *mm, *vvv;
        if (w == 0) { gg = gq; bb = bq; mm = mq; vvv = vq; }
        else if (w == 1) { gg = gk; bb = bk; mm = mk; vvv = vk; }
        else { gg = gv; bb = bv; mm = mv; vvv = vv; }

        float sc = gg[o] / sqrtf(vvv[o] + 1e-5f);
        float sh = bb[o] - mm[o] * sc;
        int h = o >> 6, dd = o & 63;

        float v = 0.0f;
#pragma unroll
        for (int t = 0; t < Tt; t++) {
            float yb = y[t] * sc + sh;
            v = v + (yb - v) / 1.5f;
            float s = (v >= 1.0f) ? 1.0f : 0.0f;
            if (w == 1)
                g_kb[(size_t)(b * Cc + o) * LL + t * NN + n] = __float2bfloat16(s);
            else {
                bf16* base = (w == 0) ? g_qb : g_vb;
                base[((size_t)(b * HH + h) * LL + t * NN + n) * DD + dd] =
                    __float2bfloat16(s);
            }
            if (s != 0.0f) v = 0.0f;
        }
    }
}

// ---------------------------------------------------------------------------
// Kernel 4: attention on tensor cores (exact), K/V double-buffered.
// ---------------------------------------------------------------------------
__global__ __launch_bounds__(256) void k_attn_mma() {
    int l0 = blockIdx.x * 128;
    int bh = blockIdx.y;
    int b = bh >> 3, h = bh & 7;

    const bf16* Q = g_qb + (size_t)bh * LL * DD;
    const bf16* K = g_kb + (size_t)(b * Cc + h * 64) * LL;
    const bf16* V = g_vb + (size_t)bh * LL * DD;

    __shared__ bf16 Qs[128 * 72];
    __shared__ bf16 Ks[2][64 * 64];
    __shared__ bf16 Vs[2][64 * 64];

    int tid = threadIdx.x, lane = tid & 31, warp = tid >> 5;
    const uint32_t sQ = smem_u32(Qs);
    const uint32_t sK[2] = {smem_u32(Ks[0]), smem_u32(Ks[1])};
    const uint32_t sV[2] = {smem_u32(Vs[0]), smem_u32(Vs[1])};

    int rr[2], cc[2], xx[2];
#pragma unroll
    for (int t = 0; t < 2; t++) {
        int id = tid + t * 256;
        rr[t] = id >> 3; cc[t] = id & 7;
        xx[t] = cc[t] ^ (rr[t] & 7);
    }
    uint4 pk[2], pv[2];

#define LDKV(k0)                                                                   \
    {                                                                              \
        _Pragma("unroll") for (int t = 0; t < 2; t++) {                            \
            pk[t] = *(const uint4*)(K + (size_t)rr[t] * LL + (k0) + cc[t] * 8);    \
            pv[t] = *(const uint4*)(V + (size_t)((k0) + rr[t]) * DD + cc[t] * 8);  \
        }                                                                          \
    }
#define STKV(p)                                                                    \
    {                                                                              \
        _Pragma("unroll") for (int t = 0; t < 2; t++) {                            \
            *(uint4*)((char*)Ks[p] + rr[t] * 128 + xx[t] * 16) = pk[t];            \
            *(uint4*)((char*)Vs[p] + rr[t] * 128 + xx[t] * 16) = pv[t];            \
        }                                                                          \
    }

#pragma unroll
    for (int t = 0; t < 4; t++) {
        int id = tid + t * 256;
        int r = id >> 3, c = id & 7;
        uint4 qv = *(const uint4*)(Q + (size_t)(l0 + r) * DD + c * 8);
        *(uint4*)((char*)Qs + r * 144 + c * 16) = qv;
    }
    LDKV(0);
    STKV(0);
    __syncthreads();

    uint32_t aq[4][4];
    {
        int row = warp * 16 + (lane & 15);
#pragma unroll
        for (int kc = 0; kc < 4; kc++)
            ldsm4(aq[kc], sQ + row * 144 + kc * 32 + (lane >> 4) * 16);
    }

    float oacc[8][4];
#pragma unroll
    for (int i = 0; i < 8; i++)
#pragma unroll
        for (int j = 0; j < 4; j++) oacc[i][j] = 0.0f;

    for (int it = 0; it < 16; it++) {
        int p = it & 1;
        if (it < 15) LDKV((it + 1) * 64);

        float sacc[8][4];
#pragma unroll
        for (int i = 0; i < 8; i++)
#pragma unroll
            for (int j = 0; j < 4; j++) sacc[i][j] = 0.0f;
#pragma unroll
        for (int nb = 0; nb < 4; nb++) {
#pragma unroll
            for (int ks = 0; ks < 4; ks++) {
                uint32_t bf[4];
                int krow = ks * 16 + (lane & 7) + ((lane >> 3) & 1) * 8;
                int ch = nb * 2 + (lane >> 4);
                int x = ch ^ (krow & 7);
                ldsm4t(bf, sK[p] + krow * 128 + x * 16);
                mma16816(sacc[nb * 2],     aq[ks], bf[0], bf[1]);
                mma16816(sacc[nb * 2 + 1], aq[ks], bf[2], bf[3]);
            }
        }
        uint32_t sa[4][4];
#pragma unroll
        for (int kb = 0; kb < 4; kb++) {
            sa[kb][0] = packbf(sacc[2 * kb][0],     sacc[2 * kb][1]);
            sa[kb][1] = packbf(sacc[2 * kb][2],     sacc[2 * kb][3]);
            sa[kb][2] = packbf(sacc[2 * kb + 1][0], sacc[2 * kb + 1][1]);
            sa[kb][3] = packbf(sacc[2 * kb + 1][2], sacc[2 * kb + 1][3]);
        }
#pragma unroll
        for (int nb = 0; nb < 4; nb++) {
#pragma unroll
            for (int kb = 0; kb < 4; kb++) {
                uint32_t bf[4];
                int krow = kb * 16 + (lane & 7) + ((lane >> 3) & 1) * 8;
                int ch = nb * 2 + (lane >> 4);
                int x = ch ^ (krow & 7);
                ldsm4t(bf, sV[p] + krow * 128 + x * 16);
                mma16816(oacc[nb * 2],     sa[kb], bf[0], bf[1]);
                mma16816(oacc[nb * 2 + 1], sa[kb], bf[2], bf[3]);
            }
        }

        if (it < 15) STKV(p ^ 1);
        __syncthreads();
    }
#undef LDKV
#undef STKV

    int row = warp * 16 + (lane >> 2);
#pragma unroll
    for (int nj = 0; nj < 8; nj++) {
        int col = nj * 8 + (lane & 3) * 2;
#pragma unroll
        for (int e = 0; e < 4; e++) {
            int r = row + (e >> 1) * 8;
            int c = col + (e & 1);
            float o = oacc[nj][e] * 0.125f;
            float s = ((o / 1.5f - 1.0f) >= 0.0f) ? 1.0f : 0.0f;
            g_sattnb[((size_t)b * Cc + h * 64 + c) * LL + (l0 + r)] = __float2bfloat16(s);
        }
    }
}

// ---------------------------------------------------------------------------
extern "C" void kernel_launch(void* const* d_in, const int* in_sizes, int n_in,
                              void* d_out, int out_size) {
    const float* x   = (const float*)d_in[0];
    const float* wq  = (const float*)d_in[1];
    const float* wk  = (const float*)d_in[2];
    const float* wv  = (const float*)d_in[3];
    const float* wp  = (const float*)d_in[4];
    const float* bp  = (const float*)d_in[5];
    const float* gq  = (const float*)d_in[6];
    const float* bq  = (const float*)d_in[7];
    const float* mq  = (const float*)d_in[8];
    const float* vq  = (const float*)d_in[9];
    const float* gk  = (const float*)d_in[10];
    const float* bk  = (const float*)d_in[11];
    const float* mk  = (const float*)d_in[12];
    const float* vk  = (const float*)d_in[13];
    const float* gv  = (const float*)d_in[14];
    const float* bv  = (const float*)d_in[15];
    const float* mv  = (const float*)d_in[16];
    const float* vv  = (const float*)d_in[17];
    const float* gp  = (const float*)d_in[18];
    const float* bpn = (const float*)d_in[19];
    const float* mp  = (const float*)d_in[20];
    const float* vp  = (const float*)d_in[21];
    float* out = (float*)d_out;

    k_prep<<<8192, 256>>>(wq, wk, wv, wp, x, gp, bpn, mp, vp);
    k_gemm_qkv_mma<<<dim3(LL / 128, Cc / 128, 3 * Bb), 256>>>();
    k_bn_lif_qkv<<<dim3(NN / 32, HH, 3 * Bb), 256>>>(gq, bq, mq, vq,
                                                     gk, bk, mk, vk,
                                                     gv, bv, mv, vv);
    k_fallback<<<64, 256>>>(wq, wk, wv, gq, bq, mq, vq,
                            gk, bk, mk, vk, gv, bv, mv, vv);
    k_attn_mma<<<dim3(LL / 128, Bb * HH), 256>>>();
    k_gemm_out_mma<<<dim3(LL / 128, Cc / 128, Bb), 256>>>(bp, out);
}

// round 12
// speedup vs baseline: 1.5835x; 1.3160x over previous
#include <cuda_runtime.h>
#include <cuda_bf16.h>
#include <cstdint>

#define Bb 8
#define Cc 512
#define Tt 4
#define NN 256
#define LL 1024
#define HH 8
#define DD 64

#define EPSY 3e-4f
#define FLAG_CAP (1 << 20)

typedef __nv_bfloat16 bf16;

// Scratch
__device__ bf16  g_wsp[4 * 2 * Cc * Cc];   // [mat(q,k,v,p)][split(hi,mid)][o][c]
__device__ bf16  g_s0b[Bb * Cc * LL];      // proj spikes bf16 [b][c][l]
__device__ float g_y[3 * Bb * Cc * LL];    // qkv pre-activation fp32
__device__ bf16  g_qb[Bb * HH * LL * DD];  // q spikes [b][h][l][d]
__device__ bf16  g_kb[Bb * Cc * LL];       // k spikes [b][c][l]
__device__ bf16  g_vb[Bb * HH * LL * DD];  // v spikes [b][h][l][d]
__device__ bf16  g_sattnb[Bb * Cc * LL];   // attn spikes [b][c][l]
__device__ unsigned int g_nflag;
__device__ unsigned int g_flag[FLAG_CAP];  // (w<<20)|(b<<17)|(o<<8)|n

// ---------------------------------------------------------------------------
__device__ __forceinline__ uint32_t smem_u32(const void* p) {
    return (uint32_t)__cvta_generic_to_shared(p);
}
__device__ __forceinline__ void ldsm4(uint32_t* r, uint32_t a) {
    asm volatile("ldmatrix.sync.aligned.m8n8.x4.shared.b16 {%0,%1,%2,%3}, [%4];"
                 : "=r"(r[0]), "=r"(r[1]), "=r"(r[2]), "=r"(r[3]) : "r"(a));
}
__device__ __forceinline__ void ldsm4t(uint32_t* r, uint32_t a) {
    asm volatile("ldmatrix.sync.aligned.m8n8.x4.trans.shared.b16 {%0,%1,%2,%3}, [%4];"
                 : "=r"(r[0]), "=r"(r[1]), "=r"(r[2]), "=r"(r[3]) : "r"(a));
}
__device__ __forceinline__ void mma16816(float* c, const uint32_t* a, uint32_t b0, uint32_t b1) {
    asm volatile(
        "mma.sync.aligned.m16n8k16.row.col.f32.bf16.bf16.f32 "
        "{%0,%1,%2,%3}, {%4,%5,%6,%7}, {%8,%9}, {%0,%1,%2,%3};"
        : "+f"(c[0]), "+f"(c[1]), "+f"(c[2]), "+f"(c[3])
        : "r"(a[0]), "r"(a[1]), "r"(a[2]), "r"(a[3]), "r"(b0), "r"(b1));
}
__device__ __forceinline__ uint32_t packbf(float lo, float hi) {
    uint32_t l = (uint32_t)__bfloat16_as_ushort(__float2bfloat16(lo));
    uint32_t h = (uint32_t)__bfloat16_as_ushort(__float2bfloat16(hi));
    return l | (h << 16);
}

// ---------------------------------------------------------------------------
// Kernel 1 (fused prep): blocks [0,4096) = 2-way bf16 split of 4 weights;
// blocks [4096,8192) = proj BN + multi-step LIF -> g_s0b. Also zeroes flags.
// ---------------------------------------------------------------------------
__global__ void k_prep(const float* __restrict__ wq, const float* __restrict__ wk,
                       const float* __restrict__ wv, const float* __restrict__ wp,
                       const float* __restrict__ x,
                       const float* __restrict__ gp, const float* __restrict__ bpn,
                       const float* __restrict__ mp, const float* __restrict__ vp) {
    if (blockIdx.x == 0 && threadIdx.x == 0) g_nflag = 0;
    if (blockIdx.x < 4096) {
        int idx = blockIdx.x * 256 + threadIdx.x;   // over 4*Cc*Cc
        int m = idx / (Cc * Cc);
        int rc = idx % (Cc * Cc);
        const float* W = (m == 0) ? wq : (m == 1) ? wk : (m == 2) ? wv : wp;
        float w = W[rc];
        bf16 hi = __float2bfloat16(w);
        float r1 = w - __bfloat162float(hi);
        g_wsp[(size_t)(m * 2 + 0) * Cc * Cc + rc] = hi;
        g_wsp[(size_t)(m * 2 + 1) * Cc * Cc + rc] = __float2bfloat16(r1);
    } else {
        int idx = (blockIdx.x - 4096) * 256 + threadIdx.x;  // over B*C*NN
        int n = idx % NN;
        int c = (idx / NN) % Cc;
        int b = idx / (NN * Cc);

        float sc = gp[c] / sqrtf(vp[c] + 1e-5f);
        float sh = bpn[c] - mp[c] * sc;

        const float* xp = x + ((size_t)(b * Cc + c) * Tt) * NN + n;
        bf16* sp = g_s0b + (size_t)(b * Cc + c) * LL + n;

        float v = 0.0f;
#pragma unroll
        for (int t = 0; t < Tt; t++) {
            float xb = xp[(size_t)t * NN] * sc + sh;
            v = v + (xb - v) / 1.5f;
            float s = (v >= 1.0f) ? 1.0f : 0.0f;
            sp[(size_t)t * NN] = __float2bfloat16(s);
            if (s != 0.0f) v = 0.0f;
        }
    }
}

// ---------------------------------------------------------------------------
// Tensor-core GEMM core: C[512,1024] = A(2 splits, K'=1024) @ B.
// Double-buffered smem, ONE __syncthreads per k-step.
// ---------------------------------------------------------------------------
__device__ __forceinline__ void gemm_core(const bf16* __restrict__ A,
                                          const bf16* __restrict__ B,
                                          float* __restrict__ C,
                                          const float* __restrict__ bias) {
    __shared__ bf16 As[2][128 * 40];
    __shared__ bf16 Bs[2][32 * 128];

    const int tid = threadIdx.x;
    const int lane = tid & 31, warp = tid >> 5;
    const int wm = warp >> 1, wn = warp & 1;
    const int o0 = blockIdx.y * 128, l0 = blockIdx.x * 128;

    float acc[2][8][4];
#pragma unroll
    for (int i = 0; i < 2; i++)
#pragma unroll
        for (int j = 0; j < 8; j++)
#pragma unroll
            for (int k = 0; k < 4; k++) acc[i][j][k] = 0.0f;

    int aM[2], aK[2], bK[2], bX[2];
#pragma unroll
    for (int t = 0; t < 2; t++) {
        int id = tid + t * 256;
        aM[t] = id >> 2; aK[t] = id & 3;
        bK[t] = id >> 4; bX[t] = id & 15;
    }
    uint4 pa[2], pb[2];
    const uint32_t sA[2] = {smem_u32(As[0]), smem_u32(As[1])};
    const uint32_t sB[2] = {smem_u32(Bs[0]), smem_u32(Bs[1])};

#define LOADG(kk)                                                                      \
    {                                                                                  \
        int split = ((kk) * 32) >> 9;                                                  \
        int c0 = ((kk) * 32) & 511;                                                    \
        const bf16* Ab = A + (size_t)split * (Cc * Cc);                                \
        _Pragma("unroll") for (int t = 0; t < 2; t++)                                  \
            pa[t] = *(const uint4*)(Ab + (size_t)(o0 + aM[t]) * Cc + c0 + aK[t] * 8);  \
        _Pragma("unroll") for (int t = 0; t < 2; t++)                                  \
            pb[t] = *(const uint4*)(B + (size_t)(c0 + bK[t]) * LL + l0 + bX[t] * 8);   \
    }
#define STOS(p)                                                                        \
    {                                                                                  \
        _Pragma("unroll") for (int t = 0; t < 2; t++)                                  \
            *(uint4*)((char*)As[p] + aM[t] * 80 + aK[t] * 16) = pa[t];                 \
        _Pragma("unroll") for (int t = 0; t < 2; t++) {                                \
            int k = bK[t];                                                             \
            int x = bX[t] ^ (k & 7);                                                   \
            *(uint4*)((char*)Bs[p] + k * 256 + x * 16) = pb[t];                        \
        }                                                                              \
    }

    LOADG(0);
    STOS(0);
    __syncthreads();

    for (int kk = 0; kk < 32; kk++) {
        int p = kk & 1;
        if (kk < 31) LOADG(kk + 1);

#pragma unroll
        for (int ks = 0; ks < 2; ks++) {
            uint32_t a[2][4];
#pragma unroll
            for (int mi = 0; mi < 2; mi++) {
                int row = wm * 32 + mi * 16 + (lane & 15);
                ldsm4(a[mi], sA[p] + row * 80 + (ks * 16 + (lane >> 4) * 8) * 2);
            }
            uint32_t bfr[4][4];
#pragma unroll
            for (int nb = 0; nb < 4; nb++) {
                int krow = ks * 16 + (lane & 7) + ((lane >> 3) & 1) * 8;
                int x = (wn * 8 + nb * 2 + (lane >> 4)) ^ (krow & 7);
                ldsm4t(bfr[nb], sB[p] + krow * 256 + x * 16);
            }
#pragma unroll
            for (int mi = 0; mi < 2; mi++)
#pragma unroll
                for (int nj = 0; nj < 8; nj++)
                    mma16816(acc[mi][nj], a[mi], bfr[nj >> 1][(nj & 1) * 2],
                             bfr[nj >> 1][(nj & 1) * 2 + 1]);
        }

        if (kk < 31) STOS(p ^ 1);
        __syncthreads();
    }
#undef LOADG
#undef STOS

#pragma unroll
    for (int mi = 0; mi < 2; mi++) {
        int r0 = o0 + wm * 32 + mi * 16 + (lane >> 2);
        float bi0 = bias ? bias[r0] : 0.0f;
        float bi1 = bias ? bias[r0 + 8] : 0.0f;
#pragma unroll
        for (int nj = 0; nj < 8; nj++) {
            int cb = l0 + wn * 64 + nj * 8 + (lane & 3) * 2;
            float2 v0 = make_float2(acc[mi][nj][0] + bi0, acc[mi][nj][1] + bi0);
            float2 v1 = make_float2(acc[mi][nj][2] + bi1, acc[mi][nj][3] + bi1);
            *(float2*)&C[(size_t)r0 * LL + cb] = v0;
            *(float2*)&C[(size_t)(r0 + 8) * LL + cb] = v1;
        }
    }
}

// grid = (LL/128, Cc/128, 3*Bb)
__global__ __launch_bounds__(256, 2) void k_gemm_qkv_mma() {
    int z = blockIdx.z;
    int w = z >> 3, b = z & 7;
    gemm_core(g_wsp + (size_t)w * 2 * Cc * Cc,
              g_s0b + (size_t)b * Cc * LL,
              g_y + (size_t)z * Cc * LL, nullptr);
}

// grid = (LL/128, Cc/128, Bb)
__global__ __launch_bounds__(256, 2) void k_gemm_out_mma(const float* __restrict__ bp,
                                                         float* __restrict__ out) {
    gemm_core(g_wsp + (size_t)3 * 2 * Cc * Cc,
              g_sattnb + (size_t)blockIdx.z * Cc * LL,
              out + (size_t)blockIdx.z * Cc * LL, bp);
}

// ---------------------------------------------------------------------------
// Kernel 3: per-branch BN + LIF (coalesced) with certified-margin flagging.
// ---------------------------------------------------------------------------
__global__ __launch_bounds__(256) void k_bn_lif_qkv(
        const float* __restrict__ gq, const float* __restrict__ bq,
        const float* __restrict__ mq, const float* __restrict__ vq,
        const float* __restrict__ gk, const float* __restrict__ bk,
        const float* __restrict__ mk, const float* __restrict__ vk,
        const float* __restrict__ gv, const float* __restrict__ bv,
        const float* __restrict__ mv, const float* __restrict__ vv) {
    int z = blockIdx.z;
    int w = z / Bb, b = z % Bb;
    int h = blockIdx.y;
    int n0 = blockIdx.x * 32;
    int tid = threadIdx.x, lane = tid & 31, wrp = tid >> 5;

    const float *gg, *bb, *mm, *vvv;
    if (w == 0) { gg = gq; bb = bq; mm = mq; vvv = vq; }
    else if (w == 1) { gg = gk; bb = bk; mm = mk; vvv = vk; }
    else { gg = gv; bb = bv; mm = mv; vvv = vv; }

    const bool isK = (w == 1);
    __shared__ bf16 sm[Tt][32][66];

#pragma unroll
    for (int i = 0; i < 8; i++) {
        int od = wrp * 8 + i;
        int o = h * 64 + od;
        float sc = gg[o] / sqrtf(vvv[o] + 1e-5f);
        float sh = bb[o] - mm[o] * sc;
        const float* yp = g_y + (size_t)((w * Bb + b) * Cc + o) * LL + n0 + lane;

        float de = (2.0f / 3.0f) * fabsf(sc) * EPSY;
        float e = 0.0f;
        bool flagged = false;

        float v = 0.0f;
#pragma unroll
        for (int t = 0; t < Tt; t++) {
            float yb = yp[(size_t)t * NN] * sc + sh;
            v = v + (yb - v) / 1.5f;
            e = e * (1.0f / 3.0f) + de;
            if (fabsf(v - 1.0f) < e) flagged = true;
            float s = (v >= 1.0f) ? 1.0f : 0.0f;
            if (isK)
                g_kb[(size_t)(b * Cc + o) * LL + t * NN + n0 + lane] = __float2bfloat16(s);
            else
                sm[t][lane][od] = __float2bfloat16(s);
            if (s != 0.0f) { v = 0.0f; e = 0.0f; }
        }
        if (flagged) {
            unsigned int pos = atomicAdd(&g_nflag, 1u);
            if (pos < FLAG_CAP)
                g_flag[pos] = ((unsigned)w << 20) | ((unsigned)b << 17) |
                              ((unsigned)o << 8) | (unsigned)(n0 + lane);
        }
    }

    if (!isK) {
        __syncthreads();
        bf16* dst = ((w == 0) ? g_qb : g_vb) + (size_t)(b * HH + h) * LL * DD;
#pragma unroll
        for (int j = 0; j < 16; j++) {
            int flat = tid + 256 * j;
            int row = flat >> 5, col = flat & 31;
            int t = row >> 5, n = row & 31;
            uint32_t val;
            memcpy(&val, &sm[t][n][col * 2], 4);
            *(uint32_t*)(dst + ((size_t)(t * NN + n0 + n)) * DD + col * 2) = val;
        }
    }
}

// ---------------------------------------------------------------------------
// Kernel 3f: WARP-COOPERATIVE exact fallback.
// Phase 1: 32 lanes compute all 512x4 products w_c*s_c (exact: s in {0,1})
//          into smem in parallel (high MLP).
// Phase 2: lanes 0..3 serially sum ascending c (bit-identical to reference
//          fma chain since each product is exactly representable).
// One warp per flagged chain; 4 warps/block, 128 blocks.
// ---------------------------------------------------------------------------
__global__ __launch_bounds__(128) void k_fallback(
        const float* __restrict__ wq, const float* __restrict__ wk,
        const float* __restrict__ wv,
        const float* __restrict__ gq, const float* __restrict__ bq,
        const float* __restrict__ mq, const float* __restrict__ vq,
        const float* __restrict__ gk, const float* __restrict__ bk,
        const float* __restrict__ mk, const float* __restrict__ vk,
        const float* __restrict__ gv, const float* __restrict__ bv,
        const float* __restrict__ mv, const float* __restrict__ vv) {
    __shared__ float prod[4][Tt][Cc];   // [warp][t][c] = 32 KB

    int lane = threadIdx.x & 31, wrp = threadIdx.x >> 5;
    unsigned int total = g_nflag;
    if (total > FLAG_CAP) total = FLAG_CAP;
    unsigned int gw = blockIdx.x * 4 + wrp;
    unsigned int nw = gridDim.x * 4;

    for (unsigned int i = gw; i < total; i += nw) {
        unsigned int enc = g_flag[i];
        int n = enc & 255;
        int o = (enc >> 8) & 511;
        int b = (enc >> 17) & 7;
        int w = enc >> 20;

        const float* W = (w == 0) ? wq : (w == 1) ? wk : wv;
        const float* Wrow = W + (size_t)o * Cc;
        const bf16* sbase = g_s0b + (size_t)b * Cc * LL + n;

        // Phase 1: parallel product fill (each product exact in fp32)
#pragma unroll
        for (int j = 0; j < 16; j++) {
            int c = lane + 32 * j;
            float wv_ = Wrow[c];
            const bf16* sp = sbase + (size_t)c * LL;
#pragma unroll
            for (int t = 0; t < Tt; t++)
                prod[wrp][t][c] = wv_ * __bfloat162float(sp[(size_t)t * NN]);
        }
        __syncwarp();

        // Phase 2: serial ascending-c sum (lanes 0..3, one t each)
        float yt = 0.0f;
        if (lane < Tt) {
            const float* pr = prod[wrp][lane];
#pragma unroll 16
            for (int c = 0; c < Cc; c++) yt += pr[c];
        }
        float y0 = __shfl_sync(0xffffffffu, yt, 0);
        float y1 = __shfl_sync(0xffffffffu, yt, 1);
        float y2 = __shfl_sync(0xffffffffu, yt, 2);
        float y3 = __shfl_sync(0xffffffffu, yt, 3);

        if (lane == 0) {
            float y[4] = {y0, y1, y2, y3};
            const float *gg, *bb, *mm, *vvv;
            if (w == 0) { gg = gq; bb = bq; mm = mq; vvv = vq; }
            else if (w == 1) { gg = gk; bb = bk; mm = mk; vvv = vk; }
            else { gg = gv; bb = bv; mm = mv; vvv = vv; }

            float sc = gg[o] / sqrtf(vvv[o] + 1e-5f);
            float sh = bb[o] - mm[o] * sc;
            int h = o >> 6, dd = o & 63;

            float v = 0.0f;
#pragma unroll
            for (int t = 0; t < Tt; t++) {
                float yb = y[t] * sc + sh;
                v = v + (yb - v) / 1.5f;
                float s = (v >= 1.0f) ? 1.0f : 0.0f;
                if (w == 1)
                    g_kb[(size_t)(b * Cc + o) * LL + t * NN + n] = __float2bfloat16(s);
                else {
                    bf16* base = (w == 0) ? g_qb : g_vb;
                    base[((size_t)(b * HH + h) * LL + t * NN + n) * DD + dd] =
                        __float2bfloat16(s);
                }
                if (s != 0.0f) v = 0.0f;
            }
        }
        __syncwarp();
    }
}

// ---------------------------------------------------------------------------
// Kernel 4: attention on tensor cores (exact), K/V double-buffered.
// ---------------------------------------------------------------------------
__global__ __launch_bounds__(256) void k_attn_mma() {
    int l0 = blockIdx.x * 128;
    int bh = blockIdx.y;
    int b = bh >> 3, h = bh & 7;

    const bf16* Q = g_qb + (size_t)bh * LL * DD;
    const bf16* K = g_kb + (size_t)(b * Cc + h * 64) * LL;
    const bf16* V = g_vb + (size_t)bh * LL * DD;

    __shared__ bf16 Qs[128 * 72];
    __shared__ bf16 Ks[2][64 * 64];
    __shared__ bf16 Vs[2][64 * 64];

    int tid = threadIdx.x, lane = tid & 31, warp = tid >> 5;
    const uint32_t sQ = smem_u32(Qs);
    const uint32_t sK[2] = {smem_u32(Ks[0]), smem_u32(Ks[1])};
    const uint32_t sV[2] = {smem_u32(Vs[0]), smem_u32(Vs[1])};

    int rr[2], cc[2], xx[2];
#pragma unroll
    for (int t = 0; t < 2; t++) {
        int id = tid + t * 256;
        rr[t] = id >> 3; cc[t] = id & 7;
        xx[t] = cc[t] ^ (rr[t] & 7);
    }
    uint4 pk[2], pv[2];

#define LDKV(k0)                                                                   \
    {                                                                              \
        _Pragma("unroll") for (int t = 0; t < 2; t++) {                            \
            pk[t] = *(const uint4*)(K + (size_t)rr[t] * LL + (k0) + cc[t] * 8);    \
            pv[t] = *(const uint4*)(V + (size_t)((k0) + rr[t]) * DD + cc[t] * 8);  \
        }                                                                          \
    }
#define STKV(p)                                                                    \
    {                                                                              \
        _Pragma("unroll") for (int t = 0; t < 2; t++) {                            \
            *(uint4*)((char*)Ks[p] + rr[t] * 128 + xx[t] * 16) = pk[t];            \
            *(uint4*)((char*)Vs[p] + rr[t] * 128 + xx[t] * 16) = pv[t];            \
        }                                                                          \
    }

#pragma unroll
    for (int t = 0; t < 4; t++) {
        int id = tid + t * 256;
        int r = id >> 3, c = id & 7;
        uint4 qv = *(const uint4*)(Q + (size_t)(l0 + r) * DD + c * 8);
        *(uint4*)((char*)Qs + r * 144 + c * 16) = qv;
    }
    LDKV(0);
    STKV(0);
    __syncthreads();

    uint32_t aq[4][4];
    {
        int row = warp * 16 + (lane & 15);
#pragma unroll
        for (int kc = 0; kc < 4; kc++)
            ldsm4(aq[kc], sQ + row * 144 + kc * 32 + (lane >> 4) * 16);
    }

    float oacc[8][4];
#pragma unroll
    for (int i = 0; i < 8; i++)
#pragma unroll
        for (int j = 0; j < 4; j++) oacc[i][j] = 0.0f;

    for (int it = 0; it < 16; it++) {
        int p = it & 1;
        if (it < 15) LDKV((it + 1) * 64);

        float sacc[8][4];
#pragma unroll
        for (int i = 0; i < 8; i++)
#pragma unroll
            for (int j = 0; j < 4; j++) sacc[i][j] = 0.0f;
#pragma unroll
        for (int nb = 0; nb < 4; nb++) {
#pragma unroll
            for (int ks = 0; ks < 4; ks++) {
                uint32_t bf[4];
                int krow = ks * 16 + (lane & 7) + ((lane >> 3) & 1) * 8;
                int ch = nb * 2 + (lane >> 4);
                int x = ch ^ (krow & 7);
                ldsm4t(bf, sK[p] + krow * 128 + x * 16);
                mma16816(sacc[nb * 2],     aq[ks], bf[0], bf[1]);
                mma16816(sacc[nb * 2 + 1], aq[ks], bf[2], bf[3]);
            }
        }
        uint32_t sa[4][4];
#pragma unroll
        for (int kb = 0; kb < 4; kb++) {
            sa[kb][0] = packbf(sacc[2 * kb][0],     sacc[2 * kb][1]);
            sa[kb][1] = packbf(sacc[2 * kb][2],     sacc[2 * kb][3]);
            sa[kb][2] = packbf(sacc[2 * kb + 1][0], sacc[2 * kb + 1][1]);
            sa[kb][3] = packbf(sacc[2 * kb + 1][2], sacc[2 * kb + 1][3]);
        }
#pragma unroll
        for (int nb = 0; nb < 4; nb++) {
#pragma unroll
            for (int kb = 0; kb < 4; kb++) {
                uint32_t bf[4];
                int krow = kb * 16 + (lane & 7) + ((lane >> 3) & 1) * 8;
                int ch = nb * 2 + (lane >> 4);
                int x = ch ^ (krow & 7);
                ldsm4t(bf, sV[p] + krow * 128 + x * 16);
                mma16816(oacc[nb * 2],     sa[kb], bf[0], bf[1]);
                mma16816(oacc[nb * 2 + 1], sa[kb], bf[2], bf[3]);
            }
        }

        if (it < 15) STKV(p ^ 1);
        __syncthreads();
    }
#undef LDKV
#undef STKV

    int row = warp * 16 + (lane >> 2);
#pragma unroll
    for (int nj = 0; nj < 8; nj++) {
        int col = nj * 8 + (lane & 3) * 2;
#pragma unroll
        for (int e = 0; e < 4; e++) {
            int r = row + (e >> 1) * 8;
            int c = col + (e & 1);
            float o = oacc[nj][e] * 0.125f;
            float s = ((o / 1.5f - 1.0f) >= 0.0f) ? 1.0f : 0.0f;
            g_sattnb[((size_t)b * Cc + h * 64 + c) * LL + (l0 + r)] = __float2bfloat16(s);
        }
    }
}

// ---------------------------------------------------------------------------
extern "C" void kernel_launch(void* const* d_in, const int* in_sizes, int n_in,
                              void* d_out, int out_size) {
    const float* x   = (const float*)d_in[0];
    const float* wq  = (const float*)d_in[1];
    const float* wk  = (const float*)d_in[2];
    const float* wv  = (const float*)d_in[3];
    const float* wp  = (const float*)d_in[4];
    const float* bp  = (const float*)d_in[5];
    const float* gq  = (const float*)d_in[6];
    const float* bq  = (const float*)d_in[7];
    const float* mq  = (const float*)d_in[8];
    const float* vq  = (const float*)d_in[9];
    const float* gk  = (const float*)d_in[10];
    const float* bk  = (const float*)d_in[11];
    const float* mk  = (const float*)d_in[12];
    const float* vk  = (const float*)d_in[13];
    const float* gv  = (const float*)d_in[14];
    const float* bv  = (const float*)d_in[15];
    const float* mv  = (const float*)d_in[16];
    const float* vv  = (const float*)d_in[17];
    const float* gp  = (const float*)d_in[18];
    const float* bpn = (const float*)d_in[19];
    const float* mp  = (const float*)d_in[20];
    const float* vp  = (const float*)d_in[21];
    float* out = (float*)d_out;

    k_prep<<<8192, 256>>>(wq, wk, wv, wp, x, gp, bpn, mp, vp);
    k_gemm_qkv_mma<<<dim3(LL / 128, Cc / 128, 3 * Bb), 256>>>();
    k_bn_lif_qkv<<<dim3(NN / 32, HH, 3 * Bb), 256>>>(gq, bq, mq, vq,
                                                     gk, bk, mk, vk,
                                                     gv, bv, mv, vv);
    k_fallback<<<128, 128>>>(wq, wk, wv, gq, bq, mq, vq,
                             gk, bk, mk, vk, gv, bv, mv, vv);
    k_attn_mma<<<dim3(LL / 128, Bb * HH), 256>>>();
    k_gemm_out_mma<<<dim3(LL / 128, Cc / 128, Bb), 256>>>(bp, out);
}

// round 13
// speedup vs baseline: 1.6742x; 1.0573x over previous
#include <cuda_runtime.h>
#include <cuda_bf16.h>
#include <cstdint>

#define Bb 8
#define Cc 512
#define Tt 4
#define NN 256
#define LL 1024
#define HH 8
#define DD 64

#define EPSY 3e-4f
#define FLAG_CAP (1 << 20)

typedef __nv_bfloat16 bf16;

// Scratch
__device__ bf16  g_wsp[4 * 2 * Cc * Cc];   // [mat(q,k,v,p)][split(hi,mid)][o][c]
__device__ bf16  g_s0b[Bb * Cc * LL];      // proj spikes bf16 [b][c][l]
__device__ float g_y[3 * Bb * Cc * LL];    // qkv pre-activation fp32
__device__ bf16  g_qb[Bb * HH * LL * DD];  // q spikes [b][h][l][d]
__device__ bf16  g_kb[Bb * Cc * LL];       // k spikes [b][c][l]
__device__ bf16  g_vb[Bb * HH * LL * DD];  // v spikes [b][h][l][d]
__device__ bf16  g_sattnb[Bb * Cc * LL];   // attn spikes [b][c][l]
__device__ unsigned int g_nflag;
__device__ unsigned int g_flag[FLAG_CAP];  // (w<<20)|(b<<17)|(o<<8)|n

// ---------------------------------------------------------------------------
__device__ __forceinline__ uint32_t smem_u32(const void* p) {
    return (uint32_t)__cvta_generic_to_shared(p);
}
__device__ __forceinline__ void ldsm4(uint32_t* r, uint32_t a) {
    asm volatile("ldmatrix.sync.aligned.m8n8.x4.shared.b16 {%0,%1,%2,%3}, [%4];"
                 : "=r"(r[0]), "=r"(r[1]), "=r"(r[2]), "=r"(r[3]) : "r"(a));
}
__device__ __forceinline__ void ldsm4t(uint32_t* r, uint32_t a) {
    asm volatile("ldmatrix.sync.aligned.m8n8.x4.trans.shared.b16 {%0,%1,%2,%3}, [%4];"
                 : "=r"(r[0]), "=r"(r[1]), "=r"(r[2]), "=r"(r[3]) : "r"(a));
}
__device__ __forceinline__ void mma16816(float* c, const uint32_t* a, uint32_t b0, uint32_t b1) {
    asm volatile(
        "mma.sync.aligned.m16n8k16.row.col.f32.bf16.bf16.f32 "
        "{%0,%1,%2,%3}, {%4,%5,%6,%7}, {%8,%9}, {%0,%1,%2,%3};"
        : "+f"(c[0]), "+f"(c[1]), "+f"(c[2]), "+f"(c[3])
        : "r"(a[0]), "r"(a[1]), "r"(a[2]), "r"(a[3]), "r"(b0), "r"(b1));
}
__device__ __forceinline__ uint32_t packbf(float lo, float hi) {
    uint32_t l = (uint32_t)__bfloat16_as_ushort(__float2bfloat16(lo));
    uint32_t h = (uint32_t)__bfloat16_as_ushort(__float2bfloat16(hi));
    return l | (h << 16);
}

// ---------------------------------------------------------------------------
// Kernel 1 (fused prep): blocks [0,4096) = 2-way bf16 split of 4 weights;
// blocks [4096,8192) = proj BN + multi-step LIF -> g_s0b. Also zeroes flags.
// ---------------------------------------------------------------------------
__global__ void k_prep(const float* __restrict__ wq, const float* __restrict__ wk,
                       const float* __restrict__ wv, const float* __restrict__ wp,
                       const float* __restrict__ x,
                       const float* __restrict__ gp, const float* __restrict__ bpn,
                       const float* __restrict__ mp, const float* __restrict__ vp) {
    if (blockIdx.x == 0 && threadIdx.x == 0) g_nflag = 0;
    if (blockIdx.x < 4096) {
        int idx = blockIdx.x * 256 + threadIdx.x;   // over 4*Cc*Cc
        int m = idx / (Cc * Cc);
        int rc = idx % (Cc * Cc);
        const float* W = (m == 0) ? wq : (m == 1) ? wk : (m == 2) ? wv : wp;
        float w = W[rc];
        bf16 hi = __float2bfloat16(w);
        float r1 = w - __bfloat162float(hi);
        g_wsp[(size_t)(m * 2 + 0) * Cc * Cc + rc] = hi;
        g_wsp[(size_t)(m * 2 + 1) * Cc * Cc + rc] = __float2bfloat16(r1);
    } else {
        int idx = (blockIdx.x - 4096) * 256 + threadIdx.x;  // over B*C*NN
        int n = idx % NN;
        int c = (idx / NN) % Cc;
        int b = idx / (NN * Cc);

        float sc = gp[c] / sqrtf(vp[c] + 1e-5f);
        float sh = bpn[c] - mp[c] * sc;

        const float* xp = x + ((size_t)(b * Cc + c) * Tt) * NN + n;
        bf16* sp = g_s0b + (size_t)(b * Cc + c) * LL + n;

        float v = 0.0f;
#pragma unroll
        for (int t = 0; t < Tt; t++) {
            float xb = xp[(size_t)t * NN] * sc + sh;
            v = v + (xb - v) / 1.5f;
            float s = (v >= 1.0f) ? 1.0f : 0.0f;
            sp[(size_t)t * NN] = __float2bfloat16(s);
            if (s != 0.0f) v = 0.0f;
        }
    }
}

// ---------------------------------------------------------------------------
// Tensor-core GEMM core: C[512,1024] = A(2 splits, K'=1024) @ B.
// Double-buffered smem, ONE __syncthreads per k-step.
// ---------------------------------------------------------------------------
__device__ __forceinline__ void gemm_core(const bf16* __restrict__ A,
                                          const bf16* __restrict__ B,
                                          float* __restrict__ C,
                                          const float* __restrict__ bias) {
    __shared__ bf16 As[2][128 * 40];
    __shared__ bf16 Bs[2][32 * 128];

    const int tid = threadIdx.x;
    const int lane = tid & 31, warp = tid >> 5;
    const int wm = warp >> 1, wn = warp & 1;
    const int o0 = blockIdx.y * 128, l0 = blockIdx.x * 128;

    float acc[2][8][4];
#pragma unroll
    for (int i = 0; i < 2; i++)
#pragma unroll
        for (int j = 0; j < 8; j++)
#pragma unroll
            for (int k = 0; k < 4; k++) acc[i][j][k] = 0.0f;

    int aM[2], aK[2], bK[2], bX[2];
#pragma unroll
    for (int t = 0; t < 2; t++) {
        int id = tid + t * 256;
        aM[t] = id >> 2; aK[t] = id & 3;
        bK[t] = id >> 4; bX[t] = id & 15;
    }
    uint4 pa[2], pb[2];
    const uint32_t sA[2] = {smem_u32(As[0]), smem_u32(As[1])};
    const uint32_t sB[2] = {smem_u32(Bs[0]), smem_u32(Bs[1])};

#define LOADG(kk)                                                                      \
    {                                                                                  \
        int split = ((kk) * 32) >> 9;                                                  \
        int c0 = ((kk) * 32) & 511;                                                    \
        const bf16* Ab = A + (size_t)split * (Cc * Cc);                                \
        _Pragma("unroll") for (int t = 0; t < 2; t++)                                  \
            pa[t] = *(const uint4*)(Ab + (size_t)(o0 + aM[t]) * Cc + c0 + aK[t] * 8);  \
        _Pragma("unroll") for (int t = 0; t < 2; t++)                                  \
            pb[t] = *(const uint4*)(B + (size_t)(c0 + bK[t]) * LL + l0 + bX[t] * 8);   \
    }
#define STOS(p)                                                                        \
    {                                                                                  \
        _Pragma("unroll") for (int t = 0; t < 2; t++)                                  \
            *(uint4*)((char*)As[p] + aM[t] * 80 + aK[t] * 16) = pa[t];                 \
        _Pragma("unroll") for (int t = 0; t < 2; t++) {                                \
            int k = bK[t];                                                             \
            int x = bX[t] ^ (k & 7);                                                   \
            *(uint4*)((char*)Bs[p] + k * 256 + x * 16) = pb[t];                        \
        }                                                                              \
    }

    LOADG(0);
    STOS(0);
    __syncthreads();

    for (int kk = 0; kk < 32; kk++) {
        int p = kk & 1;
        if (kk < 31) LOADG(kk + 1);

#pragma unroll
        for (int ks = 0; ks < 2; ks++) {
            uint32_t a[2][4];
#pragma unroll
            for (int mi = 0; mi < 2; mi++) {
                int row = wm * 32 + mi * 16 + (lane & 15);
                ldsm4(a[mi], sA[p] + row * 80 + (ks * 16 + (lane >> 4) * 8) * 2);
            }
            uint32_t bfr[4][4];
#pragma unroll
            for (int nb = 0; nb < 4; nb++) {
                int krow = ks * 16 + (lane & 7) + ((lane >> 3) & 1) * 8;
                int x = (wn * 8 + nb * 2 + (lane >> 4)) ^ (krow & 7);
                ldsm4t(bfr[nb], sB[p] + krow * 256 + x * 16);
            }
#pragma unroll
            for (int mi = 0; mi < 2; mi++)
#pragma unroll
                for (int nj = 0; nj < 8; nj++)
                    mma16816(acc[mi][nj], a[mi], bfr[nj >> 1][(nj & 1) * 2],
                             bfr[nj >> 1][(nj & 1) * 2 + 1]);
        }

        if (kk < 31) STOS(p ^ 1);
        __syncthreads();
    }
#undef LOADG
#undef STOS

#pragma unroll
    for (int mi = 0; mi < 2; mi++) {
        int r0 = o0 + wm * 32 + mi * 16 + (lane >> 2);
        float bi0 = bias ? bias[r0] : 0.0f;
        float bi1 = bias ? bias[r0 + 8] : 0.0f;
#pragma unroll
        for (int nj = 0; nj < 8; nj++) {
            int cb = l0 + wn * 64 + nj * 8 + (lane & 3) * 2;
            float2 v0 = make_float2(acc[mi][nj][0] + bi0, acc[mi][nj][1] + bi0);
            float2 v1 = make_float2(acc[mi][nj][2] + bi1, acc[mi][nj][3] + bi1);
            *(float2*)&C[(size_t)r0 * LL + cb] = v0;
            *(float2*)&C[(size_t)(r0 + 8) * LL + cb] = v1;
        }
    }
}

// grid = (LL/128, Cc/128, 3*Bb)
__global__ __launch_bounds__(256, 2) void k_gemm_qkv_mma() {
    int z = blockIdx.z;
    int w = z >> 3, b = z & 7;
    gemm_core(g_wsp + (size_t)w * 2 * Cc * Cc,
              g_s0b + (size_t)b * Cc * LL,
              g_y + (size_t)z * Cc * LL, nullptr);
}

// grid = (LL/128, Cc/128, Bb)
__global__ __launch_bounds__(256, 2) void k_gemm_out_mma(const float* __restrict__ bp,
                                                         float* __restrict__ out) {
    gemm_core(g_wsp + (size_t)3 * 2 * Cc * Cc,
              g_sattnb + (size_t)blockIdx.z * Cc * LL,
              out + (size_t)blockIdx.z * Cc * LL, bp);
}

// ---------------------------------------------------------------------------
// Kernel 3: per-branch BN + LIF (coalesced) with certified-margin flagging.
// ---------------------------------------------------------------------------
__global__ __launch_bounds__(256) void k_bn_lif_qkv(
        const float* __restrict__ gq, const float* __restrict__ bq,
        const float* __restrict__ mq, const float* __restrict__ vq,
        const float* __restrict__ gk, const float* __restrict__ bk,
        const float* __restrict__ mk, const float* __restrict__ vk,
        const float* __restrict__ gv, const float* __restrict__ bv,
        const float* __restrict__ mv, const float* __restrict__ vv) {
    int z = blockIdx.z;
    int w = z / Bb, b = z % Bb;
    int h = blockIdx.y;
    int n0 = blockIdx.x * 32;
    int tid = threadIdx.x, lane = tid & 31, wrp = tid >> 5;

    const float *gg, *bb, *mm, *vvv;
    if (w == 0) { gg = gq; bb = bq; mm = mq; vvv = vq; }
    else if (w == 1) { gg = gk; bb = bk; mm = mk; vvv = vk; }
    else { gg = gv; bb = bv; mm = mv; vvv = vv; }

    const bool isK = (w == 1);
    __shared__ bf16 sm[Tt][32][66];

#pragma unroll
    for (int i = 0; i < 8; i++) {
        int od = wrp * 8 + i;
        int o = h * 64 + od;
        float sc = gg[o] / sqrtf(vvv[o] + 1e-5f);
        float sh = bb[o] - mm[o] * sc;
        const float* yp = g_y + (size_t)((w * Bb + b) * Cc + o) * LL + n0 + lane;

        float de = (2.0f / 3.0f) * fabsf(sc) * EPSY;
        float e = 0.0f;
        bool flagged = false;

        float v = 0.0f;
#pragma unroll
        for (int t = 0; t < Tt; t++) {
            float yb = yp[(size_t)t * NN] * sc + sh;
            v = v + (yb - v) / 1.5f;
            e = e * (1.0f / 3.0f) + de;
            if (fabsf(v - 1.0f) < e) flagged = true;
            float s = (v >= 1.0f) ? 1.0f : 0.0f;
            if (isK)
                g_kb[(size_t)(b * Cc + o) * LL + t * NN + n0 + lane] = __float2bfloat16(s);
            else
                sm[t][lane][od] = __float2bfloat16(s);
            if (s != 0.0f) { v = 0.0f; e = 0.0f; }
        }
        if (flagged) {
            unsigned int pos = atomicAdd(&g_nflag, 1u);
            if (pos < FLAG_CAP)
                g_flag[pos] = ((unsigned)w << 20) | ((unsigned)b << 17) |
                              ((unsigned)o << 8) | (unsigned)(n0 + lane);
        }
    }

    if (!isK) {
        __syncthreads();
        bf16* dst = ((w == 0) ? g_qb : g_vb) + (size_t)(b * HH + h) * LL * DD;
#pragma unroll
        for (int j = 0; j < 16; j++) {
            int flat = tid + 256 * j;
            int row = flat >> 5, col = flat & 31;
            int t = row >> 5, n = row & 31;
            uint32_t val;
            memcpy(&val, &sm[t][n][col * 2], 4);
            *(uint32_t*)(dst + ((size_t)(t * NN + n0 + n)) * DD + col * 2) = val;
        }
    }
}

// ---------------------------------------------------------------------------
// Kernel 3f: WARP-COOPERATIVE exact fallback (one warp per flagged chain).
// ---------------------------------------------------------------------------
__global__ __launch_bounds__(128) void k_fallback(
        const float* __restrict__ wq, const float* __restrict__ wk,
        const float* __restrict__ wv,
        const float* __restrict__ gq, const float* __restrict__ bq,
        const float* __restrict__ mq, const float* __restrict__ vq,
        const float* __restrict__ gk, const float* __restrict__ bk,
        const float* __restrict__ mk, const float* __restrict__ vk,
        const float* __restrict__ gv, const float* __restrict__ bv,
        const float* __restrict__ mv, const float* __restrict__ vv) {
    __shared__ float prod[4][Tt][Cc];   // [warp][t][c] = 32 KB

    int lane = threadIdx.x & 31, wrp = threadIdx.x >> 5;
    unsigned int total = g_nflag;
    if (total > FLAG_CAP) total = FLAG_CAP;
    unsigned int gw = blockIdx.x * 4 + wrp;
    unsigned int nw = gridDim.x * 4;

    for (unsigned int i = gw; i < total; i += nw) {
        unsigned int enc = g_flag[i];
        int n = enc & 255;
        int o = (enc >> 8) & 511;
        int b = (enc >> 17) & 7;
        int w = enc >> 20;

        const float* W = (w == 0) ? wq : (w == 1) ? wk : wv;
        const float* Wrow = W + (size_t)o * Cc;
        const bf16* sbase = g_s0b + (size_t)b * Cc * LL + n;

        // Phase 1: parallel product fill (each product exact in fp32)
#pragma unroll
        for (int j = 0; j < 16; j++) {
            int c = lane + 32 * j;
            float wv_ = Wrow[c];
            const bf16* sp = sbase + (size_t)c * LL;
#pragma unroll
            for (int t = 0; t < Tt; t++)
                prod[wrp][t][c] = wv_ * __bfloat162float(sp[(size_t)t * NN]);
        }
        __syncwarp();

        // Phase 2: serial ascending-c sum (lanes 0..3, one t each)
        float yt = 0.0f;
        if (lane < Tt) {
            const float* pr = prod[wrp][lane];
#pragma unroll 16
            for (int c = 0; c < Cc; c++) yt += pr[c];
        }
        float y0 = __shfl_sync(0xffffffffu, yt, 0);
        float y1 = __shfl_sync(0xffffffffu, yt, 1);
        float y2 = __shfl_sync(0xffffffffu, yt, 2);
        float y3 = __shfl_sync(0xffffffffu, yt, 3);

        if (lane == 0) {
            float y[4] = {y0, y1, y2, y3};
            const float *gg, *bb, *mm, *vvv;
            if (w == 0) { gg = gq; bb = bq; mm = mq; vvv = vq; }
            else if (w == 1) { gg = gk; bb = bk; mm = mk; vvv = vk; }
            else { gg = gv; bb = bv; mm = mv; vvv = vv; }

            float sc = gg[o] / sqrtf(vvv[o] + 1e-5f);
            float sh = bb[o] - mm[o] * sc;
            int h = o >> 6, dd = o & 63;

            float v = 0.0f;
#pragma unroll
            for (int t = 0; t < Tt; t++) {
                float yb = y[t] * sc + sh;
                v = v + (yb - v) / 1.5f;
                float s = (v >= 1.0f) ? 1.0f : 0.0f;
                if (w == 1)
                    g_kb[(size_t)(b * Cc + o) * LL + t * NN + n] = __float2bfloat16(s);
                else {
                    bf16* base = (w == 0) ? g_qb : g_vb;
                    base[((size_t)(b * HH + h) * LL + t * NN + n) * DD + dd] =
                        __float2bfloat16(s);
                }
                if (s != 0.0f) v = 0.0f;
            }
        }
        __syncwarp();
    }
}

// ---------------------------------------------------------------------------
// Kernel 4: attention on tensor cores (exact), K/V double-buffered.
// ---------------------------------------------------------------------------
__global__ __launch_bounds__(256) void k_attn_mma() {
    int l0 = blockIdx.x * 128;
    int bh = blockIdx.y;
    int b = bh >> 3, h = bh & 7;

    const bf16* Q = g_qb + (size_t)bh * LL * DD;
    const bf16* K = g_kb + (size_t)(b * Cc + h * 64) * LL;
    const bf16* V = g_vb + (size_t)bh * LL * DD;

    __shared__ bf16 Qs[128 * 72];
    __shared__ bf16 Ks[2][64 * 64];
    __shared__ bf16 Vs[2][64 * 64];

    int tid = threadIdx.x, lane = tid & 31, warp = tid >> 5;
    const uint32_t sQ = smem_u32(Qs);
    const uint32_t sK[2] = {smem_u32(Ks[0]), smem_u32(Ks[1])};
    const uint32_t sV[2] = {smem_u32(Vs[0]), smem_u32(Vs[1])};

    int rr[2], cc[2], xx[2];
#pragma unroll
    for (int t = 0; t < 2; t++) {
        int id = tid + t * 256;
        rr[t] = id >> 3; cc[t] = id & 7;
        xx[t] = cc[t] ^ (rr[t] & 7);
    }
    uint4 pk[2], pv[2];

#define LDKV(k0)                                                                   \
    {                                                                              \
        _Pragma("unroll") for (int t = 0; t < 2; t++) {                            \
            pk[t] = *(const uint4*)(K + (size_t)rr[t] * LL + (k0) + cc[t] * 8);    \
            pv[t] = *(const uint4*)(V + (size_t)((k0) + rr[t]) * DD + cc[t] * 8);  \
        }                                                                          \
    }
#define STKV(p)                                                                    \
    {                                                                              \
        _Pragma("unroll") for (int t = 0; t < 2; t++) {                            \
            *(uint4*)((char*)Ks[p] + rr[t] * 128 + xx[t] * 16) = pk[t];            \
            *(uint4*)((char*)Vs[p] + rr[t] * 128 + xx[t] * 16) = pv[t];            \
        }                                                                          \
    }

#pragma unroll
    for (int t = 0; t < 4; t++) {
        int id = tid + t * 256;
        int r = id >> 3, c = id & 7;
        uint4 qv = *(const uint4*)(Q + (size_t)(l0 + r) * DD + c * 8);
        *(uint4*)((char*)Qs + r * 144 + c * 16) = qv;
    }
    LDKV(0);
    STKV(0);
    __syncthreads();

    uint32_t aq[4][4];
    {
        int row = warp * 16 + (lane & 15);
#pragma unroll
        for (int kc = 0; kc < 4; kc++)
            ldsm4(aq[kc], sQ + row * 144 + kc * 32 + (lane >> 4) * 16);
    }

    float oacc[8][4];
#pragma unroll
    for (int i = 0; i < 8; i++)
#pragma unroll
        for (int j = 0; j < 4; j++) oacc[i][j] = 0.0f;

    for (int it = 0; it < 16; it++) {
        int p = it & 1;
        if (it < 15) LDKV((it + 1) * 64);

        float sacc[8][4];
#pragma unroll
        for (int i = 0; i < 8; i++)
#pragma unroll
            for (int j = 0; j < 4; j++) sacc[i][j] = 0.0f;
#pragma unroll
        for (int nb = 0; nb < 4; nb++) {
#pragma unroll
            for (int ks = 0; ks < 4; ks++) {
                uint32_t bf[4];
                int krow = ks * 16 + (lane & 7) + ((lane >> 3) & 1) * 8;
                int ch = nb * 2 + (lane >> 4);
                int x = ch ^ (krow & 7);
                ldsm4t(bf, sK[p] + krow * 128 + x * 16);
                mma16816(sacc[nb * 2],     aq[ks], bf[0], bf[1]);
                mma16816(sacc[nb * 2 + 1], aq[ks], bf[2], bf[3]);
            }
        }
        uint32_t sa[4][4];
#pragma unroll
        for (int kb = 0; kb < 4; kb++) {
            sa[kb][0] = packbf(sacc[2 * kb][0],     sacc[2 * kb][1]);
            sa[kb][1] = packbf(sacc[2 * kb][2],     sacc[2 * kb][3]);
            sa[kb][2] = packbf(sacc[2 * kb + 1][0], sacc[2 * kb + 1][1]);
            sa[kb][3] = packbf(sacc[2 * kb + 1][2], sacc[2 * kb + 1][3]);
        }
#pragma unroll
        for (int nb = 0; nb < 4; nb++) {
#pragma unroll
            for (int kb = 0; kb < 4; kb++) {
                uint32_t bf[4];
                int krow = kb * 16 + (lane & 7) + ((lane >> 3) & 1) * 8;
                int ch = nb * 2 + (lane >> 4);
                int x = ch ^ (krow & 7);
                ldsm4t(bf, sV[p] + krow * 128 + x * 16);
                mma16816(oacc[nb * 2],     sa[kb], bf[0], bf[1]);
                mma16816(oacc[nb * 2 + 1], sa[kb], bf[2], bf[3]);
            }
        }

        if (it < 15) STKV(p ^ 1);
        __syncthreads();
    }
#undef LDKV
#undef STKV

    int row = warp * 16 + (lane >> 2);
#pragma unroll
    for (int nj = 0; nj < 8; nj++) {
        int col = nj * 8 + (lane & 3) * 2;
#pragma unroll
        for (int e = 0; e < 4; e++) {
            int r = row + (e >> 1) * 8;
            int c = col + (e & 1);
            float o = oacc[nj][e] * 0.125f;
            float s = ((o / 1.5f - 1.0f) >= 0.0f) ? 1.0f : 0.0f;
            g_sattnb[((size_t)b * Cc + h * 64 + c) * LL + (l0 + r)] = __float2bfloat16(s);
        }
    }
}

// ---------------------------------------------------------------------------
extern "C" void kernel_launch(void* const* d_in, const int* in_sizes, int n_in,
                              void* d_out, int out_size) {
    const float* x   = (const float*)d_in[0];
    const float* wq  = (const float*)d_in[1];
    const float* wk  = (const float*)d_in[2];
    const float* wv  = (const float*)d_in[3];
    const float* wp  = (const float*)d_in[4];
    const float* bp  = (const float*)d_in[5];
    const float* gq  = (const float*)d_in[6];
    const float* bq  = (const float*)d_in[7];
    const float* mq  = (const float*)d_in[8];
    const float* vq  = (const float*)d_in[9];
    const float* gk  = (const float*)d_in[10];
    const float* bk  = (const float*)d_in[11];
    const float* mk  = (const float*)d_in[12];
    const float* vk  = (const float*)d_in[13];
    const float* gv  = (const float*)d_in[14];
    const float* bv  = (const float*)d_in[15];
    const float* mv  = (const float*)d_in[16];
    const float* vv  = (const float*)d_in[17];
    const float* gp  = (const float*)d_in[18];
    const float* bpn = (const float*)d_in[19];
    const float* mp  = (const float*)d_in[20];
    const float* vp  = (const float*)d_in[21];
    float* out = (float*)d_out;

    k_prep<<<8192, 256>>>(wq, wk, wv, wp, x, gp, bpn, mp, vp);
    k_gemm_qkv_mma<<<dim3(LL / 128, Cc / 128, 3 * Bb), 256>>>();
    k_bn_lif_qkv<<<dim3(NN / 32, HH, 3 * Bb), 256>>>(gq, bq, mq, vq,
                                                     gk, bk, mk, vk,
                                                     gv, bv, mv, vv);
    k_fallback<<<1024, 128>>>(wq, wk, wv, gq, bq, mq, vq,
                              gk, bk, mk, vk, gv, bv, mv, vv);
    k_attn_mma<<<dim3(LL / 128, Bb * HH), 256>>>();
    k_gemm_out_mma<<<dim3(LL / 128, Cc / 128, Bb), 256>>>(bp, out);
}

// round 14
// speedup vs baseline: 1.8716x; 1.1179x over previous
#include <cuda_runtime.h>
#include <cuda_bf16.h>
#include <cstdint>

#define Bb 8
#define Cc 512
#define Tt 4
#define NN 256
#define LL 1024
#define HH 8
#define DD 64

#define EPSY 3e-4f
#define FLAG_CAP (1 << 20)

typedef __nv_bfloat16 bf16;

// Scratch
__device__ bf16  g_wsp[4 * 2 * Cc * Cc];   // [mat(q,k,v,p)][split(hi,mid)][o][c]
__device__ bf16  g_s0b[Bb * Cc * LL];      // proj spikes bf16 [b][c][l]
__device__ bf16  g_s0T[Bb * LL * Cc];      // proj spikes bf16 [b][l][c] (transposed)
__device__ float g_y[3 * Bb * Cc * LL];    // qkv pre-activation fp32
__device__ bf16  g_qb[Bb * HH * LL * DD];  // q spikes [b][h][l][d]
__device__ bf16  g_kb[Bb * Cc * LL];       // k spikes [b][c][l]
__device__ bf16  g_vb[Bb * HH * LL * DD];  // v spikes [b][h][l][d]
__device__ bf16  g_sattnb[Bb * Cc * LL];   // attn spikes [b][c][l]
__device__ unsigned int g_nflag;
__device__ unsigned int g_flag[FLAG_CAP];  // (w<<20)|(b<<17)|(o<<8)|n

// ---------------------------------------------------------------------------
__device__ __forceinline__ uint32_t smem_u32(const void* p) {
    return (uint32_t)__cvta_generic_to_shared(p);
}
__device__ __forceinline__ void ldsm4(uint32_t* r, uint32_t a) {
    asm volatile("ldmatrix.sync.aligned.m8n8.x4.shared.b16 {%0,%1,%2,%3}, [%4];"
                 : "=r"(r[0]), "=r"(r[1]), "=r"(r[2]), "=r"(r[3]) : "r"(a));
}
__device__ __forceinline__ void ldsm4t(uint32_t* r, uint32_t a) {
    asm volatile("ldmatrix.sync.aligned.m8n8.x4.trans.shared.b16 {%0,%1,%2,%3}, [%4];"
                 : "=r"(r[0]), "=r"(r[1]), "=r"(r[2]), "=r"(r[3]) : "r"(a));
}
__device__ __forceinline__ void mma16816(float* c, const uint32_t* a, uint32_t b0, uint32_t b1) {
    asm volatile(
        "mma.sync.aligned.m16n8k16.row.col.f32.bf16.bf16.f32 "
        "{%0,%1,%2,%3}, {%4,%5,%6,%7}, {%8,%9}, {%0,%1,%2,%3};"
        : "+f"(c[0]), "+f"(c[1]), "+f"(c[2]), "+f"(c[3])
        : "r"(a[0]), "r"(a[1]), "r"(a[2]), "r"(a[3]), "r"(b0), "r"(b1));
}
__device__ __forceinline__ uint32_t packbf(float lo, float hi) {
    uint32_t l = (uint32_t)__bfloat16_as_ushort(__float2bfloat16(lo));
    uint32_t h = (uint32_t)__bfloat16_as_ushort(__float2bfloat16(hi));
    return l | (h << 16);
}

// ---------------------------------------------------------------------------
// Kernel 1 (fused prep): blocks [0,4096) = 2-way bf16 split of 4 weights;
// blocks [4096,8192) = proj BN + multi-step LIF -> g_s0b. Also zeroes flags.
// ---------------------------------------------------------------------------
__global__ void k_prep(const float* __restrict__ wq, const float* __restrict__ wk,
                       const float* __restrict__ wv, const float* __restrict__ wp,
                       const float* __restrict__ x,
                       const float* __restrict__ gp, const float* __restrict__ bpn,
                       const float* __restrict__ mp, const float* __restrict__ vp) {
    if (blockIdx.x == 0 && threadIdx.x == 0) g_nflag = 0;
    if (blockIdx.x < 4096) {
        int idx = blockIdx.x * 256 + threadIdx.x;   // over 4*Cc*Cc
        int m = idx / (Cc * Cc);
        int rc = idx % (Cc * Cc);
        const float* W = (m == 0) ? wq : (m == 1) ? wk : (m == 2) ? wv : wp;
        float w = W[rc];
        bf16 hi = __float2bfloat16(w);
        float r1 = w - __bfloat162float(hi);
        g_wsp[(size_t)(m * 2 + 0) * Cc * Cc + rc] = hi;
        g_wsp[(size_t)(m * 2 + 1) * Cc * Cc + rc] = __float2bfloat16(r1);
    } else {
        int idx = (blockIdx.x - 4096) * 256 + threadIdx.x;  // over B*C*NN
        int n = idx % NN;
        int c = (idx / NN) % Cc;
        int b = idx / (NN * Cc);

        float sc = gp[c] / sqrtf(vp[c] + 1e-5f);
        float sh = bpn[c] - mp[c] * sc;

        const float* xp = x + ((size_t)(b * Cc + c) * Tt) * NN + n;
        bf16* sp = g_s0b + (size_t)(b * Cc + c) * LL + n;

        float v = 0.0f;
#pragma unroll
        for (int t = 0; t < Tt; t++) {
            float xb = xp[(size_t)t * NN] * sc + sh;
            v = v + (xb - v) / 1.5f;
            float s = (v >= 1.0f) ? 1.0f : 0.0f;
            sp[(size_t)t * NN] = __float2bfloat16(s);
            if (s != 0.0f) v = 0.0f;
        }
    }
}

// ---------------------------------------------------------------------------
// Kernel 1b: transpose g_s0b [b][c][l] -> g_s0T [b][l][c] via smem tiles.
// grid = (LL/32, Cc/64, Bb), block 256.
// ---------------------------------------------------------------------------
__global__ __launch_bounds__(256) void k_s0T() {
    int b = blockIdx.z;
    int c0 = blockIdx.y * 64;
    int l0 = blockIdx.x * 32;
    int tid = threadIdx.x, lane = tid & 31, wrp = tid >> 5;

    __shared__ bf16 sm[32][72];   // [l][c], 144B rows (16B-aligned)

#pragma unroll
    for (int i = 0; i < 8; i++) {
        int cl = wrp * 8 + i;
        sm[lane][cl] = g_s0b[((size_t)(b * Cc + c0 + cl)) * LL + l0 + lane];
    }
    __syncthreads();

    int l = tid >> 3, c8 = (tid & 7) * 8;
    uint4 v;
    memcpy(&v, &sm[l][c8], 16);
    *(uint4*)&g_s0T[((size_t)b * LL + l0 + l) * Cc + c0 + c8] = v;
}

// ---------------------------------------------------------------------------
// Tensor-core GEMM core: C[512,1024] = A(2 splits, K'=1024) @ B.
// Double-buffered smem, ONE __syncthreads per k-step.
// ---------------------------------------------------------------------------
__device__ __forceinline__ void gemm_core(const bf16* __restrict__ A,
                                          const bf16* __restrict__ B,
                                          float* __restrict__ C,
                                          const float* __restrict__ bias) {
    __shared__ bf16 As[2][128 * 40];
    __shared__ bf16 Bs[2][32 * 128];

    const int tid = threadIdx.x;
    const int lane = tid & 31, warp = tid >> 5;
    const int wm = warp >> 1, wn = warp & 1;
    const int o0 = blockIdx.y * 128, l0 = blockIdx.x * 128;

    float acc[2][8][4];
#pragma unroll
    for (int i = 0; i < 2; i++)
#pragma unroll
        for (int j = 0; j < 8; j++)
#pragma unroll
            for (int k = 0; k < 4; k++) acc[i][j][k] = 0.0f;

    int aM[2], aK[2], bK[2], bX[2];
#pragma unroll
    for (int t = 0; t < 2; t++) {
        int id = tid + t * 256;
        aM[t] = id >> 2; aK[t] = id & 3;
        bK[t] = id >> 4; bX[t] = id & 15;
    }
    uint4 pa[2], pb[2];
    const uint32_t sA[2] = {smem_u32(As[0]), smem_u32(As[1])};
    const uint32_t sB[2] = {smem_u32(Bs[0]), smem_u32(Bs[1])};

#define LOADG(kk)                                                                      \
    {                                                                                  \
        int split = ((kk) * 32) >> 9;                                                  \
        int c0 = ((kk) * 32) & 511;                                                    \
        const bf16* Ab = A + (size_t)split * (Cc * Cc);                                \
        _Pragma("unroll") for (int t = 0; t < 2; t++)                                  \
            pa[t] = *(const uint4*)(Ab + (size_t)(o0 + aM[t]) * Cc + c0 + aK[t] * 8);  \
        _Pragma("unroll") for (int t = 0; t < 2; t++)                                  \
            pb[t] = *(const uint4*)(B + (size_t)(c0 + bK[t]) * LL + l0 + bX[t] * 8);   \
    }
#define STOS(p)                                                                        \
    {                                                                                  \
        _Pragma("unroll") for (int t = 0; t < 2; t++)                                  \
            *(uint4*)((char*)As[p] + aM[t] * 80 + aK[t] * 16) = pa[t];                 \
        _Pragma("unroll") for (int t = 0; t < 2; t++) {                                \
            int k = bK[t];                                                             \
            int x = bX[t] ^ (k & 7);                                                   \
            *(uint4*)((char*)Bs[p] + k * 256 + x * 16) = pb[t];                        \
        }                                                                              \
    }

    LOADG(0);
    STOS(0);
    __syncthreads();

    for (int kk = 0; kk < 32; kk++) {
        int p = kk & 1;
        if (kk < 31) LOADG(kk + 1);

#pragma unroll
        for (int ks = 0; ks < 2; ks++) {
            uint32_t a[2][4];
#pragma unroll
            for (int mi = 0; mi < 2; mi++) {
                int row = wm * 32 + mi * 16 + (lane & 15);
                ldsm4(a[mi], sA[p] + row * 80 + (ks * 16 + (lane >> 4) * 8) * 2);
            }
            uint32_t bfr[4][4];
#pragma unroll
            for (int nb = 0; nb < 4; nb++) {
                int krow = ks * 16 + (lane & 7) + ((lane >> 3) & 1) * 8;
                int x = (wn * 8 + nb * 2 + (lane >> 4)) ^ (krow & 7);
                ldsm4t(bfr[nb], sB[p] + krow * 256 + x * 16);
            }
#pragma unroll
            for (int mi = 0; mi < 2; mi++)
#pragma unroll
                for (int nj = 0; nj < 8; nj++)
                    mma16816(acc[mi][nj], a[mi], bfr[nj >> 1][(nj & 1) * 2],
                             bfr[nj >> 1][(nj & 1) * 2 + 1]);
        }

        if (kk < 31) STOS(p ^ 1);
        __syncthreads();
    }
#undef LOADG
#undef STOS

#pragma unroll
    for (int mi = 0; mi < 2; mi++) {
        int r0 = o0 + wm * 32 + mi * 16 + (lane >> 2);
        float bi0 = bias ? bias[r0] : 0.0f;
        float bi1 = bias ? bias[r0 + 8] : 0.0f;
#pragma unroll
        for (int nj = 0; nj < 8; nj++) {
            int cb = l0 + wn * 64 + nj * 8 + (lane & 3) * 2;
            float2 v0 = make_float2(acc[mi][nj][0] + bi0, acc[mi][nj][1] + bi0);
            float2 v1 = make_float2(acc[mi][nj][2] + bi1, acc[mi][nj][3] + bi1);
            *(float2*)&C[(size_t)r0 * LL + cb] = v0;
            *(float2*)&C[(size_t)(r0 + 8) * LL + cb] = v1;
        }
    }
}

// grid = (LL/128, Cc/128, 3*Bb)
__global__ __launch_bounds__(256, 2) void k_gemm_qkv_mma() {
    int z = blockIdx.z;
    int w = z >> 3, b = z & 7;
    gemm_core(g_wsp + (size_t)w * 2 * Cc * Cc,
              g_s0b + (size_t)b * Cc * LL,
              g_y + (size_t)z * Cc * LL, nullptr);
}

// grid = (LL/128, Cc/128, Bb)
__global__ __launch_bounds__(256, 2) void k_gemm_out_mma(const float* __restrict__ bp,
                                                         float* __restrict__ out) {
    gemm_core(g_wsp + (size_t)3 * 2 * Cc * Cc,
              g_sattnb + (size_t)blockIdx.z * Cc * LL,
              out + (size_t)blockIdx.z * Cc * LL, bp);
}

// ---------------------------------------------------------------------------
// Kernel 3: per-branch BN + LIF (coalesced) with certified-margin flagging.
// ---------------------------------------------------------------------------
__global__ __launch_bounds__(256) void k_bn_lif_qkv(
        const float* __restrict__ gq, const float* __restrict__ bq,
        const float* __restrict__ mq, const float* __restrict__ vq,
        const float* __restrict__ gk, const float* __restrict__ bk,
        const float* __restrict__ mk, const float* __restrict__ vk,
        const float* __restrict__ gv, const float* __restrict__ bv,
        const float* __restrict__ mv, const float* __restrict__ vv) {
    int z = blockIdx.z;
    int w = z / Bb, b = z % Bb;
    int h = blockIdx.y;
    int n0 = blockIdx.x * 32;
    int tid = threadIdx.x, lane = tid & 31, wrp = tid >> 5;

    const float *gg, *bb, *mm, *vvv;
    if (w == 0) { gg = gq; bb = bq; mm = mq; vvv = vq; }
    else if (w == 1) { gg = gk; bb = bk; mm = mk; vvv = vk; }
    else { gg = gv; bb = bv; mm = mv; vvv = vv; }

    const bool isK = (w == 1);
    __shared__ bf16 sm[Tt][32][66];

#pragma unroll
    for (int i = 0; i < 8; i++) {
        int od = wrp * 8 + i;
        int o = h * 64 + od;
        float sc = gg[o] / sqrtf(vvv[o] + 1e-5f);
        float sh = bb[o] - mm[o] * sc;
        const float* yp = g_y + (size_t)((w * Bb + b) * Cc + o) * LL + n0 + lane;

        float de = (2.0f / 3.0f) * fabsf(sc) * EPSY;
        float e = 0.0f;
        bool flagged = false;

        float v = 0.0f;
#pragma unroll
        for (int t = 0; t < Tt; t++) {
            float yb = yp[(size_t)t * NN] * sc + sh;
            v = v + (yb - v) / 1.5f;
            e = e * (1.0f / 3.0f) + de;
            if (fabsf(v - 1.0f) < e) flagged = true;
            float s = (v >= 1.0f) ? 1.0f : 0.0f;
            if (isK)
                g_kb[(size_t)(b * Cc + o) * LL + t * NN + n0 + lane] = __float2bfloat16(s);
            else
                sm[t][lane][od] = __float2bfloat16(s);
            if (s != 0.0f) { v = 0.0f; e = 0.0f; }
        }
        if (flagged) {
            unsigned int pos = atomicAdd(&g_nflag, 1u);
            if (pos < FLAG_CAP)
                g_flag[pos] = ((unsigned)w << 20) | ((unsigned)b << 17) |
                              ((unsigned)o << 8) | (unsigned)(n0 + lane);
        }
    }

    if (!isK) {
        __syncthreads();
        bf16* dst = ((w == 0) ? g_qb : g_vb) + (size_t)(b * HH + h) * LL * DD;
#pragma unroll
        for (int j = 0; j < 16; j++) {
            int flat = tid + 256 * j;
            int row = flat >> 5, col = flat & 31;
            int t = row >> 5, n = row & 31;
            uint32_t val;
            memcpy(&val, &sm[t][n][col * 2], 4);
            *(uint32_t*)(dst + ((size_t)(t * NN + n0 + n)) * DD + col * 2) = val;
        }
    }
}

// ---------------------------------------------------------------------------
// Kernel 3f: bitmask warp fallback.
// Per chain: (a) warp loads W row coalesced into smem; (b) warp loads spikes
// from g_s0T coalesced, ballots into bitmasks; (c) lanes 0..3 sum ONLY set
// bits in ascending c (bit-identical: fma(w,0,acc)=acc, fma(w,1,acc)=acc+w).
// 8 warps/block, 2048 blocks.
// ---------------------------------------------------------------------------
__global__ __launch_bounds__(256) void k_fallback(
        const float* __restrict__ wq, const float* __restrict__ wk,
        const float* __restrict__ wv,
        const float* __restrict__ gq, const float* __restrict__ bq,
        const float* __restrict__ mq, const float* __restrict__ vq,
        const float* __restrict__ gk, const float* __restrict__ bk,
        const float* __restrict__ mk, const float* __restrict__ vk,
        const float* __restrict__ gv, const float* __restrict__ bv,
        const float* __restrict__ mv, const float* __restrict__ vv) {
    __shared__ float Wsm[8][Cc];          // 16 KB
    __shared__ uint32_t msm[8][Tt][16];   // 2 KB

    int lane = threadIdx.x & 31, wrp = threadIdx.x >> 5;
    unsigned int total = g_nflag;
    if (total > FLAG_CAP) total = FLAG_CAP;
    unsigned int gw = blockIdx.x * 8 + wrp;
    unsigned int nw = gridDim.x * 8;

    for (unsigned int i = gw; i < total; i += nw) {
        unsigned int enc = g_flag[i];
        int n = enc & 255;
        int o = (enc >> 8) & 511;
        int b = (enc >> 17) & 7;
        int w = enc >> 20;

        const float* W = (w == 0) ? wq : (w == 1) ? wk : wv;
        const float* Wrow = W + (size_t)o * Cc;

        // (a)+(b): coalesced W row load + spike ballots
#pragma unroll
        for (int j = 0; j < 16; j++) {
            int c = lane + 32 * j;
            Wsm[wrp][c] = Wrow[c];
#pragma unroll
            for (int t = 0; t < Tt; t++) {
                bf16 s = g_s0T[((size_t)b * LL + t * NN + n) * Cc + c];
                unsigned m = __ballot_sync(0xffffffffu,
                                           __bfloat16_as_ushort(s) != 0);
                if (lane == 0) msm[wrp][t][j] = m;
            }
        }
        __syncwarp();

        // (c): lanes 0..3 sum set bits ascending c
        float yt = 0.0f;
        if (lane < Tt) {
#pragma unroll
            for (int j = 0; j < 16; j++) {
                unsigned m = msm[wrp][lane][j];
                while (m) {
                    int cb = __ffs(m) - 1;
                    m &= m - 1;
                    yt += Wsm[wrp][32 * j + cb];
                }
            }
        }
        float y0 = __shfl_sync(0xffffffffu, yt, 0);
        float y1 = __shfl_sync(0xffffffffu, yt, 1);
        float y2 = __shfl_sync(0xffffffffu, yt, 2);
        float y3 = __shfl_sync(0xffffffffu, yt, 3);

        if (lane == 0) {
            float y[4] = {y0, y1, y2, y3};
            const float *gg, *bb, *mm, *vvv;
            if (w == 0) { gg = gq; bb = bq; mm = mq; vvv = vq; }
            else if (w == 1) { gg = gk; bb = bk; mm = mk; vvv = vk; }
            else { gg = gv; bb = bv; mm = mv; vvv = vv; }

            float sc = gg[o] / sqrtf(vvv[o] + 1e-5f);
            float sh = bb[o] - mm[o] * sc;
            int h = o >> 6, dd = o & 63;

            float v = 0.0f;
#pragma unroll
            for (int t = 0; t < Tt; t++) {
                float yb = y[t] * sc + sh;
                v = v + (yb - v) / 1.5f;
                float s = (v >= 1.0f) ? 1.0f : 0.0f;
                if (w == 1)
                    g_kb[(size_t)(b * Cc + o) * LL + t * NN + n] = __float2bfloat16(s);
                else {
                    bf16* base = (w == 0) ? g_qb : g_vb;
                    base[((size_t)(b * HH + h) * LL + t * NN + n) * DD + dd] =
                        __float2bfloat16(s);
                }
                if (s != 0.0f) v = 0.0f;
            }
        }
        __syncwarp();
    }
}

// ---------------------------------------------------------------------------
// Kernel 4: attention on tensor cores (exact), K/V double-buffered.
// ---------------------------------------------------------------------------
__global__ __launch_bounds__(256) void k_attn_mma() {
    int l0 = blockIdx.x * 128;
    int bh = blockIdx.y;
    int b = bh >> 3, h = bh & 7;

    const bf16* Q = g_qb + (size_t)bh * LL * DD;
    const bf16* K = g_kb + (size_t)(b * Cc + h * 64) * LL;
    const bf16* V = g_vb + (size_t)bh * LL * DD;

    __shared__ bf16 Qs[128 * 72];
    __shared__ bf16 Ks[2][64 * 64];
    __shared__ bf16 Vs[2][64 * 64];

    int tid = threadIdx.x, lane = tid & 31, warp = tid >> 5;
    const uint32_t sQ = smem_u32(Qs);
    const uint32_t sK[2] = {smem_u32(Ks[0]), smem_u32(Ks[1])};
    const uint32_t sV[2] = {smem_u32(Vs[0]), smem_u32(Vs[1])};

    int rr[2], cc[2], xx[2];
#pragma unroll
    for (int t = 0; t < 2; t++) {
        int id = tid + t * 256;
        rr[t] = id >> 3; cc[t] = id & 7;
        xx[t] = cc[t] ^ (rr[t] & 7);
    }
    uint4 pk[2], pv[2];

#define LDKV(k0)                                                                   \
    {                                                                              \
        _Pragma("unroll") for (int t = 0; t < 2; t++) {                            \
            pk[t] = *(const uint4*)(K + (size_t)rr[t] * LL + (k0) + cc[t] * 8);    \
            pv[t] = *(const uint4*)(V + (size_t)((k0) + rr[t]) * DD + cc[t] * 8);  \
        }                                                                          \
    }
#define STKV(p)                                                                    \
    {                                                                              \
        _Pragma("unroll") for (int t = 0; t < 2; t++) {                            \
            *(uint4*)((char*)Ks[p] + rr[t] * 128 + xx[t] * 16) = pk[t];            \
            *(uint4*)((char*)Vs[p] + rr[t] * 128 + xx[t] * 16) = pv[t];            \
        }                                                                          \
    }

#pragma unroll
    for (int t = 0; t < 4; t++) {
        int id = tid + t * 256;
        int r = id >> 3, c = id & 7;
        uint4 qv = *(const uint4*)(Q + (size_t)(l0 + r) * DD + c * 8);
        *(uint4*)((char*)Qs + r * 144 + c * 16) = qv;
    }
    LDKV(0);
    STKV(0);
    __syncthreads();

    uint32_t aq[4][4];
    {
        int row = warp * 16 + (lane & 15);
#pragma unroll
        for (int kc = 0; kc < 4; kc++)
            ldsm4(aq[kc], sQ + row * 144 + kc * 32 + (lane >> 4) * 16);
    }

    float oacc[8][4];
#pragma unroll
    for (int i = 0; i < 8; i++)
#pragma unroll
        for (int j = 0; j < 4; j++) oacc[i][j] = 0.0f;

    for (int it = 0; it < 16; it++) {
        int p = it & 1;
        if (it < 15) LDKV((it + 1) * 64);

        float sacc[8][4];
#pragma unroll
        for (int i = 0; i < 8; i++)
#pragma unroll
            for (int j = 0; j < 4; j++) sacc[i][j] = 0.0f;
#pragma unroll
        for (int nb = 0; nb < 4; nb++) {
#pragma unroll
            for (int ks = 0; ks < 4; ks++) {
                uint32_t bf[4];
                int krow = ks * 16 + (lane & 7) + ((lane >> 3) & 1) * 8;
                int ch = nb * 2 + (lane >> 4);
                int x = ch ^ (krow & 7);
                ldsm4t(bf, sK[p] + krow * 128 + x * 16);
                mma16816(sacc[nb * 2],     aq[ks], bf[0], bf[1]);
                mma16816(sacc[nb * 2 + 1], aq[ks], bf[2], bf[3]);
            }
        }
        uint32_t sa[4][4];
#pragma unroll
        for (int kb = 0; kb < 4; kb++) {
            sa[kb][0] = packbf(sacc[2 * kb][0],     sacc[2 * kb][1]);
            sa[kb][1] = packbf(sacc[2 * kb][2],     sacc[2 * kb][3]);
            sa[kb][2] = packbf(sacc[2 * kb + 1][0], sacc[2 * kb + 1][1]);
            sa[kb][3] = packbf(sacc[2 * kb + 1][2], sacc[2 * kb + 1][3]);
        }
#pragma unroll
        for (int nb = 0; nb < 4; nb++) {
#pragma unroll
            for (int kb = 0; kb < 4; kb++) {
                uint32_t bf[4];
                int krow = kb * 16 + (lane & 7) + ((lane >> 3) & 1) * 8;
                int ch = nb * 2 + (lane >> 4);
                int x = ch ^ (krow & 7);
                ldsm4t(bf, sV[p] + krow * 128 + x * 16);
                mma16816(oacc[nb * 2],     sa[kb], bf[0], bf[1]);
                mma16816(oacc[nb * 2 + 1], sa[kb], bf[2], bf[3]);
            }
        }

        if (it < 15) STKV(p ^ 1);
        __syncthreads();
    }
#undef LDKV
#undef STKV

    int row = warp * 16 + (lane >> 2);
#pragma unroll
    for (int nj = 0; nj < 8; nj++) {
        int col = nj * 8 + (lane & 3) * 2;
#pragma unroll
        for (int e = 0; e < 4; e++) {
            int r = row + (e >> 1) * 8;
            int c = col + (e & 1);
            float o = oacc[nj][e] * 0.125f;
            float s = ((o / 1.5f - 1.0f) >= 0.0f) ? 1.0f : 0.0f;
            g_sattnb[((size_t)b * Cc + h * 64 + c) * LL + (l0 + r)] = __float2bfloat16(s);
        }
    }
}

// ---------------------------------------------------------------------------
extern "C" void kernel_launch(void* const* d_in, const int* in_sizes, int n_in,
                              void* d_out, int out_size) {
    const float* x   = (const float*)d_in[0];
    const float* wq  = (const float*)d_in[1];
    const float* wk  = (const float*)d_in[2];
    const float* wv  = (const float*)d_in[3];
    const float* wp  = (const float*)d_in[4];
    const float* bp  = (const float*)d_in[5];
    const float* gq  = (const float*)d_in[6];
    const float* bq  = (const float*)d_in[7];
    const float* mq  = (const float*)d_in[8];
    const float* vq  = (const float*)d_in[9];
    const float* gk  = (const float*)d_in[10];
    const float* bk  = (const float*)d_in[11];
    const float* mk  = (const float*)d_in[12];
    const float* vk  = (const float*)d_in[13];
    const float* gv  = (const float*)d_in[14];
    const float* bv  = (const float*)d_in[15];
    const float* mv  = (const float*)d_in[16];
    const float* vv  = (const float*)d_in[17];
    const float* gp  = (const float*)d_in[18];
    const float* bpn = (const float*)d_in[19];
    const float* mp  = (const float*)d_in[20];
    const float* vp  = (const float*)d_in[21];
    float* out = (float*)d_out;

    k_prep<<<8192, 256>>>(wq, wk, wv, wp, x, gp, bpn, mp, vp);
    k_s0T<<<dim3(LL / 32, Cc / 64, Bb), 256>>>();
    k_gemm_qkv_mma<<<dim3(LL / 128, Cc / 128, 3 * Bb), 256>>>();
    k_bn_lif_qkv<<<dim3(NN / 32, HH, 3 * Bb), 256>>>(gq, bq, mq, vq,
                                                     gk, bk, mk, vk,
                                                     gv, bv, mv, vv);
    k_fallback<<<2048, 256>>>(wq, wk, wv, gq, bq, mq, vq,
                              gk, bk, mk, vk, gv, bv, mv, vv);
    k_attn_mma<<<dim3(LL / 128, Bb * HH), 256>>>();
    k_gemm_out_mma<<<dim3(LL / 128, Cc / 128, Bb), 256>>>(bp, out);
}

// round 15
// speedup vs baseline: 1.9580x; 1.0462x over previous
#include <cuda_runtime.h>
#include <cuda_bf16.h>
#include <cstdint>

#define Bb 8
#define Cc 512
#define Tt 4
#define NN 256
#define LL 1024
#define HH 8
#define DD 64

#define EPSY 3e-4f
#define FLAG_CAP (1 << 20)

typedef __nv_bfloat16 bf16;

// Scratch
__device__ bf16  g_wsp[4 * 2 * Cc * Cc];   // [mat(q,k,v,p)][split(hi,mid)][o][c]
__device__ bf16  g_s0b[Bb * Cc * LL];      // proj spikes bf16 [b][c][l]
__device__ bf16  g_s0T[Bb * LL * Cc];      // proj spikes bf16 [b][l][c]
__device__ float g_y[3 * Bb * Cc * LL];    // qkv pre-activation fp32
__device__ bf16  g_qb[Bb * HH * LL * DD];  // q spikes [b][h][l][d]
__device__ bf16  g_kb[Bb * Cc * LL];       // k spikes [b][c][l]
__device__ bf16  g_vb[Bb * HH * LL * DD];  // v spikes [b][h][l][d]
__device__ bf16  g_sattnb[Bb * Cc * LL];   // attn spikes [b][c][l]
__device__ unsigned int g_nflag;
__device__ unsigned int g_flag[FLAG_CAP];  // (w<<20)|(b<<17)|(o<<8)|n

// ---------------------------------------------------------------------------
__device__ __forceinline__ uint32_t smem_u32(const void* p) {
    return (uint32_t)__cvta_generic_to_shared(p);
}
__device__ __forceinline__ void ldsm4(uint32_t* r, uint32_t a) {
    asm volatile("ldmatrix.sync.aligned.m8n8.x4.shared.b16 {%0,%1,%2,%3}, [%4];"
                 : "=r"(r[0]), "=r"(r[1]), "=r"(r[2]), "=r"(r[3]) : "r"(a));
}
__device__ __forceinline__ void ldsm4t(uint32_t* r, uint32_t a) {
    asm volatile("ldmatrix.sync.aligned.m8n8.x4.trans.shared.b16 {%0,%1,%2,%3}, [%4];"
                 : "=r"(r[0]), "=r"(r[1]), "=r"(r[2]), "=r"(r[3]) : "r"(a));
}
__device__ __forceinline__ void mma16816(float* c, const uint32_t* a, uint32_t b0, uint32_t b1) {
    asm volatile(
        "mma.sync.aligned.m16n8k16.row.col.f32.bf16.bf16.f32 "
        "{%0,%1,%2,%3}, {%4,%5,%6,%7}, {%8,%9}, {%0,%1,%2,%3};"
        : "+f"(c[0]), "+f"(c[1]), "+f"(c[2]), "+f"(c[3])
        : "r"(a[0]), "r"(a[1]), "r"(a[2]), "r"(a[3]), "r"(b0), "r"(b1));
}
__device__ __forceinline__ uint32_t packbf(float lo, float hi) {
    uint32_t l = (uint32_t)__bfloat16_as_ushort(__float2bfloat16(lo));
    uint32_t h = (uint32_t)__bfloat16_as_ushort(__float2bfloat16(hi));
    return l | (h << 16);
}
__device__ __forceinline__ void cpasync16(uint32_t s, const void* g) {
    asm volatile("cp.async.cg.shared.global [%0], [%1], 16;" :: "r"(s), "l"(g));
}
#define CP_COMMIT() asm volatile("cp.async.commit_group;" ::: "memory")
#define CP_WAIT0()  asm volatile("cp.async.wait_group 0;" ::: "memory")

// ---------------------------------------------------------------------------
// Kernel 1 (fused prep): blocks [0,4096) = 2-way bf16 split of 4 weights;
// blocks [4096,8192) = proj BN + multi-step LIF -> g_s0b. Also zeroes flags.
// ---------------------------------------------------------------------------
__global__ void k_prep(const float* __restrict__ wq, const float* __restrict__ wk,
                       const float* __restrict__ wv, const float* __restrict__ wp,
                       const float* __restrict__ x,
                       const float* __restrict__ gp, const float* __restrict__ bpn,
                       const float* __restrict__ mp, const float* __restrict__ vp) {
    if (blockIdx.x == 0 && threadIdx.x == 0) g_nflag = 0;
    if (blockIdx.x < 4096) {
        int idx = blockIdx.x * 256 + threadIdx.x;
        int m = idx / (Cc * Cc);
        int rc = idx % (Cc * Cc);
        const float* W = (m == 0) ? wq : (m == 1) ? wk : (m == 2) ? wv : wp;
        float w = W[rc];
        bf16 hi = __float2bfloat16(w);
        float r1 = w - __bfloat162float(hi);
        g_wsp[(size_t)(m * 2 + 0) * Cc * Cc + rc] = hi;
        g_wsp[(size_t)(m * 2 + 1) * Cc * Cc + rc] = __float2bfloat16(r1);
    } else {
        int idx = (blockIdx.x - 4096) * 256 + threadIdx.x;
        int n = idx % NN;
        int c = (idx / NN) % Cc;
        int b = idx / (NN * Cc);

        float sc = gp[c] / sqrtf(vp[c] + 1e-5f);
        float sh = bpn[c] - mp[c] * sc;

        const float* xp = x + ((size_t)(b * Cc + c) * Tt) * NN + n;
        bf16* sp = g_s0b + (size_t)(b * Cc + c) * LL + n;

        float xv[4];
#pragma unroll
        for (int t = 0; t < Tt; t++) xv[t] = xp[(size_t)t * NN];

        float v = 0.0f;
#pragma unroll
        for (int t = 0; t < Tt; t++) {
            float xb = xv[t] * sc + sh;
            v = v + (xb - v) / 1.5f;
            float s = (v >= 1.0f) ? 1.0f : 0.0f;
            sp[(size_t)t * NN] = __float2bfloat16(s);
            if (s != 0.0f) v = 0.0f;
        }
    }
}

// ---------------------------------------------------------------------------
// Kernel 1b: transpose g_s0b [b][c][l] -> g_s0T [b][l][c].
// ---------------------------------------------------------------------------
__global__ __launch_bounds__(256) void k_s0T() {
    int b = blockIdx.z;
    int c0 = blockIdx.y * 64;
    int l0 = blockIdx.x * 32;
    int tid = threadIdx.x, lane = tid & 31, wrp = tid >> 5;

    __shared__ bf16 sm[32][72];

#pragma unroll
    for (int i = 0; i < 8; i++) {
        int cl = wrp * 8 + i;
        sm[lane][cl] = g_s0b[((size_t)(b * Cc + c0 + cl)) * LL + l0 + lane];
    }
    __syncthreads();

    int l = tid >> 3, c8 = (tid & 7) * 8;
    uint4 v;
    memcpy(&v, &sm[l][c8], 16);
    *(uint4*)&g_s0T[((size_t)b * LL + l0 + l) * Cc + c0 + c8] = v;
}

// ---------------------------------------------------------------------------
// Tensor-core GEMM core: C[512,1024] = A(2 splits, K'=1024) @ B.
// cp.async double-buffer, ONE __syncthreads per k-step. MMA order unchanged.
// ---------------------------------------------------------------------------
__device__ __forceinline__ void gemm_core(const bf16* __restrict__ A,
                                          const bf16* __restrict__ B,
                                          float* __restrict__ C,
                                          const float* __restrict__ bias) {
    __shared__ bf16 As[2][128 * 40];
    __shared__ bf16 Bs[2][32 * 128];

    const int tid = threadIdx.x;
    const int lane = tid & 31, warp = tid >> 5;
    const int wm = warp >> 1, wn = warp & 1;
    const int o0 = blockIdx.y * 128, l0 = blockIdx.x * 128;

    float acc[2][8][4];
#pragma unroll
    for (int i = 0; i < 2; i++)
#pragma unroll
        for (int j = 0; j < 8; j++)
#pragma unroll
            for (int k = 0; k < 4; k++) acc[i][j][k] = 0.0f;

    int aM[2], aK[2], bK[2], bX[2], bXs[2];
#pragma unroll
    for (int t = 0; t < 2; t++) {
        int id = tid + t * 256;
        aM[t] = id >> 2; aK[t] = id & 3;
        bK[t] = id >> 4; bX[t] = id & 15;
        bXs[t] = bX[t] ^ (bK[t] & 7);
    }
    const uint32_t sA[2] = {smem_u32(As[0]), smem_u32(As[1])};
    const uint32_t sB[2] = {smem_u32(Bs[0]), smem_u32(Bs[1])};

#define LOADG(kk, p)                                                                   \
    {                                                                                  \
        int split = ((kk) * 32) >> 9;                                                  \
        int c0 = ((kk) * 32) & 511;                                                    \
        const bf16* Ab = A + (size_t)split * (Cc * Cc);                                \
        _Pragma("unroll") for (int t = 0; t < 2; t++)                                  \
            cpasync16(sA[p] + aM[t] * 80 + aK[t] * 16,                                 \
                      Ab + (size_t)(o0 + aM[t]) * Cc + c0 + aK[t] * 8);                \
        _Pragma("unroll") for (int t = 0; t < 2; t++)                                  \
            cpasync16(sB[p] + bK[t] * 256 + bXs[t] * 16,                               \
                      B + (size_t)(c0 + bK[t]) * LL + l0 + bX[t] * 8);                 \
        CP_COMMIT();                                                                   \
    }

    LOADG(0, 0);

    for (int kk = 0; kk < 32; kk++) {
        int p = kk & 1;
        CP_WAIT0();
        __syncthreads();
        if (kk < 31) LOADG(kk + 1, p ^ 1);

#pragma unroll
        for (int ks = 0; ks < 2; ks++) {
            uint32_t a[2][4];
#pragma unroll
            for (int mi = 0; mi < 2; mi++) {
                int row = wm * 32 + mi * 16 + (lane & 15);
                ldsm4(a[mi], sA[p] + row * 80 + (ks * 16 + (lane >> 4) * 8) * 2);
            }
            uint32_t bfr[4][4];
#pragma unroll
            for (int nb = 0; nb < 4; nb++) {
                int krow = ks * 16 + (lane & 7) + ((lane >> 3) & 1) * 8;
                int x = (wn * 8 + nb * 2 + (lane >> 4)) ^ (krow & 7);
                ldsm4t(bfr[nb], sB[p] + krow * 256 + x * 16);
            }
#pragma unroll
            for (int mi = 0; mi < 2; mi++)
#pragma unroll
                for (int nj = 0; nj < 8; nj++)
                    mma16816(acc[mi][nj], a[mi], bfr[nj >> 1][(nj & 1) * 2],
                             bfr[nj >> 1][(nj & 1) * 2 + 1]);
        }
    }
#undef LOADG

#pragma unroll
    for (int mi = 0; mi < 2; mi++) {
        int r0 = o0 + wm * 32 + mi * 16 + (lane >> 2);
        float bi0 = bias ? bias[r0] : 0.0f;
        float bi1 = bias ? bias[r0 + 8] : 0.0f;
#pragma unroll
        for (int nj = 0; nj < 8; nj++) {
            int cb = l0 + wn * 64 + nj * 8 + (lane & 3) * 2;
            float2 v0 = make_float2(acc[mi][nj][0] + bi0, acc[mi][nj][1] + bi0);
            float2 v1 = make_float2(acc[mi][nj][2] + bi1, acc[mi][nj][3] + bi1);
            *(float2*)&C[(size_t)r0 * LL + cb] = v0;
            *(float2*)&C[(size_t)(r0 + 8) * LL + cb] = v1;
        }
    }
}

// grid = (LL/128, Cc/128, 3*Bb)
__global__ __launch_bounds__(256, 2) void k_gemm_qkv_mma() {
    int z = blockIdx.z;
    int w = z >> 3, b = z & 7;
    gemm_core(g_wsp + (size_t)w * 2 * Cc * Cc,
              g_s0b + (size_t)b * Cc * LL,
              g_y + (size_t)z * Cc * LL, nullptr);
}

// grid = (LL/128, Cc/128, Bb)
__global__ __launch_bounds__(256, 2) void k_gemm_out_mma(const float* __restrict__ bp,
                                                         float* __restrict__ out) {
    gemm_core(g_wsp + (size_t)3 * 2 * Cc * Cc,
              g_sattnb + (size_t)blockIdx.z * Cc * LL,
              out + (size_t)blockIdx.z * Cc * LL, bp);
}

// ---------------------------------------------------------------------------
// Kernel 3: per-branch BN + LIF with certified-margin flagging.
// ALL 32 y loads hoisted before compute (MLP 4 -> 32).
// ---------------------------------------------------------------------------
__global__ __launch_bounds__(256) void k_bn_lif_qkv(
        const float* __restrict__ gq, const float* __restrict__ bq,
        const float* __restrict__ mq, const float* __restrict__ vq,
        const float* __restrict__ gk, const float* __restrict__ bk,
        const float* __restrict__ mk, const float* __restrict__ vk,
        const float* __restrict__ gv, const float* __restrict__ bv,
        const float* __restrict__ mv, const float* __restrict__ vv) {
    int z = blockIdx.z;
    int w = z / Bb, b = z % Bb;
    int h = blockIdx.y;
    int n0 = blockIdx.x * 32;
    int tid = threadIdx.x, lane = tid & 31, wrp = tid >> 5;

    const float *gg, *bb, *mm, *vvv;
    if (w == 0) { gg = gq; bb = bq; mm = mq; vvv = vq; }
    else if (w == 1) { gg = gk; bb = bk; mm = mk; vvv = vk; }
    else { gg = gv; bb = bv; mm = mv; vvv = vv; }

    const bool isK = (w == 1);
    __shared__ bf16 sm[Tt][32][66];

    // hoisted load pass: 32 independent LDGs in flight
    float yv[8][4];
#pragma unroll
    for (int i = 0; i < 8; i++) {
        int o = h * 64 + wrp * 8 + i;
        const float* yp = g_y + (size_t)((w * Bb + b) * Cc + o) * LL + n0 + lane;
#pragma unroll
        for (int t = 0; t < Tt; t++) yv[i][t] = yp[(size_t)t * NN];
    }

#pragma unroll
    for (int i = 0; i < 8; i++) {
        int od = wrp * 8 + i;
        int o = h * 64 + od;
        float sc = gg[o] / sqrtf(vvv[o] + 1e-5f);
        float sh = bb[o] - mm[o] * sc;

        float de = (2.0f / 3.0f) * fabsf(sc) * EPSY;
        float e = 0.0f;
        bool flagged = false;

        float v = 0.0f;
#pragma unroll
        for (int t = 0; t < Tt; t++) {
            float yb = yv[i][t] * sc + sh;
            v = v + (yb - v) / 1.5f;
            e = e * (1.0f / 3.0f) + de;
            if (fabsf(v - 1.0f) < e) flagged = true;
            float s = (v >= 1.0f) ? 1.0f : 0.0f;
            if (isK)
                g_kb[(size_t)(b * Cc + o) * LL + t * NN + n0 + lane] = __float2bfloat16(s);
            else
                sm[t][lane][od] = __float2bfloat16(s);
            if (s != 0.0f) { v = 0.0f; e = 0.0f; }
        }
        if (flagged) {
            unsigned int pos = atomicAdd(&g_nflag, 1u);
            if (pos < FLAG_CAP)
                g_flag[pos] = ((unsigned)w << 20) | ((unsigned)b << 17) |
                              ((unsigned)o << 8) | (unsigned)(n0 + lane);
        }
    }

    if (!isK) {
        __syncthreads();
        bf16* dst = ((w == 0) ? g_qb : g_vb) + (size_t)(b * HH + h) * LL * DD;
#pragma unroll
        for (int j = 0; j < 16; j++) {
            int flat = tid + 256 * j;
            int row = flat >> 5, col = flat & 31;
            int t = row >> 5, n = row & 31;
            uint32_t val;
            memcpy(&val, &sm[t][n][col * 2], 4);
            *(uint32_t*)(dst + ((size_t)(t * NN + n0 + n)) * DD + col * 2) = val;
        }
    }
}

// ---------------------------------------------------------------------------
// Kernel 3f: bitmask warp fallback (coalesced, zero-skip, bit-identical).
// ---------------------------------------------------------------------------
__global__ __launch_bounds__(256) void k_fallback(
        const float* __restrict__ wq, const float* __restrict__ wk,
        const float* __restrict__ wv,
        const float* __restrict__ gq, const float* __restrict__ bq,
        const float* __restrict__ mq, const float* __restrict__ vq,
        const float* __restrict__ gk, const float* __restrict__ bk,
        const float* __restrict__ mk, const float* __restrict__ vk,
        const float* __restrict__ gv, const float* __restrict__ bv,
        const float* __restrict__ mv, const float* __restrict__ vv) {
    __shared__ float Wsm[8][Cc];
    __shared__ uint32_t msm[8][Tt][16];

    int lane = threadIdx.x & 31, wrp = threadIdx.x >> 5;
    unsigned int total = g_nflag;
    if (total > FLAG_CAP) total = FLAG_CAP;
    unsigned int gw = blockIdx.x * 8 + wrp;
    unsigned int nw = gridDim.x * 8;

    for (unsigned int i = gw; i < total; i += nw) {
        unsigned int enc = g_flag[i];
        int n = enc & 255;
        int o = (enc >> 8) & 511;
        int b = (enc >> 17) & 7;
        int w = enc >> 20;

        const float* W = (w == 0) ? wq : (w == 1) ? wk : wv;
        const float* Wrow = W + (size_t)o * Cc;

#pragma unroll
        for (int j = 0; j < 16; j++) {
            int c = lane + 32 * j;
            Wsm[wrp][c] = Wrow[c];
#pragma unroll
            for (int t = 0; t < Tt; t++) {
                bf16 s = g_s0T[((size_t)b * LL + t * NN + n) * Cc + c];
                unsigned m = __ballot_sync(0xffffffffu,
                                           __bfloat16_as_ushort(s) != 0);
                if (lane == 0) msm[wrp][t][j] = m;
            }
        }
        __syncwarp();

        float yt = 0.0f;
        if (lane < Tt) {
#pragma unroll
            for (int j = 0; j < 16; j++) {
                unsigned m = msm[wrp][lane][j];
                while (m) {
                    int cb = __ffs(m) - 1;
                    m &= m - 1;
                    yt += Wsm[wrp][32 * j + cb];
                }
            }
        }
        float y0 = __shfl_sync(0xffffffffu, yt, 0);
        float y1 = __shfl_sync(0xffffffffu, yt, 1);
        float y2 = __shfl_sync(0xffffffffu, yt, 2);
        float y3 = __shfl_sync(0xffffffffu, yt, 3);

        if (lane == 0) {
            float y[4] = {y0, y1, y2, y3};
            const float *gg, *bb, *mm, *vvv;
            if (w == 0) { gg = gq; bb = bq; mm = mq; vvv = vq; }
            else if (w == 1) { gg = gk; bb = bk; mm = mk; vvv = vk; }
            else { gg = gv; bb = bv; mm = mv; vvv = vv; }

            float sc = gg[o] / sqrtf(vvv[o] + 1e-5f);
            float sh = bb[o] - mm[o] * sc;
            int h = o >> 6, dd = o & 63;

            float v = 0.0f;
#pragma unroll
            for (int t = 0; t < Tt; t++) {
                float yb = y[t] * sc + sh;
                v = v + (yb - v) / 1.5f;
                float s = (v >= 1.0f) ? 1.0f : 0.0f;
                if (w == 1)
                    g_kb[(size_t)(b * Cc + o) * LL + t * NN + n] = __float2bfloat16(s);
                else {
                    bf16* base = (w == 0) ? g_qb : g_vb;
                    base[((size_t)(b * HH + h) * LL + t * NN + n) * DD + dd] =
                        __float2bfloat16(s);
                }
                if (s != 0.0f) v = 0.0f;
            }
        }
        __syncwarp();
    }
}

// ---------------------------------------------------------------------------
// Kernel 4: attention on tensor cores (exact), K/V double-buffered.
// ---------------------------------------------------------------------------
__global__ __launch_bounds__(256) void k_attn_mma() {
    int l0 = blockIdx.x * 128;
    int bh = blockIdx.y;
    int b = bh >> 3, h = bh & 7;

    const bf16* Q = g_qb + (size_t)bh * LL * DD;
    const bf16* K = g_kb + (size_t)(b * Cc + h * 64) * LL;
    const bf16* V = g_vb + (size_t)bh * LL * DD;

    __shared__ bf16 Qs[128 * 72];
    __shared__ bf16 Ks[2][64 * 64];
    __shared__ bf16 Vs[2][64 * 64];

    int tid = threadIdx.x, lane = tid & 31, warp = tid >> 5;
    const uint32_t sQ = smem_u32(Qs);
    const uint32_t sK[2] = {smem_u32(Ks[0]), smem_u32(Ks[1])};
    const uint32_t sV[2] = {smem_u32(Vs[0]), smem_u32(Vs[1])};

    int rr[2], cc[2], xx[2];
#pragma unroll
    for (int t = 0; t < 2; t++) {
        int id = tid + t * 256;
        rr[t] = id >> 3; cc[t] = id & 7;
        xx[t] = cc[t] ^ (rr[t] & 7);
    }
    uint4 pk[2], pv[2];

#define LDKV(k0)                                                                   \
    {                                                                              \
        _Pragma("unroll") for (int t = 0; t < 2; t++) {                            \
            pk[t] = *(const uint4*)(K + (size_t)rr[t] * LL + (k0) + cc[t] * 8);    \
            pv[t] = *(const uint4*)(V + (size_t)((k0) + rr[t]) * DD + cc[t] * 8);  \
        }                                                                          \
    }
#define STKV(p)                                                                    \
    {                                                                              \
        _Pragma("unroll") for (int t = 0; t < 2; t++) {                            \
            *(uint4*)((char*)Ks[p] + rr[t] * 128 + xx[t] * 16) = pk[t];            \
            *(uint4*)((char*)Vs[p] + rr[t] * 128 + xx[t] * 16) = pv[t];            \
        }                                                                          \
    }

#pragma unroll
    for (int t = 0; t < 4; t++) {
        int id = tid + t * 256;
        int r = id >> 3, c = id & 7;
        uint4 qv = *(const uint4*)(Q + (size_t)(l0 + r) * DD + c * 8);
        *(uint4*)((char*)Qs + r * 144 + c * 16) = qv;
    }
    LDKV(0);
    STKV(0);
    __syncthreads();

    uint32_t aq[4][4];
    {
        int row = warp * 16 + (lane & 15);
#pragma unroll
        for (int kc = 0; kc < 4; kc++)
            ldsm4(aq[kc], sQ + row * 144 + kc * 32 + (lane >> 4) * 16);
    }

    float oacc[8][4];
#pragma unroll
    for (int i = 0; i < 8; i++)
#pragma unroll
        for (int j = 0; j < 4; j++) oacc[i][j] = 0.0f;

    for (int it = 0; it < 16; it++) {
        int p = it & 1;
        if (it < 15) LDKV((it + 1) * 64);

        float sacc[8][4];
#pragma unroll
        for (int i = 0; i < 8; i++)
#pragma unroll
            for (int j = 0; j < 4; j++) sacc[i][j] = 0.0f;
#pragma unroll
        for (int nb = 0; nb < 4; nb++) {
#pragma unroll
            for (int ks = 0; ks < 4; ks++) {
                uint32_t bf[4];
                int krow = ks * 16 + (lane & 7) + ((lane >> 3) & 1) * 8;
                int ch = nb * 2 + (lane >> 4);
                int x = ch ^ (krow & 7);
                ldsm4t(bf, sK[p] + krow * 128 + x * 16);
                mma16816(sacc[nb * 2],     aq[ks], bf[0], bf[1]);
                mma16816(sacc[nb * 2 + 1], aq[ks], bf[2], bf[3]);
            }
        }
        uint32_t sa[4][4];
#pragma unroll
        for (int kb = 0; kb < 4; kb++) {
            sa[kb][0] = packbf(sacc[2 * kb][0],     sacc[2 * kb][1]);
            sa[kb][1] = packbf(sacc[2 * kb][2],     sacc[2 * kb][3]);
            sa[kb][2] = packbf(sacc[2 * kb + 1][0], sacc[2 * kb + 1][1]);
            sa[kb][3] = packbf(sacc[2 * kb + 1][2], sacc[2 * kb + 1][3]);
        }
#pragma unroll
        for (int nb = 0; nb < 4; nb++) {
#pragma unroll
            for (int kb = 0; kb < 4; kb++) {
                uint32_t bf[4];
                int krow = kb * 16 + (lane & 7) + ((lane >> 3) & 1) * 8;
                int ch = nb * 2 + (lane >> 4);
                int x = ch ^ (krow & 7);
                ldsm4t(bf, sV[p] + krow * 128 + x * 16);
                mma16816(oacc[nb * 2],     sa[kb], bf[0], bf[1]);
                mma16816(oacc[nb * 2 + 1], sa[kb], bf[2], bf[3]);
            }
        }

        if (it < 15) STKV(p ^ 1);
        __syncthreads();
    }
#undef LDKV
#undef STKV

    int row = warp * 16 + (lane >> 2);
#pragma unroll
    for (int nj = 0; nj < 8; nj++) {
        int col = nj * 8 + (lane & 3) * 2;
#pragma unroll
        for (int e = 0; e < 4; e++) {
            int r = row + (e >> 1) * 8;
            int c = col + (e & 1);
            float o = oacc[nj][e] * 0.125f;
            float s = ((o / 1.5f - 1.0f) >= 0.0f) ? 1.0f : 0.0f;
            g_sattnb[((size_t)b * Cc + h * 64 + c) * LL + (l0 + r)] = __float2bfloat16(s);
        }
    }
}

// ---------------------------------------------------------------------------
extern "C" void kernel_launch(void* const* d_in, const int* in_sizes, int n_in,
                              void* d_out, int out_size) {
    const float* x   = (const float*)d_in[0];
    const float* wq  = (const float*)d_in[1];
    const float* wk  = (const float*)d_in[2];
    const float* wv  = (const float*)d_in[3];
    const float* wp  = (const float*)d_in[4];
    const float* bp  = (const float*)d_in[5];
    const float* gq  = (const float*)d_in[6];
    const float* bq  = (const float*)d_in[7];
    const float* mq  = (const float*)d_in[8];
    const float* vq  = (const float*)d_in[9];
    const float* gk  = (const float*)d_in[10];
    const float* bk  = (const float*)d_in[11];
    const float* mk  = (const float*)d_in[12];
    const float* vk  = (const float*)d_in[13];
    const float* gv  = (const float*)d_in[14];
    const float* bv  = (const float*)d_in[15];
    const float* mv  = (const float*)d_in[16];
    const float* vv  = (const float*)d_in[17];
    const float* gp  = (const float*)d_in[18];
    const float* bpn = (const float*)d_in[19];
    const float* mp  = (const float*)d_in[20];
    const float* vp  = (const float*)d_in[21];
    float* out = (float*)d_out;

    k_prep<<<8192, 256>>>(wq, wk, wv, wp, x, gp, bpn, mp, vp);
    k_s0T<<<dim3(LL / 32, Cc / 64, Bb), 256>>>();
    k_gemm_qkv_mma<<<dim3(LL / 128, Cc / 128, 3 * Bb), 256>>>();
    k_bn_lif_qkv<<<dim3(NN / 32, HH, 3 * Bb), 256>>>(gq, bq, mq, vq,
                                                     gk, bk, mk, vk,
                                                     gv, bv, mv, vv);
    k_fallback<<<2048, 256>>>(wq, wk, wv, gq, bq, mq, vq,
                              gk, bk, mk, vk, gv, bv, mv, vv);
    k_attn_mma<<<dim3(LL / 128, Bb * HH), 256>>>();
    k_gemm_out_mma<<<dim3(LL / 128, Cc / 128, Bb), 256>>>(bp, out);
}

// round 16
// speedup vs baseline: 1.9790x; 1.0107x over previous
#include <cuda_runtime.h>
#include <cuda_bf16.h>
#include <cstdint>

#define Bb 8
#define Cc 512
#define Tt 4
#define NN 256
#define LL 1024
#define HH 8
#define DD 64

#define EPSY 3e-4f
#define FLAG_CAP (1 << 20)

typedef __nv_bfloat16 bf16;

// Scratch
__device__ bf16  g_wsp[4 * 2 * Cc * Cc];   // [mat(q,k,v,p)][split(hi,mid)][o][c]
__device__ bf16  g_s0b[Bb * Cc * LL];      // proj spikes bf16 [b][c][l]
__device__ bf16  g_s0T[Bb * LL * Cc];      // proj spikes bf16 [b][l][c]
__device__ float g_y[3 * Bb * Cc * LL];    // qkv pre-activation fp32
__device__ bf16  g_qb[Bb * HH * LL * DD];  // q spikes [b][h][l][d]
__device__ bf16  g_kb[Bb * Cc * LL];       // k spikes [b][c][l]
__device__ bf16  g_vb[Bb * HH * LL * DD];  // v spikes [b][h][l][d]
__device__ bf16  g_sattnb[Bb * Cc * LL];   // attn spikes [b][c][l]
__device__ unsigned int g_nflag;
__device__ unsigned int g_flag[FLAG_CAP];  // (w<<20)|(b<<17)|(o<<8)|n

// ---------------------------------------------------------------------------
__device__ __forceinline__ uint32_t smem_u32(const void* p) {
    return (uint32_t)__cvta_generic_to_shared(p);
}
__device__ __forceinline__ void ldsm4(uint32_t* r, uint32_t a) {
    asm volatile("ldmatrix.sync.aligned.m8n8.x4.shared.b16 {%0,%1,%2,%3}, [%4];"
                 : "=r"(r[0]), "=r"(r[1]), "=r"(r[2]), "=r"(r[3]) : "r"(a));
}
__device__ __forceinline__ void ldsm4t(uint32_t* r, uint32_t a) {
    asm volatile("ldmatrix.sync.aligned.m8n8.x4.trans.shared.b16 {%0,%1,%2,%3}, [%4];"
                 : "=r"(r[0]), "=r"(r[1]), "=r"(r[2]), "=r"(r[3]) : "r"(a));
}
__device__ __forceinline__ void mma16816(float* c, const uint32_t* a, uint32_t b0, uint32_t b1) {
    asm volatile(
        "mma.sync.aligned.m16n8k16.row.col.f32.bf16.bf16.f32 "
        "{%0,%1,%2,%3}, {%4,%5,%6,%7}, {%8,%9}, {%0,%1,%2,%3};"
        : "+f"(c[0]), "+f"(c[1]), "+f"(c[2]), "+f"(c[3])
        : "r"(a[0]), "r"(a[1]), "r"(a[2]), "r"(a[3]), "r"(b0), "r"(b1));
}
__device__ __forceinline__ uint32_t packbf(float lo, float hi) {
    uint32_t l = (uint32_t)__bfloat16_as_ushort(__float2bfloat16(lo));
    uint32_t h = (uint32_t)__bfloat16_as_ushort(__float2bfloat16(hi));
    return l | (h << 16);
}
__device__ __forceinline__ void cpasync16(uint32_t s, const void* g) {
    asm volatile("cp.async.cg.shared.global [%0], [%1], 16;" :: "r"(s), "l"(g));
}
#define CP_COMMIT() asm volatile("cp.async.commit_group;" ::: "memory")
#define CP_WAIT0()  asm volatile("cp.async.wait_group 0;" ::: "memory")
#define CP_WAIT1()  asm volatile("cp.async.wait_group 1;" ::: "memory")

// ---------------------------------------------------------------------------
// Kernel 1 (fused prep)
// ---------------------------------------------------------------------------
__global__ void k_prep(const float* __restrict__ wq, const float* __restrict__ wk,
                       const float* __restrict__ wv, const float* __restrict__ wp,
                       const float* __restrict__ x,
                       const float* __restrict__ gp, const float* __restrict__ bpn,
                       const float* __restrict__ mp, const float* __restrict__ vp) {
    if (blockIdx.x == 0 && threadIdx.x == 0) g_nflag = 0;
    if (blockIdx.x < 4096) {
        int idx = blockIdx.x * 256 + threadIdx.x;
        int m = idx / (Cc * Cc);
        int rc = idx % (Cc * Cc);
        const float* W = (m == 0) ? wq : (m == 1) ? wk : (m == 2) ? wv : wp;
        float w = W[rc];
        bf16 hi = __float2bfloat16(w);
        float r1 = w - __bfloat162float(hi);
        g_wsp[(size_t)(m * 2 + 0) * Cc * Cc + rc] = hi;
        g_wsp[(size_t)(m * 2 + 1) * Cc * Cc + rc] = __float2bfloat16(r1);
    } else {
        int idx = (blockIdx.x - 4096) * 256 + threadIdx.x;
        int n = idx % NN;
        int c = (idx / NN) % Cc;
        int b = idx / (NN * Cc);

        float sc = gp[c] / sqrtf(vp[c] + 1e-5f);
        float sh = bpn[c] - mp[c] * sc;

        const float* xp = x + ((size_t)(b * Cc + c) * Tt) * NN + n;
        bf16* sp = g_s0b + (size_t)(b * Cc + c) * LL + n;

        float xv[4];
#pragma unroll
        for (int t = 0; t < Tt; t++) xv[t] = xp[(size_t)t * NN];

        float v = 0.0f;
#pragma unroll
        for (int t = 0; t < Tt; t++) {
            float xb = xv[t] * sc + sh;
            v = v + (xb - v) / 1.5f;
            float s = (v >= 1.0f) ? 1.0f : 0.0f;
            sp[(size_t)t * NN] = __float2bfloat16(s);
            if (s != 0.0f) v = 0.0f;
        }
    }
}

// ---------------------------------------------------------------------------
// Kernel 1b: transpose g_s0b -> g_s0T
// ---------------------------------------------------------------------------
__global__ __launch_bounds__(256) void k_s0T() {
    int b = blockIdx.z;
    int c0 = blockIdx.y * 64;
    int l0 = blockIdx.x * 32;
    int tid = threadIdx.x, lane = tid & 31, wrp = tid >> 5;

    __shared__ bf16 sm[32][72];

#pragma unroll
    for (int i = 0; i < 8; i++) {
        int cl = wrp * 8 + i;
        sm[lane][cl] = g_s0b[((size_t)(b * Cc + c0 + cl)) * LL + l0 + lane];
    }
    __syncthreads();

    int l = tid >> 3, c8 = (tid & 7) * 8;
    uint4 v;
    memcpy(&v, &sm[l][c8], 16);
    *(uint4*)&g_s0T[((size_t)b * LL + l0 + l) * Cc + c0 + c8] = v;
}

// ---------------------------------------------------------------------------
// Tensor-core GEMM core: 3-stage cp.async pipeline (2 loads in flight).
// MMA issue order unchanged -> outputs bit-identical.
// ---------------------------------------------------------------------------
__device__ __forceinline__ void gemm_core(const bf16* __restrict__ A,
                                          const bf16* __restrict__ B,
                                          float* __restrict__ C,
                                          const float* __restrict__ bias) {
    __shared__ bf16 As[3][128 * 40];
    __shared__ bf16 Bs[3][32 * 128];

    const int tid = threadIdx.x;
    const int lane = tid & 31, warp = tid >> 5;
    const int wm = warp >> 1, wn = warp & 1;
    const int o0 = blockIdx.y * 128, l0 = blockIdx.x * 128;

    float acc[2][8][4];
#pragma unroll
    for (int i = 0; i < 2; i++)
#pragma unroll
        for (int j = 0; j < 8; j++)
#pragma unroll
            for (int k = 0; k < 4; k++) acc[i][j][k] = 0.0f;

    int aM[2], aK[2], bK[2], bX[2], bXs[2];
#pragma unroll
    for (int t = 0; t < 2; t++) {
        int id = tid + t * 256;
        aM[t] = id >> 2; aK[t] = id & 3;
        bK[t] = id >> 4; bX[t] = id & 15;
        bXs[t] = bX[t] ^ (bK[t] & 7);
    }
    const uint32_t sA[3] = {smem_u32(As[0]), smem_u32(As[1]), smem_u32(As[2])};
    const uint32_t sB[3] = {smem_u32(Bs[0]), smem_u32(Bs[1]), smem_u32(Bs[2])};

#define LOADG(kk, p)                                                                   \
    {                                                                                  \
        int split = ((kk) * 32) >> 9;                                                  \
        int c0 = ((kk) * 32) & 511;                                                    \
        const bf16* Ab = A + (size_t)split * (Cc * Cc);                                \
        _Pragma("unroll") for (int t = 0; t < 2; t++)                                  \
            cpasync16(sA[p] + aM[t] * 80 + aK[t] * 16,                                 \
                      Ab + (size_t)(o0 + aM[t]) * Cc + c0 + aK[t] * 8);                \
        _Pragma("unroll") for (int t = 0; t < 2; t++)                                  \
            cpasync16(sB[p] + bK[t] * 256 + bXs[t] * 16,                               \
                      B + (size_t)(c0 + bK[t]) * LL + l0 + bX[t] * 8);                 \
        CP_COMMIT();                                                                   \
    }

    LOADG(0, 0);
    LOADG(1, 1);

    for (int kk = 0; kk < 32; kk++) {
        int p = kk % 3;
        if (kk < 31) CP_WAIT1(); else CP_WAIT0();
        __syncthreads();
        if (kk < 30) LOADG(kk + 2, (kk + 2) % 3);

#pragma unroll
        for (int ks = 0; ks < 2; ks++) {
            uint32_t a[2][4];
#pragma unroll
            for (int mi = 0; mi < 2; mi++) {
                int row = wm * 32 + mi * 16 + (lane & 15);
                ldsm4(a[mi], sA[p] + row * 80 + (ks * 16 + (lane >> 4) * 8) * 2);
            }
            uint32_t bfr[4][4];
#pragma unroll
            for (int nb = 0; nb < 4; nb++) {
                int krow = ks * 16 + (lane & 7) + ((lane >> 3) & 1) * 8;
                int x = (wn * 8 + nb * 2 + (lane >> 4)) ^ (krow & 7);
                ldsm4t(bfr[nb], sB[p] + krow * 256 + x * 16);
            }
#pragma unroll
            for (int mi = 0; mi < 2; mi++)
#pragma unroll
                for (int nj = 0; nj < 8; nj++)
                    mma16816(acc[mi][nj], a[mi], bfr[nj >> 1][(nj & 1) * 2],
                             bfr[nj >> 1][(nj & 1) * 2 + 1]);
        }
    }
#undef LOADG

#pragma unroll
    for (int mi = 0; mi < 2; mi++) {
        int r0 = o0 + wm * 32 + mi * 16 + (lane >> 2);
        float bi0 = bias ? bias[r0] : 0.0f;
        float bi1 = bias ? bias[r0 + 8] : 0.0f;
#pragma unroll
        for (int nj = 0; nj < 8; nj++) {
            int cb = l0 + wn * 64 + nj * 8 + (lane & 3) * 2;
            float2 v0 = make_float2(acc[mi][nj][0] + bi0, acc[mi][nj][1] + bi0);
            float2 v1 = make_float2(acc[mi][nj][2] + bi1, acc[mi][nj][3] + bi1);
            *(float2*)&C[(size_t)r0 * LL + cb] = v0;
            *(float2*)&C[(size_t)(r0 + 8) * LL + cb] = v1;
        }
    }
}

// grid = (LL/128, Cc/128, 3*Bb)
__global__ __launch_bounds__(256, 2) void k_gemm_qkv_mma() {
    int z = blockIdx.z;
    int w = z >> 3, b = z & 7;
    gemm_core(g_wsp + (size_t)w * 2 * Cc * Cc,
              g_s0b + (size_t)b * Cc * LL,
              g_y + (size_t)z * Cc * LL, nullptr);
}

// grid = (LL/128, Cc/128, Bb)
__global__ __launch_bounds__(256, 2) void k_gemm_out_mma(const float* __restrict__ bp,
                                                         float* __restrict__ out) {
    gemm_core(g_wsp + (size_t)3 * 2 * Cc * Cc,
              g_sattnb + (size_t)blockIdx.z * Cc * LL,
              out + (size_t)blockIdx.z * Cc * LL, bp);
}

// ---------------------------------------------------------------------------
// Kernel 3: per-branch BN + LIF with certified-margin flagging (hoisted loads)
// ---------------------------------------------------------------------------
__global__ __launch_bounds__(256) void k_bn_lif_qkv(
        const float* __restrict__ gq, const float* __restrict__ bq,
        const float* __restrict__ mq, const float* __restrict__ vq,
        const float* __restrict__ gk, const float* __restrict__ bk,
        const float* __restrict__ mk, const float* __restrict__ vk,
        const float* __restrict__ gv, const float* __restrict__ bv,
        const float* __restrict__ mv, const float* __restrict__ vv) {
    int z = blockIdx.z;
    int w = z / Bb, b = z % Bb;
    int h = blockIdx.y;
    int n0 = blockIdx.x * 32;
    int tid = threadIdx.x, lane = tid & 31, wrp = tid >> 5;

    const float *gg, *bb, *mm, *vvv;
    if (w == 0) { gg = gq; bb = bq; mm = mq; vvv = vq; }
    else if (w == 1) { gg = gk; bb = bk; mm = mk; vvv = vk; }
    else { gg = gv; bb = bv; mm = mv; vvv = vv; }

    const bool isK = (w == 1);
    __shared__ bf16 sm[Tt][32][66];

    float yv[8][4];
#pragma unroll
    for (int i = 0; i < 8; i++) {
        int o = h * 64 + wrp * 8 + i;
        const float* yp = g_y + (size_t)((w * Bb + b) * Cc + o) * LL + n0 + lane;
#pragma unroll
        for (int t = 0; t < Tt; t++) yv[i][t] = yp[(size_t)t * NN];
    }

#pragma unroll
    for (int i = 0; i < 8; i++) {
        int od = wrp * 8 + i;
        int o = h * 64 + od;
        float sc = gg[o] / sqrtf(vvv[o] + 1e-5f);
        float sh = bb[o] - mm[o] * sc;

        float de = (2.0f / 3.0f) * fabsf(sc) * EPSY;
        float e = 0.0f;
        bool flagged = false;

        float v = 0.0f;
#pragma unroll
        for (int t = 0; t < Tt; t++) {
            float yb = yv[i][t] * sc + sh;
            v = v + (yb - v) / 1.5f;
            e = e * (1.0f / 3.0f) + de;
            if (fabsf(v - 1.0f) < e) flagged = true;
            float s = (v >= 1.0f) ? 1.0f : 0.0f;
            if (isK)
                g_kb[(size_t)(b * Cc + o) * LL + t * NN + n0 + lane] = __float2bfloat16(s);
            else
                sm[t][lane][od] = __float2bfloat16(s);
            if (s != 0.0f) { v = 0.0f; e = 0.0f; }
        }
        if (flagged) {
            unsigned int pos = atomicAdd(&g_nflag, 1u);
            if (pos < FLAG_CAP)
                g_flag[pos] = ((unsigned)w << 20) | ((unsigned)b << 17) |
                              ((unsigned)o << 8) | (unsigned)(n0 + lane);
        }
    }

    if (!isK) {
        __syncthreads();
        bf16* dst = ((w == 0) ? g_qb : g_vb) + (size_t)(b * HH + h) * LL * DD;
#pragma unroll
        for (int j = 0; j < 16; j++) {
            int flat = tid + 256 * j;
            int row = flat >> 5, col = flat & 31;
            int t = row >> 5, n = row & 31;
            uint32_t val;
            memcpy(&val, &sm[t][n][col * 2], 4);
            *(uint32_t*)(dst + ((size_t)(t * NN + n0 + n)) * DD + col * 2) = val;
        }
    }
}

// ---------------------------------------------------------------------------
// Kernel 3f: bitmask warp fallback (coalesced, zero-skip, bit-identical).
// ---------------------------------------------------------------------------
__global__ __launch_bounds__(256) void k_fallback(
        const float* __restrict__ wq, const float* __restrict__ wk,
        const float* __restrict__ wv,
        const float* __restrict__ gq, const float* __restrict__ bq,
        const float* __restrict__ mq, const float* __restrict__ vq,
        const float* __restrict__ gk, const float* __restrict__ bk,
        const float* __restrict__ mk, const float* __restrict__ vk,
        const float* __restrict__ gv, const float* __restrict__ bv,
        const float* __restrict__ mv, const float* __restrict__ vv) {
    __shared__ float Wsm[8][Cc];
    __shared__ uint32_t msm[8][Tt][16];

    int lane = threadIdx.x & 31, wrp = threadIdx.x >> 5;
    unsigned int total = g_nflag;
    if (total > FLAG_CAP) total = FLAG_CAP;
    unsigned int gw = blockIdx.x * 8 + wrp;
    unsigned int nw = gridDim.x * 8;

    for (unsigned int i = gw; i < total; i += nw) {
        unsigned int enc = g_flag[i];
        int n = enc & 255;
        int o = (enc >> 8) & 511;
        int b = (enc >> 17) & 7;
        int w = enc >> 20;

        const float* W = (w == 0) ? wq : (w == 1) ? wk : wv;
        const float* Wrow = W + (size_t)o * Cc;

#pragma unroll
        for (int j = 0; j < 16; j++) {
            int c = lane + 32 * j;
            Wsm[wrp][c] = Wrow[c];
#pragma unroll
            for (int t = 0; t < Tt; t++) {
                bf16 s = g_s0T[((size_t)b * LL + t * NN + n) * Cc + c];
                unsigned m = __ballot_sync(0xffffffffu,
                                           __bfloat16_as_ushort(s) != 0);
                if (lane == 0) msm[wrp][t][j] = m;
            }
        }
        __syncwarp();

        float yt = 0.0f;
        if (lane < Tt) {
#pragma unroll
            for (int j = 0; j < 16; j++) {
                unsigned m = msm[wrp][lane][j];
                while (m) {
                    int cb = __ffs(m) - 1;
                    m &= m - 1;
                    yt += Wsm[wrp][32 * j + cb];
                }
            }
        }
        float y0 = __shfl_sync(0xffffffffu, yt, 0);
        float y1 = __shfl_sync(0xffffffffu, yt, 1);
        float y2 = __shfl_sync(0xffffffffu, yt, 2);
        float y3 = __shfl_sync(0xffffffffu, yt, 3);

        if (lane == 0) {
            float y[4] = {y0, y1, y2, y3};
            const float *gg, *bb, *mm, *vvv;
            if (w == 0) { gg = gq; bb = bq; mm = mq; vvv = vq; }
            else if (w == 1) { gg = gk; bb = bk; mm = mk; vvv = vk; }
            else { gg = gv; bb = bv; mm = mv; vvv = vv; }

            float sc = gg[o] / sqrtf(vvv[o] + 1e-5f);
            float sh = bb[o] - mm[o] * sc;
            int h = o >> 6, dd = o & 63;

            float v = 0.0f;
#pragma unroll
            for (int t = 0; t < Tt; t++) {
                float yb = y[t] * sc + sh;
                v = v + (yb - v) / 1.5f;
                float s = (v >= 1.0f) ? 1.0f : 0.0f;
                if (w == 1)
                    g_kb[(size_t)(b * Cc + o) * LL + t * NN + n] = __float2bfloat16(s);
                else {
                    bf16* base = (w == 0) ? g_qb : g_vb;
                    base[((size_t)(b * HH + h) * LL + t * NN + n) * DD + dd] =
                        __float2bfloat16(s);
                }
                if (s != 0.0f) v = 0.0f;
            }
        }
        __syncwarp();
    }
}

// ---------------------------------------------------------------------------
// Kernel 4: attention on tensor cores (exact), K/V double-buffered.
// ---------------------------------------------------------------------------
__global__ __launch_bounds__(256) void k_attn_mma() {
    int l0 = blockIdx.x * 128;
    int bh = blockIdx.y;
    int b = bh >> 3, h = bh & 7;

    const bf16* Q = g_qb + (size_t)bh * LL * DD;
    const bf16* K = g_kb + (size_t)(b * Cc + h * 64) * LL;
    const bf16* V = g_vb + (size_t)bh * LL * DD;

    __shared__ bf16 Qs[128 * 72];
    __shared__ bf16 Ks[2][64 * 64];
    __shared__ bf16 Vs[2][64 * 64];

    int tid = threadIdx.x, lane = tid & 31, warp = tid >> 5;
    const uint32_t sQ = smem_u32(Qs);
    const uint32_t sK[2] = {smem_u32(Ks[0]), smem_u32(Ks[1])};
    const uint32_t sV[2] = {smem_u32(Vs[0]), smem_u32(Vs[1])};

    int rr[2], cc[2], xx[2];
#pragma unroll
    for (int t = 0; t < 2; t++) {
        int id = tid + t * 256;
        rr[t] = id >> 3; cc[t] = id & 7;
        xx[t] = cc[t] ^ (rr[t] & 7);
    }
    uint4 pk[2], pv[2];

#define LDKV(k0)                                                                   \
    {                                                                              \
        _Pragma("unroll") for (int t = 0; t < 2; t++) {                            \
            pk[t] = *(const uint4*)(K + (size_t)rr[t] * LL + (k0) + cc[t] * 8);    \
            pv[t] = *(const uint4*)(V + (size_t)((k0) + rr[t]) * DD + cc[t] * 8);  \
        }                                                                          \
    }
#define STKV(p)                                                                    \
    {                                                                              \
        _Pragma("unroll") for (int t = 0; t < 2; t++) {                            \
            *(uint4*)((char*)Ks[p] + rr[t] * 128 + xx[t] * 16) = pk[t];            \
            *(uint4*)((char*)Vs[p] + rr[t] * 128 + xx[t] * 16) = pv[t];            \
        }                                                                          \
    }

#pragma unroll
    for (int t = 0; t < 4; t++) {
        int id = tid + t * 256;
        int r = id >> 3, c = id & 7;
        uint4 qv = *(const uint4*)(Q + (size_t)(l0 + r) * DD + c * 8);
        *(uint4*)((char*)Qs + r * 144 + c * 16) = qv;
    }
    LDKV(0);
    STKV(0);
    __syncthreads();

    uint32_t aq[4][4];
    {
        int row = warp * 16 + (lane & 15);
#pragma unroll
        for (int kc = 0; kc < 4; kc++)
            ldsm4(aq[kc], sQ + row * 144 + kc * 32 + (lane >> 4) * 16);
    }

    float oacc[8][4];
#pragma unroll
    for (int i = 0; i < 8; i++)
#pragma unroll
        for (int j = 0; j < 4; j++) oacc[i][j] = 0.0f;

    for (int it = 0; it < 16; it++) {
        int p = it & 1;
        if (it < 15) LDKV((it + 1) * 64);

        float sacc[8][4];
#pragma unroll
        for (int i = 0; i < 8; i++)
#pragma unroll
            for (int j = 0; j < 4; j++) sacc[i][j] = 0.0f;
#pragma unroll
        for (int nb = 0; nb < 4; nb++) {
#pragma unroll
            for (int ks = 0; ks < 4; ks++) {
                uint32_t bf[4];
                int krow = ks * 16 + (lane & 7) + ((lane >> 3) & 1) * 8;
                int ch = nb * 2 + (lane >> 4);
                int x = ch ^ (krow & 7);
                ldsm4t(bf, sK[p] + krow * 128 + x * 16);
                mma16816(sacc[nb * 2],     aq[ks], bf[0], bf[1]);
                mma16816(sacc[nb * 2 + 1], aq[ks], bf[2], bf[3]);
            }
        }
        uint32_t sa[4][4];
#pragma unroll
        for (int kb = 0; kb < 4; kb++) {
            sa[kb][0] = packbf(sacc[2 * kb][0],     sacc[2 * kb][1]);
            sa[kb][1] = packbf(sacc[2 * kb][2],     sacc[2 * kb][3]);
            sa[kb][2] = packbf(sacc[2 * kb + 1][0], sacc[2 * kb + 1][1]);
            sa[kb][3] = packbf(sacc[2 * kb + 1][2], sacc[2 * kb + 1][3]);
        }
#pragma unroll
        for (int nb = 0; nb < 4; nb++) {
#pragma unroll
            for (int kb = 0; kb < 4; kb++) {
                uint32_t bf[4];
                int krow = kb * 16 + (lane & 7) + ((lane >> 3) & 1) * 8;
                int ch = nb * 2 + (lane >> 4);
                int x = ch ^ (krow & 7);
                ldsm4t(bf, sV[p] + krow * 128 + x * 16);
                mma16816(oacc[nb * 2],     sa[kb], bf[0], bf[1]);
                mma16816(oacc[nb * 2 + 1], sa[kb], bf[2], bf[3]);
            }
        }

        if (it < 15) STKV(p ^ 1);
        __syncthreads();
    }
#undef LDKV
#undef STKV

    int row = warp * 16 + (lane >> 2);
#pragma unroll
    for (int nj = 0; nj < 8; nj++) {
        int col = nj * 8 + (lane & 3) * 2;
#pragma unroll
        for (int e = 0; e < 4; e++) {
            int r = row + (e >> 1) * 8;
            int c = col + (e & 1);
            float o = oacc[nj][e] * 0.125f;
            float s = ((o / 1.5f - 1.0f) >= 0.0f) ? 1.0f : 0.0f;
            g_sattnb[((size_t)b * Cc + h * 64 + c) * LL + (l0 + r)] = __float2bfloat16(s);
        }
    }
}

// ---------------------------------------------------------------------------
extern "C" void kernel_launch(void* const* d_in, const int* in_sizes, int n_in,
                              void* d_out, int out_size) {
    const float* x   = (const float*)d_in[0];
    const float* wq  = (const float*)d_in[1];
    const float* wk  = (const float*)d_in[2];
    const float* wv  = (const float*)d_in[3];
    const float* wp  = (const float*)d_in[4];
    const float* bp  = (const float*)d_in[5];
    const float* gq  = (const float*)d_in[6];
    const float* bq  = (const float*)d_in[7];
    const float* mq  = (const float*)d_in[8];
    const float* vq  = (const float*)d_in[9];
    const float* gk  = (const float*)d_in[10];
    const float* bk  = (const float*)d_in[11];
    const float* mk  = (const float*)d_in[12];
    const float* vk  = (const float*)d_in[13];
    const float* gv  = (const float*)d_in[14];
    const float* bv  = (const float*)d_in[15];
    const float* mv  = (const float*)d_in[16];
    const float* vv  = (const float*)d_in[17];
    const float* gp  = (const float*)d_in[18];
    const float* bpn = (const float*)d_in[19];
    const float* mp  = (const float*)d_in[20];
    const float* vp  = (const float*)d_in[21];
    float* out = (float*)d_out;

    k_prep<<<8192, 256>>>(wq, wk, wv, wp, x, gp, bpn, mp, vp);
    k_s0T<<<dim3(LL / 32, Cc / 64, Bb), 256>>>();
    k_gemm_qkv_mma<<<dim3(LL / 128, Cc / 128, 3 * Bb), 256>>>();
    k_bn_lif_qkv<<<dim3(NN / 32, HH, 3 * Bb), 256>>>(gq, bq, mq, vq,
                                                     gk, bk, mk, vk,
                                                     gv, bv, mv, vv);
    k_fallback<<<2048, 256>>>(wq, wk, wv, gq, bq, mq, vq,
                              gk, bk, mk, vk, gv, bv, mv, vv);
    k_attn_mma<<<dim3(LL / 128, Bb * HH), 256>>>();
    k_gemm_out_mma<<<dim3(LL / 128, Cc / 128, Bb), 256>>>(bp, out);
}

// round 17
// speedup vs baseline: 2.3216x; 1.1731x over previous
#include <cuda_runtime.h>
#include <cuda_bf16.h>
#include <cstdint>

#define Bb 8
#define Cc 512
#define Tt 4
#define NN 256
#define LL 1024
#define HH 8
#define DD 64

#define EPSY 3e-4f
#define FLAG_CAP (1 << 20)

typedef __nv_bfloat16 bf16;

// Scratch
__device__ bf16  g_wsp[4 * 2 * Cc * Cc];   // [mat(q,k,v,p)][split(hi,mid)][o][c]
__device__ bf16  g_s0b[Bb * Cc * LL];      // proj spikes bf16 [b][c][l]
__device__ bf16  g_s0T[Bb * LL * Cc];      // proj spikes bf16 [b][l][c]
__device__ float g_y[3 * Bb * Cc * LL];    // qkv pre-activation fp32
__device__ bf16  g_qb[Bb * HH * LL * DD];  // q spikes [b][h][l][d]
__device__ bf16  g_kb[Bb * Cc * LL];       // k spikes [b][c][l]
__device__ bf16  g_vb[Bb * HH * LL * DD];  // v spikes [b][h][l][d]
__device__ bf16  g_Mhl[Bb * HH * 128 * 64];// M=K^T V exact 2-part bf16 [bh][hi|lo dk][dv]
__device__ bf16  g_sattnb[Bb * Cc * LL];   // attn spikes [b][c][l]
__device__ unsigned int g_nflag;
__device__ unsigned int g_flag[FLAG_CAP];  // (w<<20)|(b<<17)|(o<<8)|n

// ---------------------------------------------------------------------------
__device__ __forceinline__ uint32_t smem_u32(const void* p) {
    return (uint32_t)__cvta_generic_to_shared(p);
}
__device__ __forceinline__ void ldsm4(uint32_t* r, uint32_t a) {
    asm volatile("ldmatrix.sync.aligned.m8n8.x4.shared.b16 {%0,%1,%2,%3}, [%4];"
                 : "=r"(r[0]), "=r"(r[1]), "=r"(r[2]), "=r"(r[3]) : "r"(a));
}
__device__ __forceinline__ void ldsm4t(uint32_t* r, uint32_t a) {
    asm volatile("ldmatrix.sync.aligned.m8n8.x4.trans.shared.b16 {%0,%1,%2,%3}, [%4];"
                 : "=r"(r[0]), "=r"(r[1]), "=r"(r[2]), "=r"(r[3]) : "r"(a));
}
__device__ __forceinline__ void mma16816(float* c, const uint32_t* a, uint32_t b0, uint32_t b1) {
    asm volatile(
        "mma.sync.aligned.m16n8k16.row.col.f32.bf16.bf16.f32 "
        "{%0,%1,%2,%3}, {%4,%5,%6,%7}, {%8,%9}, {%0,%1,%2,%3};"
        : "+f"(c[0]), "+f"(c[1]), "+f"(c[2]), "+f"(c[3])
        : "r"(a[0]), "r"(a[1]), "r"(a[2]), "r"(a[3]), "r"(b0), "r"(b1));
}
__device__ __forceinline__ void cpasync16(uint32_t s, const void* g) {
    asm volatile("cp.async.cg.shared.global [%0], [%1], 16;" :: "r"(s), "l"(g));
}
#define CP_COMMIT() asm volatile("cp.async.commit_group;" ::: "memory")
#define CP_WAIT0()  asm volatile("cp.async.wait_group 0;" ::: "memory")
#define CP_WAIT1()  asm volatile("cp.async.wait_group 1;" ::: "memory")

// ---------------------------------------------------------------------------
// Kernel 1 (fused prep)
// ---------------------------------------------------------------------------
__global__ void k_prep(const float* __restrict__ wq, const float* __restrict__ wk,
                       const float* __restrict__ wv, const float* __restrict__ wp,
                       const float* __restrict__ x,
                       const float* __restrict__ gp, const float* __restrict__ bpn,
                       const float* __restrict__ mp, const float* __restrict__ vp) {
    if (blockIdx.x == 0 && threadIdx.x == 0) g_nflag = 0;
    if (blockIdx.x < 4096) {
        int idx = blockIdx.x * 256 + threadIdx.x;
        int m = idx / (Cc * Cc);
        int rc = idx % (Cc * Cc);
        const float* W = (m == 0) ? wq : (m == 1) ? wk : (m == 2) ? wv : wp;
        float w = W[rc];
        bf16 hi = __float2bfloat16(w);
        float r1 = w - __bfloat162float(hi);
        g_wsp[(size_t)(m * 2 + 0) * Cc * Cc + rc] = hi;
        g_wsp[(size_t)(m * 2 + 1) * Cc * Cc + rc] = __float2bfloat16(r1);
    } else {
        int idx = (blockIdx.x - 4096) * 256 + threadIdx.x;
        int n = idx % NN;
        int c = (idx / NN) % Cc;
        int b = idx / (NN * Cc);

        float sc = gp[c] / sqrtf(vp[c] + 1e-5f);
        float sh = bpn[c] - mp[c] * sc;

        const float* xp = x + ((size_t)(b * Cc + c) * Tt) * NN + n;
        bf16* sp = g_s0b + (size_t)(b * Cc + c) * LL + n;

        float xv[4];
#pragma unroll
        for (int t = 0; t < Tt; t++) xv[t] = xp[(size_t)t * NN];

        float v = 0.0f;
#pragma unroll
        for (int t = 0; t < Tt; t++) {
            float xb = xv[t] * sc + sh;
            v = v + (xb - v) / 1.5f;
            float s = (v >= 1.0f) ? 1.0f : 0.0f;
            sp[(size_t)t * NN] = __float2bfloat16(s);
            if (s != 0.0f) v = 0.0f;
        }
    }
}

// ---------------------------------------------------------------------------
// Kernel 1b: transpose g_s0b -> g_s0T
// ---------------------------------------------------------------------------
__global__ __launch_bounds__(256) void k_s0T() {
    int b = blockIdx.z;
    int c0 = blockIdx.y * 64;
    int l0 = blockIdx.x * 32;
    int tid = threadIdx.x, lane = tid & 31, wrp = tid >> 5;

    __shared__ bf16 sm[32][72];

#pragma unroll
    for (int i = 0; i < 8; i++) {
        int cl = wrp * 8 + i;
        sm[lane][cl] = g_s0b[((size_t)(b * Cc + c0 + cl)) * LL + l0 + lane];
    }
    __syncthreads();

    int l = tid >> 3, c8 = (tid & 7) * 8;
    uint4 v;
    memcpy(&v, &sm[l][c8], 16);
    *(uint4*)&g_s0T[((size_t)b * LL + l0 + l) * Cc + c0 + c8] = v;
}

// ---------------------------------------------------------------------------
// Tensor-core GEMM core: 3-stage cp.async pipeline.
// ---------------------------------------------------------------------------
__device__ __forceinline__ void gemm_core(const bf16* __restrict__ A,
                                          const bf16* __restrict__ B,
                                          float* __restrict__ C,
                                          const float* __restrict__ bias) {
    __shared__ bf16 As[3][128 * 40];
    __shared__ bf16 Bs[3][32 * 128];

    const int tid = threadIdx.x;
    const int lane = tid & 31, warp = tid >> 5;
    const int wm = warp >> 1, wn = warp & 1;
    const int o0 = blockIdx.y * 128, l0 = blockIdx.x * 128;

    float acc[2][8][4];
#pragma unroll
    for (int i = 0; i < 2; i++)
#pragma unroll
        for (int j = 0; j < 8; j++)
#pragma unroll
            for (int k = 0; k < 4; k++) acc[i][j][k] = 0.0f;

    int aM[2], aK[2], bK[2], bX[2], bXs[2];
#pragma unroll
    for (int t = 0; t < 2; t++) {
        int id = tid + t * 256;
        aM[t] = id >> 2; aK[t] = id & 3;
        bK[t] = id >> 4; bX[t] = id & 15;
        bXs[t] = bX[t] ^ (bK[t] & 7);
    }
    const uint32_t sA[3] = {smem_u32(As[0]), smem_u32(As[1]), smem_u32(As[2])};
    const uint32_t sB[3] = {smem_u32(Bs[0]), smem_u32(Bs[1]), smem_u32(Bs[2])};

#define LOADG(kk, p)                                                                   \
    {                                                                                  \
        int split = ((kk) * 32) >> 9;                                                  \
        int c0 = ((kk) * 32) & 511;                                                    \
        const bf16* Ab = A + (size_t)split * (Cc * Cc);                                \
        _Pragma("unroll") for (int t = 0; t < 2; t++)                                  \
            cpasync16(sA[p] + aM[t] * 80 + aK[t] * 16,                                 \
                      Ab + (size_t)(o0 + aM[t]) * Cc + c0 + aK[t] * 8);                \
        _Pragma("unroll") for (int t = 0; t < 2; t++)                                  \
            cpasync16(sB[p] + bK[t] * 256 + bXs[t] * 16,                               \
                      B + (size_t)(c0 + bK[t]) * LL + l0 + bX[t] * 8);                 \
        CP_COMMIT();                                                                   \
    }

    LOADG(0, 0);
    LOADG(1, 1);

    for (int kk = 0; kk < 32; kk++) {
        int p = kk % 3;
        if (kk < 31) CP_WAIT1(); else CP_WAIT0();
        __syncthreads();
        if (kk < 30) LOADG(kk + 2, (kk + 2) % 3);

#pragma unroll
        for (int ks = 0; ks < 2; ks++) {
            uint32_t a[2][4];
#pragma unroll
            for (int mi = 0; mi < 2; mi++) {
                int row = wm * 32 + mi * 16 + (lane & 15);
                ldsm4(a[mi], sA[p] + row * 80 + (ks * 16 + (lane >> 4) * 8) * 2);
            }
            uint32_t bfr[4][4];
#pragma unroll
            for (int nb = 0; nb < 4; nb++) {
                int krow = ks * 16 + (lane & 7) + ((lane >> 3) & 1) * 8;
                int x = (wn * 8 + nb * 2 + (lane >> 4)) ^ (krow & 7);
                ldsm4t(bfr[nb], sB[p] + krow * 256 + x * 16);
            }
#pragma unroll
            for (int mi = 0; mi < 2; mi++)
#pragma unroll
                for (int nj = 0; nj < 8; nj++)
                    mma16816(acc[mi][nj], a[mi], bfr[nj >> 1][(nj & 1) * 2],
                             bfr[nj >> 1][(nj & 1) * 2 + 1]);
        }
    }
#undef LOADG

#pragma unroll
    for (int mi = 0; mi < 2; mi++) {
        int r0 = o0 + wm * 32 + mi * 16 + (lane >> 2);
        float bi0 = bias ? bias[r0] : 0.0f;
        float bi1 = bias ? bias[r0 + 8] : 0.0f;
#pragma unroll
        for (int nj = 0; nj < 8; nj++) {
            int cb = l0 + wn * 64 + nj * 8 + (lane & 3) * 2;
            float2 v0 = make_float2(acc[mi][nj][0] + bi0, acc[mi][nj][1] + bi0);
            float2 v1 = make_float2(acc[mi][nj][2] + bi1, acc[mi][nj][3] + bi1);
            *(float2*)&C[(size_t)r0 * LL + cb] = v0;
            *(float2*)&C[(size_t)(r0 + 8) * LL + cb] = v1;
        }
    }
}

// grid = (LL/128, Cc/128, 3*Bb)
__global__ __launch_bounds__(256, 2) void k_gemm_qkv_mma() {
    int z = blockIdx.z;
    int w = z >> 3, b = z & 7;
    gemm_core(g_wsp + (size_t)w * 2 * Cc * Cc,
              g_s0b + (size_t)b * Cc * LL,
              g_y + (size_t)z * Cc * LL, nullptr);
}

// grid = (LL/128, Cc/128, Bb)
__global__ __launch_bounds__(256, 2) void k_gemm_out_mma(const float* __restrict__ bp,
                                                         float* __restrict__ out) {
    gemm_core(g_wsp + (size_t)3 * 2 * Cc * Cc,
              g_sattnb + (size_t)blockIdx.z * Cc * LL,
              out + (size_t)blockIdx.z * Cc * LL, bp);
}

// ---------------------------------------------------------------------------
// Kernel 3: per-branch BN + LIF with certified-margin flagging (hoisted loads)
// ---------------------------------------------------------------------------
__global__ __launch_bounds__(256) void k_bn_lif_qkv(
        const float* __restrict__ gq, const float* __restrict__ bq,
        const float* __restrict__ mq, const float* __restrict__ vq,
        const float* __restrict__ gk, const float* __restrict__ bk,
        const float* __restrict__ mk, const float* __restrict__ vk,
        const float* __restrict__ gv, const float* __restrict__ bv,
        const float* __restrict__ mv, const float* __restrict__ vv) {
    int z = blockIdx.z;
    int w = z / Bb, b = z % Bb;
    int h = blockIdx.y;
    int n0 = blockIdx.x * 32;
    int tid = threadIdx.x, lane = tid & 31, wrp = tid >> 5;

    const float *gg, *bb, *mm, *vvv;
    if (w == 0) { gg = gq; bb = bq; mm = mq; vvv = vq; }
    else if (w == 1) { gg = gk; bb = bk; mm = mk; vvv = vk; }
    else { gg = gv; bb = bv; mm = mv; vvv = vv; }

    const bool isK = (w == 1);
    __shared__ bf16 sm[Tt][32][66];

    float yv[8][4];
#pragma unroll
    for (int i = 0; i < 8; i++) {
        int o = h * 64 + wrp * 8 + i;
        const float* yp = g_y + (size_t)((w * Bb + b) * Cc + o) * LL + n0 + lane;
#pragma unroll
        for (int t = 0; t < Tt; t++) yv[i][t] = yp[(size_t)t * NN];
    }

#pragma unroll
    for (int i = 0; i < 8; i++) {
        int od = wrp * 8 + i;
        int o = h * 64 + od;
        float sc = gg[o] / sqrtf(vvv[o] + 1e-5f);
        float sh = bb[o] - mm[o] * sc;

        float de = (2.0f / 3.0f) * fabsf(sc) * EPSY;
        float e = 0.0f;
        bool flagged = false;

        float v = 0.0f;
#pragma unroll
        for (int t = 0; t < Tt; t++) {
            float yb = yv[i][t] * sc + sh;
            v = v + (yb - v) / 1.5f;
            e = e * (1.0f / 3.0f) + de;
            if (fabsf(v - 1.0f) < e) flagged = true;
            float s = (v >= 1.0f) ? 1.0f : 0.0f;
            if (isK)
                g_kb[(size_t)(b * Cc + o) * LL + t * NN + n0 + lane] = __float2bfloat16(s);
            else
                sm[t][lane][od] = __float2bfloat16(s);
            if (s != 0.0f) { v = 0.0f; e = 0.0f; }
        }
        if (flagged) {
            unsigned int pos = atomicAdd(&g_nflag, 1u);
            if (pos < FLAG_CAP)
                g_flag[pos] = ((unsigned)w << 20) | ((unsigned)b << 17) |
                              ((unsigned)o << 8) | (unsigned)(n0 + lane);
        }
    }

    if (!isK) {
        __syncthreads();
        bf16* dst = ((w == 0) ? g_qb : g_vb) + (size_t)(b * HH + h) * LL * DD;
#pragma unroll
        for (int j = 0; j < 16; j++) {
            int flat = tid + 256 * j;
            int row = flat >> 5, col = flat & 31;
            int t = row >> 5, n = row & 31;
            uint32_t val;
            memcpy(&val, &sm[t][n][col * 2], 4);
            *(uint32_t*)(dst + ((size_t)(t * NN + n0 + n)) * DD + col * 2) = val;
        }
    }
}

// ---------------------------------------------------------------------------
// Kernel 3f: bitmask warp fallback (coalesced, zero-skip, bit-identical).
// ---------------------------------------------------------------------------
__global__ __launch_bounds__(256) void k_fallback(
        const float* __restrict__ wq, const float* __restrict__ wk,
        const float* __restrict__ wv,
        const float* __restrict__ gq, const float* __restrict__ bq,
        const float* __restrict__ mq, const float* __restrict__ vq,
        const float* __restrict__ gk, const float* __restrict__ bk,
        const float* __restrict__ mk, const float* __restrict__ vk,
        const float* __restrict__ gv, const float* __restrict__ bv,
        const float* __restrict__ mv, const float* __restrict__ vv) {
    __shared__ float Wsm[8][Cc];
    __shared__ uint32_t msm[8][Tt][16];

    int lane = threadIdx.x & 31, wrp = threadIdx.x >> 5;
    unsigned int total = g_nflag;
    if (total > FLAG_CAP) total = FLAG_CAP;
    unsigned int gw = blockIdx.x * 8 + wrp;
    unsigned int nw = gridDim.x * 8;

    for (unsigned int i = gw; i < total; i += nw) {
        unsigned int enc = g_flag[i];
        int n = enc & 255;
        int o = (enc >> 8) & 511;
        int b = (enc >> 17) & 7;
        int w = enc >> 20;

        const float* W = (w == 0) ? wq : (w == 1) ? wk : wv;
        const float* Wrow = W + (size_t)o * Cc;

#pragma unroll
        for (int j = 0; j < 16; j++) {
            int c = lane + 32 * j;
            Wsm[wrp][c] = Wrow[c];
#pragma unroll
            for (int t = 0; t < Tt; t++) {
                bf16 s = g_s0T[((size_t)b * LL + t * NN + n) * Cc + c];
                unsigned m = __ballot_sync(0xffffffffu,
                                           __bfloat16_as_ushort(s) != 0);
                if (lane == 0) msm[wrp][t][j] = m;
            }
        }
        __syncwarp();

        float yt = 0.0f;
        if (lane < Tt) {
#pragma unroll
            for (int j = 0; j < 16; j++) {
                unsigned m = msm[wrp][lane][j];
                while (m) {
                    int cb = __ffs(m) - 1;
                    m &= m - 1;
                    yt += Wsm[wrp][32 * j + cb];
                }
            }
        }
        float y0 = __shfl_sync(0xffffffffu, yt, 0);
        float y1 = __shfl_sync(0xffffffffu, yt, 1);
        float y2 = __shfl_sync(0xffffffffu, yt, 2);
        float y3 = __shfl_sync(0xffffffffu, yt, 3);

        if (lane == 0) {
            float y[4] = {y0, y1, y2, y3};
            const float *gg, *bb, *mm, *vvv;
            if (w == 0) { gg = gq; bb = bq; mm = mq; vvv = vq; }
            else if (w == 1) { gg = gk; bb = bk; mm = mk; vvv = vk; }
            else { gg = gv; bb = bv; mm = mv; vvv = vv; }

            float sc = gg[o] / sqrtf(vvv[o] + 1e-5f);
            float sh = bb[o] - mm[o] * sc;
            int h = o >> 6, dd = o & 63;

            float v = 0.0f;
#pragma unroll
            for (int t = 0; t < Tt; t++) {
                float yb = y[t] * sc + sh;
                v = v + (yb - v) / 1.5f;
                float s = (v >= 1.0f) ? 1.0f : 0.0f;
                if (w == 1)
                    g_kb[(size_t)(b * Cc + o) * LL + t * NN + n] = __float2bfloat16(s);
                else {
                    bf16* base = (w == 0) ? g_qb : g_vb;
                    base[((size_t)(b * HH + h) * LL + t * NN + n) * DD + dd] =
                        __float2bfloat16(s);
                }
                if (s != 0.0f) v = 0.0f;
            }
        }
        __syncwarp();
    }
}

// ---------------------------------------------------------------------------
// Kernel 4a: M = K^T V per (b,h). Exact integers (binary inputs, fp32 acc).
// Epilogue: exact 2-part bf16 split M = hi + lo into g_Mhl [bh][hi|lo][dv].
// grid = 64 CTAs (one per bh), 256 threads, warps 4x2 -> 16x32 tiles.
// ---------------------------------------------------------------------------
__global__ __launch_bounds__(256) void k_kv() {
    int bh = blockIdx.x;
    int b = bh >> 3, h = bh & 7;

    const bf16* K = g_kb + (size_t)(b * Cc + h * 64) * LL;   // [dk][l]
    const bf16* V = g_vb + (size_t)bh * LL * DD;             // [l][dv]

    __shared__ bf16 Ks[2][64 * 64];
    __shared__ bf16 Vs[2][64 * 64];

    int tid = threadIdx.x, lane = tid & 31, warp = tid >> 5;
    int wm = warp >> 1, wn = warp & 1;
    const uint32_t sK[2] = {smem_u32(Ks[0]), smem_u32(Ks[1])};
    const uint32_t sV[2] = {smem_u32(Vs[0]), smem_u32(Vs[1])};

    int rr[2], cc[2], xx[2];
#pragma unroll
    for (int t = 0; t < 2; t++) {
        int id = tid + t * 256;
        rr[t] = id >> 3; cc[t] = id & 7;
        xx[t] = cc[t] ^ (rr[t] & 7);
    }
    uint4 pk[2], pv[2];

#define LDKV(k0)                                                                   \
    {                                                                              \
        _Pragma("unroll") for (int t = 0; t < 2; t++) {                            \
            pk[t] = *(const uint4*)(K + (size_t)rr[t] * LL + (k0) + cc[t] * 8);    \
            pv[t] = *(const uint4*)(V + (size_t)((k0) + rr[t]) * DD + cc[t] * 8);  \
        }                                                                          \
    }
#define STKV(p)                                                                    \
    {                                                                              \
        _Pragma("unroll") for (int t = 0; t < 2; t++) {                            \
            *(uint4*)((char*)Ks[p] + rr[t] * 128 + xx[t] * 16) = pk[t];            \
            *(uint4*)((char*)Vs[p] + rr[t] * 128 + xx[t] * 16) = pv[t];            \
        }                                                                          \
    }

    LDKV(0);
    STKV(0);
    __syncthreads();

    float acc[4][4];
#pragma unroll
    for (int i = 0; i < 4; i++)
#pragma unroll
        for (int j = 0; j < 4; j++) acc[i][j] = 0.0f;

    for (int it = 0; it < 16; it++) {
        int p = it & 1;
        if (it < 15) LDKV((it + 1) * 64);

#pragma unroll
        for (int ks = 0; ks < 4; ks++) {
            // A: K [dk][l] tile, m-rows = dk
            uint32_t a[4];
            {
                int row = wm * 16 + (lane & 15);
                int ch = ks * 2 + (lane >> 4);
                int x = ch ^ (row & 7);
                ldsm4(a, sK[p] + row * 128 + x * 16);
            }
#pragma unroll
            for (int nb = 0; nb < 2; nb++) {
                uint32_t bf[4];
                int krow = ks * 16 + (lane & 7) + ((lane >> 3) & 1) * 8;
                int ch = wn * 4 + nb * 2 + (lane >> 4);
                int x = ch ^ (krow & 7);
                ldsm4t(bf, sV[p] + krow * 128 + x * 16);
                mma16816(acc[nb * 2],     a, bf[0], bf[1]);
                mma16816(acc[nb * 2 + 1], a, bf[2], bf[3]);
            }
        }

        if (it < 15) STKV(p ^ 1);
        __syncthreads();
    }
#undef LDKV
#undef STKV

    // epilogue: exact 2-part bf16 split (M integer <= 1024)
    bf16* Mo = g_Mhl + (size_t)bh * 128 * 64;
    int r0 = wm * 16 + (lane >> 2);
#pragma unroll
    for (int nj = 0; nj < 4; nj++) {
        int col = wn * 32 + nj * 8 + (lane & 3) * 2;
#pragma unroll
        for (int e = 0; e < 4; e++) {
            int row = r0 + (e >> 1) * 8;
            int c = col + (e & 1);
            float m = acc[nj][e];
            bf16 hi = __float2bfloat16(m);
            bf16 lo = __float2bfloat16(m - __bfloat162float(hi));
            Mo[(size_t)row * 64 + c] = hi;
            Mo[(size_t)(row + 64) * 64 + c] = lo;
        }
    }
}

// ---------------------------------------------------------------------------
// Kernel 4b: O = Q @ (hi + lo) exactly (integers < 2^24, order-free), spike.
// grid = (LL/128, 64 bh), 256 threads, warp = 16 q-rows x full dv=64.
// ---------------------------------------------------------------------------
__global__ __launch_bounds__(256) void k_qm() {
    int l0 = blockIdx.x * 128;
    int bh = blockIdx.y;
    int b = bh >> 3, h = bh & 7;

    const bf16* Q = g_qb + (size_t)bh * LL * DD;     // [l][dk]
    const bf16* M = g_Mhl + (size_t)bh * 128 * 64;   // [hi|lo dk][dv]

    __shared__ bf16 Qs[128 * 72];
    __shared__ bf16 Ms[128 * 64];

    int tid = threadIdx.x, lane = tid & 31, warp = tid >> 5;
    const uint32_t sQ = smem_u32(Qs), sM = smem_u32(Ms);

#pragma unroll
    for (int t = 0; t < 4; t++) {
        int id = tid + t * 256;
        int r = id >> 3, c = id & 7;
        uint4 qv = *(const uint4*)(Q + (size_t)(l0 + r) * DD + c * 8);
        *(uint4*)((char*)Qs + r * 144 + c * 16) = qv;
        int x = c ^ (r & 7);
        uint4 mv = *(const uint4*)(M + (size_t)r * 64 + c * 8);
        *(uint4*)((char*)Ms + r * 128 + x * 16) = mv;
    }
    __syncthreads();

    uint32_t aq[4][4];
    {
        int row = warp * 16 + (lane & 15);
#pragma unroll
        for (int kc = 0; kc < 4; kc++)
            ldsm4(aq[kc], sQ + row * 144 + kc * 32 + (lane >> 4) * 16);
    }

    float oacc[8][4];
#pragma unroll
    for (int i = 0; i < 8; i++)
#pragma unroll
        for (int j = 0; j < 4; j++) oacc[i][j] = 0.0f;

#pragma unroll
    for (int half = 0; half < 2; half++) {
#pragma unroll
        for (int ks = 0; ks < 4; ks++) {
#pragma unroll
            for (int nb = 0; nb < 4; nb++) {
                uint32_t bf[4];
                int krow = half * 64 + ks * 16 + (lane & 7) + ((lane >> 3) & 1) * 8;
                int ch = nb * 2 + (lane >> 4);
                int x = ch ^ (krow & 7);
                ldsm4t(bf, sM + krow * 128 + x * 16);
                mma16816(oacc[nb * 2],     aq[ks], bf[0], bf[1]);
                mma16816(oacc[nb * 2 + 1], aq[ks], bf[2], bf[3]);
            }
        }
    }

    int row = warp * 16 + (lane >> 2);
#pragma unroll
    for (int nj = 0; nj < 8; nj++) {
        int col = nj * 8 + (lane & 3) * 2;
#pragma unroll
        for (int e = 0; e < 4; e++) {
            int r = row + (e >> 1) * 8;
            int c = col + (e & 1);
            float o = oacc[nj][e] * 0.125f;
            float s = ((o / 1.5f - 1.0f) >= 0.0f) ? 1.0f : 0.0f;
            g_sattnb[((size_t)b * Cc + h * 64 + c) * LL + (l0 + r)] = __float2bfloat16(s);
        }
    }
}

// ---------------------------------------------------------------------------
extern "C" void kernel_launch(void* const* d_in, const int* in_sizes, int n_in,
                              void* d_out, int out_size) {
    const float* x   = (const float*)d_in[0];
    const float* wq  = (const float*)d_in[1];
    const float* wk  = (const float*)d_in[2];
    const float* wv  = (const float*)d_in[3];
    const float* wp  = (const float*)d_in[4];
    const float* bp  = (const float*)d_in[5];
    const float* gq  = (const float*)d_in[6];
    const float* bq  = (const float*)d_in[7];
    const float* mq  = (const float*)d_in[8];
    const float* vq  = (const float*)d_in[9];
    const float* gk  = (const float*)d_in[10];
    const float* bk  = (const float*)d_in[11];
    const float* mk  = (const float*)d_in[12];
    const float* vk  = (const float*)d_in[13];
    const float* gv  = (const float*)d_in[14];
    const float* bv  = (const float*)d_in[15];
    const float* mv  = (const float*)d_in[16];
    const float* vv  = (const float*)d_in[17];
    const float* gp  = (const float*)d_in[18];
    const float* bpn = (const float*)d_in[19];
    const float* mp  = (const float*)d_in[20];
    const float* vp  = (const float*)d_in[21];
    float* out = (float*)d_out;

    k_prep<<<8192, 256>>>(wq, wk, wv, wp, x, gp, bpn, mp, vp);
    k_s0T<<<dim3(LL / 32, Cc / 64, Bb), 256>>>();
    k_gemm_qkv_mma<<<dim3(LL / 128, Cc / 128, 3 * Bb), 256>>>();
    k_bn_lif_qkv<<<dim3(NN / 32, HH, 3 * Bb), 256>>>(gq, bq, mq, vq,
                                                     gk, bk, mk, vk,
                                                     gv, bv, mv, vv);
    k_fallback<<<2048, 256>>>(wq, wk, wv, gq, bq, mq, vq,
                              gk, bk, mk, vk, gv, bv, mv, vv);
    k_kv<<<Bb * HH, 256>>>();
    k_qm<<<dim3(LL / 128, Bb * HH), 256>>>();
    k_gemm_out_mma<<<dim3(LL / 128, Cc / 128, Bb), 256>>>(bp, out);
}